// round 1
// baseline (speedup 1.0000x reference)
#include <cuda_runtime.h>
#include <math.h>

#define BB 16
#define CC 256
#define HH 96
#define WW 96
#define HWSZ (HH*WW)           // 9216
#define NELEM (BB*CC*HWSZ)     // 37,748,736

// Scratch (device globals: allocation-free rule)
__device__ float g_theta[NELEM];
__device__ float g_phi[NELEM];
__device__ float g_g[NELEM];
__device__ float g_x1[NELEM];
__device__ float g_x2[NELEM];
__device__ float g_S[BB*CC*CC];   // attention logits/probs, max 16*256*256

// ---------------------------------------------------------------------------
// conv3: theta/phi/g = W{t,p,g} @ x + b  (per-batch GEMM, M=C, N=HW, K=C)
// 64x64 tile, BK=16, 256 threads, 4x4 microtile per output matrix.
// ---------------------------------------------------------------------------
__global__ __launch_bounds__(256) void conv3_kernel(
    const float* __restrict__ x,
    const float* __restrict__ wt, const float* __restrict__ bt,
    const float* __restrict__ wp, const float* __restrict__ bp,
    const float* __restrict__ wg, const float* __restrict__ bg)
{
    int b  = blockIdx.z;
    int o0 = blockIdx.y * 64;
    int n0 = blockIdx.x * 64;
    const float* xb = x + (size_t)b * CC * HWSZ;

    __shared__ __align__(16) float Xs[16][64];
    __shared__ __align__(16) float Wt_s[16][68];
    __shared__ __align__(16) float Wp_s[16][68];
    __shared__ __align__(16) float Wg_s[16][68];

    int tid = threadIdx.x;
    int to = (tid >> 4) * 4;
    int tn = (tid & 15) * 4;

    float aT[4][4] = {}, aP[4][4] = {}, aG[4][4] = {};

    for (int kk = 0; kk < CC; kk += 16) {
        #pragma unroll
        for (int rr = 0; rr < 4; rr++) {
            int k = rr * 4 + (tid >> 6);
            int n = tid & 63;
            Xs[k][n] = xb[(size_t)(kk + k) * HWSZ + n0 + n];
        }
        #pragma unroll
        for (int rr = 0; rr < 4; rr++) {
            int o = rr * 16 + (tid >> 4);
            int k = tid & 15;
            int gi = (o0 + o) * CC + kk + k;
            Wt_s[k][o] = wt[gi];
            Wp_s[k][o] = wp[gi];
            Wg_s[k][o] = wg[gi];
        }
        __syncthreads();
        #pragma unroll
        for (int k = 0; k < 16; k++) {
            float4 xv = *(const float4*)&Xs[k][tn];
            float4 tv = *(const float4*)&Wt_s[k][to];
            float4 pv = *(const float4*)&Wp_s[k][to];
            float4 gv = *(const float4*)&Wg_s[k][to];
            float xr[4] = {xv.x, xv.y, xv.z, xv.w};
            float tr[4] = {tv.x, tv.y, tv.z, tv.w};
            float pr[4] = {pv.x, pv.y, pv.z, pv.w};
            float gr[4] = {gv.x, gv.y, gv.z, gv.w};
            #pragma unroll
            for (int i = 0; i < 4; i++)
                #pragma unroll
                for (int j = 0; j < 4; j++) {
                    aT[i][j] += tr[i] * xr[j];
                    aP[i][j] += pr[i] * xr[j];
                    aG[i][j] += gr[i] * xr[j];
                }
        }
        __syncthreads();
    }

    #pragma unroll
    for (int i = 0; i < 4; i++) {
        int o = o0 + to + i;
        float bT = bt[o], bP = bp[o], bG = bg[o];
        size_t base = (size_t)b * CC * HWSZ + (size_t)o * HWSZ + n0 + tn;
        #pragma unroll
        for (int j = 0; j < 4; j++) {
            g_theta[base + j] = aT[i][j] + bT;
            g_phi[base + j]   = aP[i][j] + bP;
            g_g[base + j]     = aG[i][j] + bG;
        }
    }
}

// ---------------------------------------------------------------------------
// slice_logits: width (mode 0) / height (mode 1) attention logits.
// S[b,i,j] += sum over 8 channel slices of sum_k T[k][i]*P[k][j],
// where each 96x96 slice is staged in smem, transposed on load as needed.
// 576 threads, 4x4 microtile (24x24 thread grid), atomicAdd reduction.
// ---------------------------------------------------------------------------
__global__ __launch_bounds__(576) void slice_logits_kernel(int mode)
{
    extern __shared__ float sm[];
    float* Ts = sm;               // [96][100]
    float* Ps = sm + 96 * 100;

    int b = blockIdx.y;
    int cchunk = blockIdx.x;      // 32 chunks of 8 channels
    int tid = threadIdx.x;
    int r0 = (tid / 24) * 4;
    int c0 = (tid % 24) * 4;

    float acc[4][4] = {};

    for (int cc = 0; cc < 8; cc++) {
        int c = cchunk * 8 + cc;
        size_t base = ((size_t)b * CC + c) * HWSZ;
        #pragma unroll
        for (int r = 0; r < 16; r++) {
            int idx = r * 576 + tid;          // 0..9215
            int hh = idx / 96, ww = idx % 96;
            float tv = g_theta[base + idx];
            float pv = g_phi[base + idx];
            if (mode == 0) { Ts[hh*100 + ww] = tv; Ps[hh*100 + ww] = pv; }
            else           { Ts[ww*100 + hh] = tv; Ps[ww*100 + hh] = pv; }
        }
        __syncthreads();
        #pragma unroll 4
        for (int k = 0; k < 96; k++) {
            float4 a = *(float4*)&Ts[k*100 + r0];
            float4 p = *(float4*)&Ps[k*100 + c0];
            float ar[4] = {a.x, a.y, a.z, a.w};
            float pr[4] = {p.x, p.y, p.z, p.w};
            #pragma unroll
            for (int i = 0; i < 4; i++)
                #pragma unroll
                for (int j = 0; j < 4; j++)
                    acc[i][j] += ar[i] * pr[j];
        }
        __syncthreads();
    }

    float* Sb = g_S + (size_t)b * 96 * 96;
    #pragma unroll
    for (int i = 0; i < 4; i++)
        #pragma unroll
        for (int j = 0; j < 4; j++)
            atomicAdd(&Sb[(r0 + i) * 96 + (c0 + j)], acc[i][j]);
}

// ---------------------------------------------------------------------------
// channel logits: S[b,i,j] = sum_{k<9216} theta[b,i,k]*phi[b,j,k]
// 64x64 tile, BK=32, split-K over 8, atomicAdd. Transposed smem for float4.
// ---------------------------------------------------------------------------
__global__ __launch_bounds__(256) void chan_logits_kernel()
{
    int ks = blockIdx.x;                  // 0..7 (K split)
    int it = blockIdx.y >> 2, jt = blockIdx.y & 3;
    int b  = blockIdx.z;
    int i0 = it * 64, j0 = jt * 64;

    __shared__ __align__(16) float Ts[32 * 68];
    __shared__ __align__(16) float Ps[32 * 68];

    int tid = threadIdx.x;
    int lc = tid & 31, lr = tid >> 5;
    int ti4 = (tid >> 4) * 4, tj4 = (tid & 15) * 4;

    float acc[4][4] = {};
    size_t bbase = (size_t)b * CC * HWSZ;

    for (int kb = 0; kb < 36; kb++) {
        int k0 = ks * 1152 + kb * 32;
        #pragma unroll
        for (int rr = 0; rr < 8; rr++) {
            int r = rr * 8 + lr;
            Ts[lc * 68 + r] = g_theta[bbase + (size_t)(i0 + r) * HWSZ + k0 + lc];
            Ps[lc * 68 + r] = g_phi[bbase + (size_t)(j0 + r) * HWSZ + k0 + lc];
        }
        __syncthreads();
        #pragma unroll
        for (int k = 0; k < 32; k++) {
            float4 a = *(float4*)&Ts[k * 68 + ti4];
            float4 p = *(float4*)&Ps[k * 68 + tj4];
            float ar[4] = {a.x, a.y, a.z, a.w};
            float pr[4] = {p.x, p.y, p.z, p.w};
            #pragma unroll
            for (int i = 0; i < 4; i++)
                #pragma unroll
                for (int j = 0; j < 4; j++)
                    acc[i][j] += ar[i] * pr[j];
        }
        __syncthreads();
    }

    float* Sb = g_S + (size_t)b * 65536;
    #pragma unroll
    for (int i = 0; i < 4; i++)
        #pragma unroll
        for (int j = 0; j < 4; j++)
            atomicAdd(&Sb[(i0 + ti4 + i) * 256 + (j0 + tj4 + j)], acc[i][j]);
}

// ---------------------------------------------------------------------------
// softmax over last dim of g_S rows; one block per row, in place.
// ---------------------------------------------------------------------------
__global__ __launch_bounds__(256) void softmax_kernel(int n)
{
    size_t base = (size_t)blockIdx.x * n;
    int tid = threadIdx.x;
    __shared__ float red[8];

    float m = -INFINITY;
    for (int j = tid; j < n; j += 256) m = fmaxf(m, g_S[base + j]);
    #pragma unroll
    for (int o = 16; o; o >>= 1) m = fmaxf(m, __shfl_xor_sync(0xffffffffu, m, o));
    if ((tid & 31) == 0) red[tid >> 5] = m;
    __syncthreads();
    float mm = red[0];
    #pragma unroll
    for (int w = 1; w < 8; w++) mm = fmaxf(mm, red[w]);
    __syncthreads();

    float s = 0.f;
    for (int j = tid; j < n; j += 256) {
        float e = __expf(g_S[base + j] - mm);
        g_S[base + j] = e;
        s += e;
    }
    #pragma unroll
    for (int o = 16; o; o >>= 1) s += __shfl_xor_sync(0xffffffffu, s, o);
    if ((tid & 31) == 0) red[tid >> 5] = s;
    __syncthreads();
    float st = 0.f;
    #pragma unroll
    for (int w = 0; w < 8; w++) st += red[w];
    float inv = 1.0f / st;
    for (int j = tid; j < n; j += 256) g_S[base + j] *= inv;
}

// ---------------------------------------------------------------------------
// apply_slice: x_out = x_in + beta * (attention applied along width/height).
// Per (b,c) slice: mode0 out[h,i]=sum_j G[h,j]A[i,j]; mode1 out[i,w]=sum_j A[i,j]G[j,w].
// Both reduce to acc[r][c] = sum_k L[k][r]*R[k][c] with transposed smem staging.
// ---------------------------------------------------------------------------
__global__ __launch_bounds__(576) void apply_slice_kernel(
    const float* __restrict__ xin, float* __restrict__ xout,
    const float* __restrict__ beta_p, int mode)
{
    extern __shared__ float sm[];
    float* As = sm;               // [j][i] : A transposed
    float* Gs = sm + 96 * 100;    // mode0: [j][h] (transposed), mode1: [j][w] (direct)

    int b = blockIdx.y, c = blockIdx.x;
    int tid = threadIdx.x;
    size_t base = ((size_t)b * CC + c) * HWSZ;
    const float* Sb = g_S + (size_t)b * 9216;

    #pragma unroll
    for (int r = 0; r < 16; r++) {
        int idx = r * 576 + tid;
        int i = idx / 96, j = idx % 96;
        As[j * 100 + i] = Sb[idx];
        float gv = g_g[base + idx];
        int rr_ = idx / 96, cc_ = idx % 96;
        if (mode == 0) Gs[cc_ * 100 + rr_] = gv;
        else           Gs[rr_ * 100 + cc_] = gv;
    }
    __syncthreads();

    const float* L = (mode == 0) ? Gs : As;
    const float* R = (mode == 0) ? As : Gs;
    int r0 = (tid / 24) * 4;
    int c0 = (tid % 24) * 4;

    float acc[4][4] = {};
    #pragma unroll 4
    for (int k = 0; k < 96; k++) {
        float4 l = *(const float4*)&L[k * 100 + r0];
        float4 rv = *(const float4*)&R[k * 100 + c0];
        float lr[4] = {l.x, l.y, l.z, l.w};
        float rr[4] = {rv.x, rv.y, rv.z, rv.w};
        #pragma unroll
        for (int i = 0; i < 4; i++)
            #pragma unroll
            for (int j = 0; j < 4; j++)
                acc[i][j] += lr[i] * rr[j];
    }

    float beta = *beta_p;
    #pragma unroll
    for (int i = 0; i < 4; i++)
        #pragma unroll
        for (int j = 0; j < 4; j++) {
            size_t o = base + (size_t)(r0 + i) * 96 + (c0 + j);
            xout[o] = xin[o] + beta * acc[i][j];
        }
}

// ---------------------------------------------------------------------------
// apply_channel: out[b,i,hw] = x + beta * sum_j A[b,i,j]*g[b,j,hw]
// per-b GEMM [256x256]@[256x9216], 64x64 tile, BK=16.
// ---------------------------------------------------------------------------
__global__ __launch_bounds__(256) void apply_channel_kernel(
    const float* __restrict__ xin, float* __restrict__ xout,
    const float* __restrict__ beta_p)
{
    int b  = blockIdx.z;
    int i0 = blockIdx.y * 64;
    int n0 = blockIdx.x * 64;

    __shared__ __align__(16) float As[16 * 68];   // [k][i] transposed
    __shared__ __align__(16) float Gs[16 * 68];   // [k][n]

    int tid = threadIdx.x;
    int ti4 = (tid >> 4) * 4, tj4 = (tid & 15) * 4;
    float acc[4][4] = {};

    const float* Ab = g_S + (size_t)b * 65536;
    size_t bbase = (size_t)b * CC * HWSZ;

    for (int kk = 0; kk < 256; kk += 16) {
        #pragma unroll
        for (int rr = 0; rr < 4; rr++) {
            int r = rr * 16 + (tid >> 4);
            int cload = tid & 15;
            As[cload * 68 + r] = Ab[(i0 + r) * 256 + kk + cload];
        }
        #pragma unroll
        for (int rr = 0; rr < 4; rr++) {
            int k = rr * 4 + (tid >> 6);
            int n = tid & 63;
            Gs[k * 68 + n] = g_g[bbase + (size_t)(kk + k) * HWSZ + n0 + n];
        }
        __syncthreads();
        #pragma unroll
        for (int k = 0; k < 16; k++) {
            float4 a = *(float4*)&As[k * 68 + ti4];
            float4 g4 = *(float4*)&Gs[k * 68 + tj4];
            float ar[4] = {a.x, a.y, a.z, a.w};
            float gr[4] = {g4.x, g4.y, g4.z, g4.w};
            #pragma unroll
            for (int i = 0; i < 4; i++)
                #pragma unroll
                for (int j = 0; j < 4; j++)
                    acc[i][j] += ar[i] * gr[j];
        }
        __syncthreads();
    }

    float beta = *beta_p;
    #pragma unroll
    for (int i = 0; i < 4; i++)
        #pragma unroll
        for (int j = 0; j < 4; j++) {
            int irow = i0 + ti4 + i;
            int n = n0 + tj4 + j;
            size_t o = bbase + (size_t)irow * HWSZ + n;
            xout[o] = xin[o] + beta * acc[i][j];
        }
}

// ---------------------------------------------------------------------------
extern "C" void kernel_launch(void* const* d_in, const int* in_sizes, int n_in,
                              void* d_out, int out_size)
{
    const float* x      = (const float*)d_in[0];
    const float* wt     = (const float*)d_in[1];
    const float* bt     = (const float*)d_in[2];
    const float* wp     = (const float*)d_in[3];
    const float* bp     = (const float*)d_in[4];
    const float* wg     = (const float*)d_in[5];
    const float* bg     = (const float*)d_in[6];
    const float* beta_w = (const float*)d_in[7];
    const float* beta_h = (const float*)d_in[8];
    const float* beta_c = (const float*)d_in[9];
    float* out = (float*)d_out;

    float *x1, *x2, *S;
    cudaGetSymbolAddress((void**)&x1, g_x1);
    cudaGetSymbolAddress((void**)&x2, g_x2);
    cudaGetSymbolAddress((void**)&S,  g_S);

    size_t smem = 2 * 96 * 100 * sizeof(float);   // 76.8 KB
    cudaFuncSetAttribute(slice_logits_kernel,
                         cudaFuncAttributeMaxDynamicSharedMemorySize, (int)smem);
    cudaFuncSetAttribute(apply_slice_kernel,
                         cudaFuncAttributeMaxDynamicSharedMemorySize, (int)smem);

    dim3 cg(144, 4, 16);

    // ---- round 1: width attention ----
    conv3_kernel<<<cg, 256>>>(x, wt, bt, wp, bp, wg, bg);
    cudaMemsetAsync(S, 0, (size_t)16 * 96 * 96 * sizeof(float), 0);
    slice_logits_kernel<<<dim3(32, 16), 576, smem>>>(0);
    softmax_kernel<<<16 * 96, 256>>>(96);
    apply_slice_kernel<<<dim3(256, 16), 576, smem>>>(x, x1, beta_w, 0);

    // ---- round 2: height attention ----
    conv3_kernel<<<cg, 256>>>(x1, wt, bt, wp, bp, wg, bg);
    cudaMemsetAsync(S, 0, (size_t)16 * 96 * 96 * sizeof(float), 0);
    slice_logits_kernel<<<dim3(32, 16), 576, smem>>>(1);
    softmax_kernel<<<16 * 96, 256>>>(96);
    apply_slice_kernel<<<dim3(256, 16), 576, smem>>>(x1, x2, beta_h, 1);

    // ---- round 3: channel attention ----
    conv3_kernel<<<cg, 256>>>(x2, wt, bt, wp, bp, wg, bg);
    cudaMemsetAsync(S, 0, (size_t)16 * 256 * 256 * sizeof(float), 0);
    chan_logits_kernel<<<dim3(8, 16, 16), 256>>>();
    softmax_kernel<<<16 * 256, 256>>>(256);
    apply_channel_kernel<<<cg, 256>>>(x2, out, beta_c);
}

// round 2
// speedup vs baseline: 1.7089x; 1.7089x over previous
#include <cuda_runtime.h>
#include <math.h>
#include <stdint.h>

#define BB 16
#define CC 256
#define HH 96
#define WW 96
#define HWSZ (HH*WW)           // 9216
#define NELEM (BB*CC*HWSZ)     // 37,748,736

// Scratch (device globals: allocation-free rule)
__device__ float g_theta[NELEM];
__device__ float g_phi[NELEM];
__device__ float g_g[NELEM];
__device__ float g_x1[NELEM];
__device__ float g_x2[NELEM];
__device__ float g_S[BB*CC*CC];     // attention logits/probs, max 16*256*256
__device__ float g_Wcat[3*CC*CC];   // [theta; phi; g] stacked weights (768x256)

// ---------------------------------------------------------------------------
// tf32 helpers
// ---------------------------------------------------------------------------
__device__ __forceinline__ float tf32r(float f) {
    uint32_t u;
    asm("cvt.rna.tf32.f32 %0, %1;" : "=r"(u) : "f"(f));
    return __uint_as_float(u);
}

__device__ __forceinline__ void mma_m16n8k8(float (&d)[4], const uint32_t (&a)[4],
                                            uint32_t b0, uint32_t b1) {
    asm volatile(
        "mma.sync.aligned.m16n8k8.row.col.f32.tf32.tf32.f32 "
        "{%0,%1,%2,%3},{%4,%5,%6,%7},{%8,%9},{%0,%1,%2,%3};\n"
        : "+f"(d[0]), "+f"(d[1]), "+f"(d[2]), "+f"(d[3])
        : "r"(a[0]), "r"(a[1]), "r"(a[2]), "r"(a[3]), "r"(b0), "r"(b1));
}

// Warp-level MMA over a staged tile.
// As: [m][k] row-major, leading dim LDA (padded, LDA%32==4 for conflict-free frag loads)
// Bs: [k][n] row-major, leading dim LDB (LDB%32==4)
// Computes acc[MF][NF][4] over KS k-steps of 8.
template<int MF, int NF, int LDA, int LDB, int KS>
__device__ __forceinline__ void warp_mma(const float* As, const float* Bs,
                                         int m_warp, int n_warp, int lane,
                                         float (&acc)[MF][NF][4]) {
    int g = lane >> 2, tg = lane & 3;
    #pragma unroll
    for (int ks = 0; ks < KS; ks++) {
        int k0 = ks * 8;
        uint32_t a[MF][4];
        #pragma unroll
        for (int mf = 0; mf < MF; mf++) {
            const float* p = As + (m_warp + mf*16 + g) * LDA + k0 + tg;
            a[mf][0] = __float_as_uint(p[0]);
            a[mf][2] = __float_as_uint(p[4]);
            const float* p2 = p + 8 * LDA;
            a[mf][1] = __float_as_uint(p2[0]);
            a[mf][3] = __float_as_uint(p2[4]);
        }
        #pragma unroll
        for (int nf = 0; nf < NF; nf++) {
            const float* q = Bs + (k0 + tg) * LDB + n_warp + nf*8 + g;
            uint32_t b0 = __float_as_uint(q[0]);
            uint32_t b1 = __float_as_uint(q[4 * LDB]);
            #pragma unroll
            for (int mf = 0; mf < MF; mf++)
                mma_m16n8k8(acc[mf][nf], a[mf], b0, b1);
        }
    }
}

// ---------------------------------------------------------------------------
// conv3 tensor-core kernel: [768x256 Wcat] @ [256x9216 x_b] per batch.
// Block tile 128x128, BK=32, 256 threads (8 warps, 2x4, warp tile 64x32).
// Epilogue adds bias and scatters to g_theta / g_phi / g_g.
// ---------------------------------------------------------------------------
__global__ __launch_bounds__(256) void conv3_tc_kernel(
    const float* __restrict__ x,
    const float* __restrict__ bt, const float* __restrict__ bp,
    const float* __restrict__ bg)
{
    __shared__ __align__(16) float As[128 * 36];
    __shared__ __align__(16) float Bs[32 * 132];

    int b  = blockIdx.z;
    int m0 = blockIdx.y * 128;     // row in 0..767
    int n0 = blockIdx.x * 128;
    int tid = threadIdx.x;
    int wid = tid >> 5, lane = tid & 31;
    int m_warp = (wid >> 2) * 64;
    int n_warp = (wid & 3) * 32;

    const float* xb = x + (size_t)b * CC * HWSZ;
    float acc[4][4][4] = {};

    for (int kk = 0; kk < CC; kk += 32) {
        // stage A: Wcat[m0+m][kk+kh .. +16)
        {
            int m = tid >> 1, kh = (tid & 1) * 16;
            const float4* src = (const float4*)(g_Wcat + (size_t)(m0 + m) * 256 + kk + kh);
            float* dst = As + m * 36 + kh;
            #pragma unroll
            for (int j = 0; j < 4; j++) {
                float4 v = src[j];
                float4 w = make_float4(tf32r(v.x), tf32r(v.y), tf32r(v.z), tf32r(v.w));
                *(float4*)(dst + j * 4) = w;
            }
        }
        // stage B: x[kk+k][n0+ns .. +16)
        {
            int k = tid >> 3, ns = (tid & 7) * 16;
            const float4* src = (const float4*)(xb + (size_t)(kk + k) * HWSZ + n0 + ns);
            float* dst = Bs + k * 132 + ns;
            #pragma unroll
            for (int j = 0; j < 4; j++) {
                float4 v = src[j];
                float4 w = make_float4(tf32r(v.x), tf32r(v.y), tf32r(v.z), tf32r(v.w));
                *(float4*)(dst + j * 4) = w;
            }
        }
        __syncthreads();
        warp_mma<4, 4, 36, 132, 4>(As, Bs, m_warp, n_warp, lane, acc);
        __syncthreads();
    }

    // epilogue
    int g = lane >> 2, tg = lane & 3;
    int mat = m0 >> 8;                 // which of the 3 matrices (uniform per block)
    int orow_base = m0 & 255;
    float* dst = (mat == 0) ? g_theta : (mat == 1) ? g_phi : g_g;
    const float* bias = (mat == 0) ? bt : (mat == 1) ? bp : bg;

    #pragma unroll
    for (int mf = 0; mf < 4; mf++) {
        int row = m_warp + mf * 16 + g;
        int o1 = orow_base + row;
        int o2 = o1 + 8;
        float bv1 = bias[o1], bv2 = bias[o2];
        size_t base1 = ((size_t)b * CC + o1) * HWSZ + n0;
        size_t base2 = ((size_t)b * CC + o2) * HWSZ + n0;
        #pragma unroll
        for (int nf = 0; nf < 4; nf++) {
            int col = n_warp + nf * 8 + tg * 2;
            *(float2*)&dst[base1 + col] = make_float2(acc[mf][nf][0] + bv1,
                                                      acc[mf][nf][1] + bv1);
            *(float2*)&dst[base2 + col] = make_float2(acc[mf][nf][2] + bv2,
                                                      acc[mf][nf][3] + bv2);
        }
    }
}

// ---------------------------------------------------------------------------
// channel logits tensor kernel: S[b,i,j] = theta_i . phi_j, K=9216.
// 64x64 tile, BK=32, 128 threads (4 warps 2x2, warp tile 32x32). Direct store.
// ---------------------------------------------------------------------------
__global__ __launch_bounds__(128) void chan_logits_tc_kernel()
{
    __shared__ __align__(16) float As[64 * 36];
    __shared__ __align__(16) float Bs[32 * 68];

    int b  = blockIdx.z;
    int i0 = blockIdx.y * 64;
    int j0 = blockIdx.x * 64;
    int tid = threadIdx.x;
    int wid = tid >> 5, lane = tid & 31;
    int m_warp = (wid >> 1) * 32;
    int n_warp = (wid & 1) * 32;

    size_t bbase = (size_t)b * CC * HWSZ;
    float acc[2][4][4] = {};

    for (int kk = 0; kk < HWSZ; kk += 32) {
        // stage A: theta[i0+m][kk+kh..+16) direct
        {
            int m = tid >> 1, kh = (tid & 1) * 16;
            const float4* src = (const float4*)(g_theta + bbase + (size_t)(i0 + m) * HWSZ + kk + kh);
            float* dst = As + m * 36 + kh;
            #pragma unroll
            for (int j = 0; j < 4; j++) {
                float4 v = src[j];
                float4 w = make_float4(tf32r(v.x), tf32r(v.y), tf32r(v.z), tf32r(v.w));
                *(float4*)(dst + j * 4) = w;
            }
        }
        // stage B transposed: Bs[k][n] = phi[j0+n][kk+k]
        {
            int n = tid >> 1, kh = (tid & 1) * 16;
            const float4* src = (const float4*)(g_phi + bbase + (size_t)(j0 + n) * HWSZ + kk + kh);
            #pragma unroll
            for (int j = 0; j < 4; j++) {
                float4 v = src[j];
                Bs[(kh + j*4 + 0) * 68 + n] = tf32r(v.x);
                Bs[(kh + j*4 + 1) * 68 + n] = tf32r(v.y);
                Bs[(kh + j*4 + 2) * 68 + n] = tf32r(v.z);
                Bs[(kh + j*4 + 3) * 68 + n] = tf32r(v.w);
            }
        }
        __syncthreads();
        warp_mma<2, 4, 36, 68, 4>(As, Bs, m_warp, n_warp, lane, acc);
        __syncthreads();
    }

    int g = lane >> 2, tg = lane & 3;
    float* Sb = g_S + (size_t)b * 65536;
    #pragma unroll
    for (int mf = 0; mf < 2; mf++) {
        int row = m_warp + mf * 16 + g;
        #pragma unroll
        for (int nf = 0; nf < 4; nf++) {
            int col = n_warp + nf * 8 + tg * 2;
            *(float2*)&Sb[(size_t)(i0 + row) * 256 + j0 + col] =
                make_float2(acc[mf][nf][0], acc[mf][nf][1]);
            *(float2*)&Sb[(size_t)(i0 + row + 8) * 256 + j0 + col] =
                make_float2(acc[mf][nf][2], acc[mf][nf][3]);
        }
    }
}

// ---------------------------------------------------------------------------
// apply_channel tensor kernel: out = xin + beta * (P[256x256] @ g[256x9216]).
// Same tile shape as conv3_tc.
// ---------------------------------------------------------------------------
__global__ __launch_bounds__(256) void apply_channel_tc_kernel(
    const float* __restrict__ xin, float* __restrict__ xout,
    const float* __restrict__ beta_p)
{
    __shared__ __align__(16) float As[128 * 36];
    __shared__ __align__(16) float Bs[32 * 132];

    int b  = blockIdx.z;
    int m0 = blockIdx.y * 128;     // 0 or 128
    int n0 = blockIdx.x * 128;
    int tid = threadIdx.x;
    int wid = tid >> 5, lane = tid & 31;
    int m_warp = (wid >> 2) * 64;
    int n_warp = (wid & 3) * 32;

    const float* Pb = g_S + (size_t)b * 65536;
    size_t bbase = (size_t)b * CC * HWSZ;
    float acc[4][4][4] = {};

    for (int kk = 0; kk < CC; kk += 32) {
        {
            int m = tid >> 1, kh = (tid & 1) * 16;
            const float4* src = (const float4*)(Pb + (size_t)(m0 + m) * 256 + kk + kh);
            float* dst = As + m * 36 + kh;
            #pragma unroll
            for (int j = 0; j < 4; j++) {
                float4 v = src[j];
                float4 w = make_float4(tf32r(v.x), tf32r(v.y), tf32r(v.z), tf32r(v.w));
                *(float4*)(dst + j * 4) = w;
            }
        }
        {
            int k = tid >> 3, ns = (tid & 7) * 16;
            const float4* src = (const float4*)(g_g + bbase + (size_t)(kk + k) * HWSZ + n0 + ns);
            float* dst = Bs + k * 132 + ns;
            #pragma unroll
            for (int j = 0; j < 4; j++) {
                float4 v = src[j];
                float4 w = make_float4(tf32r(v.x), tf32r(v.y), tf32r(v.z), tf32r(v.w));
                *(float4*)(dst + j * 4) = w;
            }
        }
        __syncthreads();
        warp_mma<4, 4, 36, 132, 4>(As, Bs, m_warp, n_warp, lane, acc);
        __syncthreads();
    }

    int g = lane >> 2, tg = lane & 3;
    float beta = *beta_p;
    #pragma unroll
    for (int mf = 0; mf < 4; mf++) {
        int row = m0 + m_warp + mf * 16 + g;
        size_t base1 = ((size_t)b * CC + row) * HWSZ + n0;
        size_t base2 = ((size_t)b * CC + row + 8) * HWSZ + n0;
        #pragma unroll
        for (int nf = 0; nf < 4; nf++) {
            int col = n_warp + nf * 8 + tg * 2;
            float2 xi1 = *(const float2*)&xin[base1 + col];
            float2 xi2 = *(const float2*)&xin[base2 + col];
            *(float2*)&xout[base1 + col] =
                make_float2(xi1.x + beta * acc[mf][nf][0], xi1.y + beta * acc[mf][nf][1]);
            *(float2*)&xout[base2 + col] =
                make_float2(xi2.x + beta * acc[mf][nf][2], xi2.y + beta * acc[mf][nf][3]);
        }
    }
}

// ---------------------------------------------------------------------------
// slice_logits: width (mode 0) / height (mode 1) attention logits (fp32).
// ---------------------------------------------------------------------------
__global__ __launch_bounds__(576) void slice_logits_kernel(int mode)
{
    extern __shared__ float sm[];
    float* Ts = sm;               // [96][100]
    float* Ps = sm + 96 * 100;

    int b = blockIdx.y;
    int cchunk = blockIdx.x;      // 32 chunks of 8 channels
    int tid = threadIdx.x;
    int r0 = (tid / 24) * 4;
    int c0 = (tid % 24) * 4;

    float acc[4][4] = {};

    for (int cc = 0; cc < 8; cc++) {
        int c = cchunk * 8 + cc;
        size_t base = ((size_t)b * CC + c) * HWSZ;
        #pragma unroll
        for (int r = 0; r < 16; r++) {
            int idx = r * 576 + tid;          // 0..9215
            int hh = idx / 96, ww = idx % 96;
            float tv = g_theta[base + idx];
            float pv = g_phi[base + idx];
            if (mode == 0) { Ts[hh*100 + ww] = tv; Ps[hh*100 + ww] = pv; }
            else           { Ts[ww*100 + hh] = tv; Ps[ww*100 + hh] = pv; }
        }
        __syncthreads();
        #pragma unroll 4
        for (int k = 0; k < 96; k++) {
            float4 a = *(float4*)&Ts[k*100 + r0];
            float4 p = *(float4*)&Ps[k*100 + c0];
            float ar[4] = {a.x, a.y, a.z, a.w};
            float pr[4] = {p.x, p.y, p.z, p.w};
            #pragma unroll
            for (int i = 0; i < 4; i++)
                #pragma unroll
                for (int j = 0; j < 4; j++)
                    acc[i][j] += ar[i] * pr[j];
        }
        __syncthreads();
    }

    float* Sb = g_S + (size_t)b * 96 * 96;
    #pragma unroll
    for (int i = 0; i < 4; i++)
        #pragma unroll
        for (int j = 0; j < 4; j++)
            atomicAdd(&Sb[(r0 + i) * 96 + (c0 + j)], acc[i][j]);
}

// ---------------------------------------------------------------------------
// softmax over last dim of g_S rows; one block per row, in place.
// ---------------------------------------------------------------------------
__global__ __launch_bounds__(256) void softmax_kernel(int n)
{
    size_t base = (size_t)blockIdx.x * n;
    int tid = threadIdx.x;
    __shared__ float red[8];

    float m = -INFINITY;
    for (int j = tid; j < n; j += 256) m = fmaxf(m, g_S[base + j]);
    #pragma unroll
    for (int o = 16; o; o >>= 1) m = fmaxf(m, __shfl_xor_sync(0xffffffffu, m, o));
    if ((tid & 31) == 0) red[tid >> 5] = m;
    __syncthreads();
    float mm = red[0];
    #pragma unroll
    for (int w = 1; w < 8; w++) mm = fmaxf(mm, red[w]);
    __syncthreads();

    float s = 0.f;
    for (int j = tid; j < n; j += 256) {
        float e = __expf(g_S[base + j] - mm);
        g_S[base + j] = e;
        s += e;
    }
    #pragma unroll
    for (int o = 16; o; o >>= 1) s += __shfl_xor_sync(0xffffffffu, s, o);
    if ((tid & 31) == 0) red[tid >> 5] = s;
    __syncthreads();
    float st = 0.f;
    #pragma unroll
    for (int w = 0; w < 8; w++) st += red[w];
    float inv = 1.0f / st;
    for (int j = tid; j < n; j += 256) g_S[base + j] *= inv;
}

// ---------------------------------------------------------------------------
// apply_slice (fp32): x_out = x_in + beta * attention along width/height.
// ---------------------------------------------------------------------------
__global__ __launch_bounds__(576) void apply_slice_kernel(
    const float* __restrict__ xin, float* __restrict__ xout,
    const float* __restrict__ beta_p, int mode)
{
    extern __shared__ float sm[];
    float* As = sm;               // [j][i] : A transposed
    float* Gs = sm + 96 * 100;    // mode0: [j][h] (transposed), mode1: [j][w]

    int b = blockIdx.y, c = blockIdx.x;
    int tid = threadIdx.x;
    size_t base = ((size_t)b * CC + c) * HWSZ;
    const float* Sb = g_S + (size_t)b * 9216;

    #pragma unroll
    for (int r = 0; r < 16; r++) {
        int idx = r * 576 + tid;
        int i = idx / 96, j = idx % 96;
        As[j * 100 + i] = Sb[idx];
        float gv = g_g[base + idx];
        int rr_ = idx / 96, cc_ = idx % 96;
        if (mode == 0) Gs[cc_ * 100 + rr_] = gv;
        else           Gs[rr_ * 100 + cc_] = gv;
    }
    __syncthreads();

    const float* L = (mode == 0) ? Gs : As;
    const float* R = (mode == 0) ? As : Gs;
    int r0 = (tid / 24) * 4;
    int c0 = (tid % 24) * 4;

    float acc[4][4] = {};
    #pragma unroll 4
    for (int k = 0; k < 96; k++) {
        float4 l = *(const float4*)&L[k * 100 + r0];
        float4 rv = *(const float4*)&R[k * 100 + c0];
        float lr[4] = {l.x, l.y, l.z, l.w};
        float rr[4] = {rv.x, rv.y, rv.z, rv.w};
        #pragma unroll
        for (int i = 0; i < 4; i++)
            #pragma unroll
            for (int j = 0; j < 4; j++)
                acc[i][j] += lr[i] * rr[j];
    }

    float beta = *beta_p;
    #pragma unroll
    for (int i = 0; i < 4; i++)
        #pragma unroll
        for (int j = 0; j < 4; j++) {
            size_t o = base + (size_t)(r0 + i) * 96 + (c0 + j);
            xout[o] = xin[o] + beta * acc[i][j];
        }
}

// ---------------------------------------------------------------------------
extern "C" void kernel_launch(void* const* d_in, const int* in_sizes, int n_in,
                              void* d_out, int out_size)
{
    const float* x      = (const float*)d_in[0];
    const float* wt     = (const float*)d_in[1];
    const float* bt     = (const float*)d_in[2];
    const float* wp     = (const float*)d_in[3];
    const float* bp     = (const float*)d_in[4];
    const float* wg     = (const float*)d_in[5];
    const float* bg     = (const float*)d_in[6];
    const float* beta_w = (const float*)d_in[7];
    const float* beta_h = (const float*)d_in[8];
    const float* beta_c = (const float*)d_in[9];
    float* out = (float*)d_out;

    float *x1, *x2, *S, *Wcat;
    cudaGetSymbolAddress((void**)&x1, g_x1);
    cudaGetSymbolAddress((void**)&x2, g_x2);
    cudaGetSymbolAddress((void**)&S,  g_S);
    cudaGetSymbolAddress((void**)&Wcat, g_Wcat);

    size_t smem = 2 * 96 * 100 * sizeof(float);   // 76.8 KB
    cudaFuncSetAttribute(slice_logits_kernel,
                         cudaFuncAttributeMaxDynamicSharedMemorySize, (int)smem);
    cudaFuncSetAttribute(apply_slice_kernel,
                         cudaFuncAttributeMaxDynamicSharedMemorySize, (int)smem);

    // stack W_theta / W_phi / W_g into Wcat (768 x 256)
    size_t wbytes = (size_t)CC * CC * sizeof(float);
    cudaMemcpyAsync(Wcat,             wt, wbytes, cudaMemcpyDeviceToDevice, 0);
    cudaMemcpyAsync(Wcat + CC*CC,     wp, wbytes, cudaMemcpyDeviceToDevice, 0);
    cudaMemcpyAsync(Wcat + 2*CC*CC,   wg, wbytes, cudaMemcpyDeviceToDevice, 0);

    dim3 convg(72, 6, 16);

    // ---- round 1: width attention ----
    conv3_tc_kernel<<<convg, 256>>>(x, bt, bp, bg);
    cudaMemsetAsync(S, 0, (size_t)16 * 96 * 96 * sizeof(float), 0);
    slice_logits_kernel<<<dim3(32, 16), 576, smem>>>(0);
    softmax_kernel<<<16 * 96, 256>>>(96);
    apply_slice_kernel<<<dim3(256, 16), 576, smem>>>(x, x1, beta_w, 0);

    // ---- round 2: height attention ----
    conv3_tc_kernel<<<convg, 256>>>(x1, bt, bp, bg);
    cudaMemsetAsync(S, 0, (size_t)16 * 96 * 96 * sizeof(float), 0);
    slice_logits_kernel<<<dim3(32, 16), 576, smem>>>(1);
    softmax_kernel<<<16 * 96, 256>>>(96);
    apply_slice_kernel<<<dim3(256, 16), 576, smem>>>(x1, x2, beta_h, 1);

    // ---- round 3: channel attention ----
    conv3_tc_kernel<<<convg, 256>>>(x2, bt, bp, bg);
    chan_logits_tc_kernel<<<dim3(4, 4, 16), 128>>>();
    softmax_kernel<<<16 * 256, 256>>>(256);
    apply_channel_tc_kernel<<<dim3(72, 2, 16), 256>>>(x2, out, beta_c);
}

// round 3
// speedup vs baseline: 3.1292x; 1.8311x over previous
#include <cuda_runtime.h>
#include <cuda_bf16.h>
#include <math.h>
#include <stdint.h>

#define BB 16
#define CC 256
#define HH 96
#define WW 96
#define HWSZ (HH*WW)           // 9216
#define NELEM (BB*CC*HWSZ)     // 37,748,736

// Scratch (device globals: allocation-free rule)
__device__ __nv_bfloat16 g_thb[NELEM];
__device__ __nv_bfloat16 g_phb[NELEM];
__device__ __nv_bfloat16 g_gb[NELEM];
__device__ float g_x1[NELEM];
__device__ float g_x2[NELEM];
__device__ float g_S[BB*CC*CC];          // logits/probs fp32
__device__ __nv_bfloat16 g_Wbf[3*CC*CC]; // [theta; phi; g] weights bf16 (768x256)

// ---------------------------------------------------------------------------
// helpers
// ---------------------------------------------------------------------------
__device__ __forceinline__ uint32_t smem_u32(const void* p) {
    return (uint32_t)__cvta_generic_to_shared(p);
}
__device__ __forceinline__ uint32_t packbf(float lo, float hi) {
    __nv_bfloat162 h = __floats2bfloat162_rn(lo, hi);
    return *(uint32_t*)&h;
}
__device__ __forceinline__ void ldsm4(uint32_t& r0, uint32_t& r1, uint32_t& r2, uint32_t& r3, uint32_t a) {
    asm volatile("ldmatrix.sync.aligned.m8n8.x4.shared.b16 {%0,%1,%2,%3},[%4];"
                 : "=r"(r0), "=r"(r1), "=r"(r2), "=r"(r3) : "r"(a));
}
__device__ __forceinline__ void ldsm4t(uint32_t& r0, uint32_t& r1, uint32_t& r2, uint32_t& r3, uint32_t a) {
    asm volatile("ldmatrix.sync.aligned.m8n8.x4.trans.shared.b16 {%0,%1,%2,%3},[%4];"
                 : "=r"(r0), "=r"(r1), "=r"(r2), "=r"(r3) : "r"(a));
}
__device__ __forceinline__ void ldsm2(uint32_t& r0, uint32_t& r1, uint32_t a) {
    asm volatile("ldmatrix.sync.aligned.m8n8.x2.shared.b16 {%0,%1},[%2];"
                 : "=r"(r0), "=r"(r1) : "r"(a));
}
__device__ __forceinline__ void ldsm2t(uint32_t& r0, uint32_t& r1, uint32_t a) {
    asm volatile("ldmatrix.sync.aligned.m8n8.x2.trans.shared.b16 {%0,%1},[%2];"
                 : "=r"(r0), "=r"(r1) : "r"(a));
}
__device__ __forceinline__ void mma_bf16(float (&d)[4], uint32_t a0, uint32_t a1, uint32_t a2, uint32_t a3,
                                         uint32_t b0, uint32_t b1) {
    asm volatile(
        "mma.sync.aligned.m16n8k16.row.col.f32.bf16.bf16.f32 "
        "{%0,%1,%2,%3},{%4,%5,%6,%7},{%8,%9},{%0,%1,%2,%3};"
        : "+f"(d[0]), "+f"(d[1]), "+f"(d[2]), "+f"(d[3])
        : "r"(a0), "r"(a1), "r"(a2), "r"(a3), "r"(b0), "r"(b1));
}

// ---------------------------------------------------------------------------
// weight convert: wt/wp/wg fp32 -> g_Wbf bf16 (768x256)
// ---------------------------------------------------------------------------
__global__ void wconv_kernel(const float* __restrict__ wt, const float* __restrict__ wp,
                             const float* __restrict__ wg) {
    int i = blockIdx.x * 256 + threadIdx.x;       // 196608 total
    const float* src = (i < 65536) ? wt : (i < 131072 ? wp : wg);
    g_Wbf[i] = __float2bfloat16(src[i & 65535]);
}

// ---------------------------------------------------------------------------
// conv3: [768x256 Wbf] @ [256x9216 x_b]; tile 128x128, BK=64, 8 warps (2x4).
// Outputs theta/phi/g as bf16.
// ---------------------------------------------------------------------------
__global__ __launch_bounds__(256) void conv3_bf16_kernel(
    const float* __restrict__ x,
    const float* __restrict__ bt, const float* __restrict__ bp, const float* __restrict__ bg)
{
    __shared__ __align__(16) __nv_bfloat16 As[128][72];   // [m][k]
    __shared__ __align__(16) __nv_bfloat16 Bs[64][136];   // [k][n]

    int b = blockIdx.z, m0 = blockIdx.y * 128, n0 = blockIdx.x * 128;
    int tid = threadIdx.x, wid = tid >> 5, lane = tid & 31;
    int mw = (wid >> 2) * 64, nw = (wid & 3) * 32;
    int g = lane >> 2, tg = lane & 3;
    const float* xb = x + (size_t)b * CC * HWSZ;

    float acc[4][4][4] = {};
    int am = tid >> 1, akh = (tid & 1) * 32;
    int bk = tid >> 2, bns = (tid & 3) * 32;

    for (int kk = 0; kk < 256; kk += 64) {
        {   // A stage: bf16 direct copy
            const uint4* src = (const uint4*)(g_Wbf + (size_t)(m0 + am) * 256 + kk + akh);
            uint4* dst = (uint4*)&As[am][akh];
            dst[0] = src[0]; dst[1] = src[1]; dst[2] = src[2]; dst[3] = src[3];
        }
        {   // B stage: fp32 -> bf16
            const float4* src = (const float4*)(xb + (size_t)(kk + bk) * HWSZ + n0 + bns);
            uint4* dst = (uint4*)&Bs[bk][bns];
            #pragma unroll
            for (int j = 0; j < 4; j++) {
                float4 f0 = src[2*j], f1 = src[2*j+1];
                uint4 v;
                v.x = packbf(f0.x, f0.y); v.y = packbf(f0.z, f0.w);
                v.z = packbf(f1.x, f1.y); v.w = packbf(f1.z, f1.w);
                dst[j] = v;
            }
        }
        __syncthreads();
        #pragma unroll
        for (int ks = 0; ks < 4; ks++) {
            int k0 = ks * 16;
            uint32_t a[4][4], bf[4][2];
            #pragma unroll
            for (int mf = 0; mf < 4; mf++)
                ldsm4(a[mf][0], a[mf][1], a[mf][2], a[mf][3],
                      smem_u32(&As[mw + mf*16 + (lane & 15)][k0 + (lane >> 4) * 8]));
            #pragma unroll
            for (int nb = 0; nb < 2; nb++)
                ldsm4t(bf[nb*2][0], bf[nb*2][1], bf[nb*2+1][0], bf[nb*2+1][1],
                       smem_u32(&Bs[k0 + (lane & 15)][nw + nb*16 + (lane >> 4) * 8]));
            #pragma unroll
            for (int mf = 0; mf < 4; mf++)
                #pragma unroll
                for (int nf = 0; nf < 4; nf++)
                    mma_bf16(acc[mf][nf], a[mf][0], a[mf][1], a[mf][2], a[mf][3],
                             bf[nf][0], bf[nf][1]);
        }
        __syncthreads();
    }

    int mat = m0 >> 8, ob = m0 & 255;
    __nv_bfloat16* dst = (mat == 0) ? g_thb : (mat == 1) ? g_phb : g_gb;
    const float* bias = (mat == 0) ? bt : (mat == 1) ? bp : bg;
    #pragma unroll
    for (int mf = 0; mf < 4; mf++) {
        int r = mw + mf * 16 + g;
        int o1 = ob + r, o2 = o1 + 8;
        float b1 = bias[o1], b2 = bias[o2];
        size_t base1 = ((size_t)b * CC + o1) * HWSZ + n0;
        size_t base2 = ((size_t)b * CC + o2) * HWSZ + n0;
        #pragma unroll
        for (int nf = 0; nf < 4; nf++) {
            int col = nw + nf * 8 + tg * 2;
            *(uint32_t*)&dst[base1 + col] = packbf(acc[mf][nf][0] + b1, acc[mf][nf][1] + b1);
            *(uint32_t*)&dst[base2 + col] = packbf(acc[mf][nf][2] + b2, acc[mf][nf][3] + b2);
        }
    }
}

// ---------------------------------------------------------------------------
// slice logits: MODE 0 = width (k=(c,h), m=i=w), MODE 1 = height (k=(c,w), m=i=h).
// Staging identical (smem row = h, cols = w); only ldmatrix addressing differs.
// Block: 16 channels, 96x96 out, atomicAdd into S. 8 warps (2x4), warp 48x24.
// ---------------------------------------------------------------------------
template<int MODE>
__global__ __launch_bounds__(256) void slice_logits_bf16_kernel()
{
    __shared__ __align__(16) __nv_bfloat16 As[96][104];
    __shared__ __align__(16) __nv_bfloat16 Bs[96][104];

    int b = blockIdx.y, cch = blockIdx.x;
    int tid = threadIdx.x, wid = tid >> 5, lane = tid & 31;
    int mw = (wid >> 2) * 48, nw = (wid & 3) * 24;
    int g = lane >> 2, tg = lane & 3;

    float acc[3][3][4] = {};

    for (int cc = 0; cc < 16; cc++) {
        int c = cch * 16 + cc;
        const uint32_t* tsrc = (const uint32_t*)(g_thb + ((size_t)b * CC + c) * HWSZ);
        const uint32_t* psrc = (const uint32_t*)(g_phb + ((size_t)b * CC + c) * HWSZ);
        #pragma unroll
        for (int j = 0; j < 18; j++) {
            int lin = j * 256 + tid;
            int row = lin / 48, col = lin % 48;
            ((uint32_t*)&As[row][0])[col] = tsrc[row * 48 + col];
            ((uint32_t*)&Bs[row][0])[col] = psrc[row * 48 + col];
        }
        __syncthreads();
        #pragma unroll
        for (int ks = 0; ks < 6; ks++) {
            int k0 = ks * 16;
            uint32_t a[3][4], bf[3][2];
            #pragma unroll
            for (int mf = 0; mf < 3; mf++) {
                if (MODE == 0)   // As = [k][m] -> trans
                    ldsm4t(a[mf][0], a[mf][1], a[mf][2], a[mf][3],
                        smem_u32(&As[k0 + ((lane>>4)&1)*8 + (lane&7)][mw + mf*16 + ((lane>>3)&1)*8]));
                else             // As = [m][k] -> non-trans
                    ldsm4(a[mf][0], a[mf][1], a[mf][2], a[mf][3],
                        smem_u32(&As[mw + mf*16 + (lane&15)][k0 + (lane>>4)*8]));
            }
            if (MODE == 0) {     // Bs = [k][n] -> trans
                ldsm4t(bf[0][0], bf[0][1], bf[1][0], bf[1][1],
                       smem_u32(&Bs[k0 + (lane&15)][nw + (lane>>4)*8]));
                ldsm2t(bf[2][0], bf[2][1],
                       smem_u32(&Bs[k0 + (lane&15)][nw + 16]));
            } else {             // Bs = [n][k] -> non-trans
                ldsm4(bf[0][0], bf[0][1], bf[1][0], bf[1][1],
                      smem_u32(&Bs[nw + (lane>>4)*8 + (lane&7)][k0 + ((lane>>3)&1)*8]));
                ldsm2(bf[2][0], bf[2][1],
                      smem_u32(&Bs[nw + 16 + (lane&7)][k0 + ((lane>>3)&1)*8]));
            }
            #pragma unroll
            for (int mf = 0; mf < 3; mf++)
                #pragma unroll
                for (int nf = 0; nf < 3; nf++)
                    mma_bf16(acc[mf][nf], a[mf][0], a[mf][1], a[mf][2], a[mf][3],
                             bf[nf][0], bf[nf][1]);
        }
        __syncthreads();
    }
    float* Sb = g_S + (size_t)b * 9216;
    #pragma unroll
    for (int mf = 0; mf < 3; mf++) {
        int i1 = mw + mf * 16 + g, i2 = i1 + 8;
        #pragma unroll
        for (int nf = 0; nf < 3; nf++) {
            int jc = nw + nf * 8 + tg * 2;
            atomicAdd(&Sb[i1 * 96 + jc],     acc[mf][nf][0]);
            atomicAdd(&Sb[i1 * 96 + jc + 1], acc[mf][nf][1]);
            atomicAdd(&Sb[i2 * 96 + jc],     acc[mf][nf][2]);
            atomicAdd(&Sb[i2 * 96 + jc + 1], acc[mf][nf][3]);
        }
    }
}

// ---------------------------------------------------------------------------
// softmax over last dim of g_S rows; one block per row, in place.
// ---------------------------------------------------------------------------
__global__ __launch_bounds__(256) void softmax_kernel(int n)
{
    size_t base = (size_t)blockIdx.x * n;
    int tid = threadIdx.x;
    __shared__ float red[8];

    float m = -INFINITY;
    for (int j = tid; j < n; j += 256) m = fmaxf(m, g_S[base + j]);
    #pragma unroll
    for (int o = 16; o; o >>= 1) m = fmaxf(m, __shfl_xor_sync(0xffffffffu, m, o));
    if ((tid & 31) == 0) red[tid >> 5] = m;
    __syncthreads();
    float mm = red[0];
    #pragma unroll
    for (int w = 1; w < 8; w++) mm = fmaxf(mm, red[w]);
    __syncthreads();

    float s = 0.f;
    for (int j = tid; j < n; j += 256) {
        float e = __expf(g_S[base + j] - mm);
        g_S[base + j] = e;
        s += e;
    }
    #pragma unroll
    for (int o = 16; o; o >>= 1) s += __shfl_xor_sync(0xffffffffu, s, o);
    if ((tid & 31) == 0) red[tid >> 5] = s;
    __syncthreads();
    float st = 0.f;
    #pragma unroll
    for (int w = 0; w < 8; w++) st += red[w];
    float inv = 1.0f / st;
    for (int j = tid; j < n; j += 256) g_S[base + j] *= inv;
}

// ---------------------------------------------------------------------------
// apply width: D[(c,h), i] = sum_j g[(c,h), j] P[i,j];  out = xin + beta*D.
// A = g rows [m][k] non-trans; B = P [n][k] non-trans. M-tile 128, N=96, K=96.
// 8 warps (4m x 2n), warp 32x48.
// ---------------------------------------------------------------------------
__global__ __launch_bounds__(256) void apply_slice_w_kernel(
    const float* __restrict__ xin, float* __restrict__ xout, const float* __restrict__ beta_p)
{
    __shared__ __align__(16) __nv_bfloat16 As[128][104];
    __shared__ __align__(16) __nv_bfloat16 Bs[96][104];

    int b = blockIdx.y, m0 = blockIdx.x * 128;
    int tid = threadIdx.x, wid = tid >> 5, lane = tid & 31;
    int mw = (wid >> 1) * 32, nw = (wid & 1) * 48;
    int g = lane >> 2, tg = lane & 3;

    const uint32_t* gsrc = (const uint32_t*)(g_gb + (size_t)b * CC * HWSZ) + (size_t)m0 * 48;
    #pragma unroll
    for (int j = 0; j < 24; j++) {
        int lin = j * 256 + tid;
        int row = lin / 48, col = lin % 48;
        ((uint32_t*)&As[row][0])[col] = gsrc[row * 48 + col];
    }
    const float* Sb = g_S + (size_t)b * 9216;
    #pragma unroll
    for (int j = 0; j < 18; j++) {
        int lin = j * 256 + tid;
        int row = lin / 48, col = lin % 48;
        float2 f = *(const float2*)&Sb[row * 96 + col * 2];
        ((uint32_t*)&Bs[row][0])[col] = packbf(f.x, f.y);
    }
    __syncthreads();

    float acc[2][6][4] = {};
    #pragma unroll
    for (int ks = 0; ks < 6; ks++) {
        int k0 = ks * 16;
        uint32_t a[2][4], bf[6][2];
        #pragma unroll
        for (int mf = 0; mf < 2; mf++)
            ldsm4(a[mf][0], a[mf][1], a[mf][2], a[mf][3],
                  smem_u32(&As[mw + mf*16 + (lane&15)][k0 + (lane>>4)*8]));
        #pragma unroll
        for (int nb = 0; nb < 3; nb++)
            ldsm4(bf[nb*2][0], bf[nb*2][1], bf[nb*2+1][0], bf[nb*2+1][1],
                  smem_u32(&Bs[nw + nb*16 + (lane>>4)*8 + (lane&7)][k0 + ((lane>>3)&1)*8]));
        #pragma unroll
        for (int mf = 0; mf < 2; mf++)
            #pragma unroll
            for (int nf = 0; nf < 6; nf++)
                mma_bf16(acc[mf][nf], a[mf][0], a[mf][1], a[mf][2], a[mf][3],
                         bf[nf][0], bf[nf][1]);
    }
    float beta = *beta_p;
    size_t gb = (size_t)b * CC * HWSZ;
    #pragma unroll
    for (int mf = 0; mf < 2; mf++) {
        int r1 = m0 + mw + mf * 16 + g, r2 = r1 + 8;
        #pragma unroll
        for (int nf = 0; nf < 6; nf++) {
            int col = nw + nf * 8 + tg * 2;
            size_t o1 = gb + (size_t)r1 * 96 + col;
            size_t o2 = gb + (size_t)r2 * 96 + col;
            float2 xa = *(const float2*)&xin[o1];
            float2 xb2 = *(const float2*)&xin[o2];
            *(float2*)&xout[o1] = make_float2(xa.x + beta*acc[mf][nf][0], xa.y + beta*acc[mf][nf][1]);
            *(float2*)&xout[o2] = make_float2(xb2.x + beta*acc[mf][nf][2], xb2.y + beta*acc[mf][nf][3]);
        }
    }
}

// ---------------------------------------------------------------------------
// apply height: per (b,c): D[i=h, w] = sum_j P[i,j] g[c,j,w]; out = xin + beta*D.
// A = P [m][k] non-trans (cvt from fp32); B = g [k][n] trans. 96x96x96.
// 8 warps (2m x 4n), warp 48x24.
// ---------------------------------------------------------------------------
__global__ __launch_bounds__(256) void apply_slice_h_kernel(
    const float* __restrict__ xin, float* __restrict__ xout, const float* __restrict__ beta_p)
{
    __shared__ __align__(16) __nv_bfloat16 As[96][104];
    __shared__ __align__(16) __nv_bfloat16 Bs[96][104];

    int b = blockIdx.y, c = blockIdx.x;
    int tid = threadIdx.x, wid = tid >> 5, lane = tid & 31;
    int mw = (wid >> 2) * 48, nw = (wid & 3) * 24;
    int g = lane >> 2, tg = lane & 3;

    const float* Sb = g_S + (size_t)b * 9216;
    const uint32_t* gsrc = (const uint32_t*)(g_gb + ((size_t)b * CC + c) * HWSZ);
    #pragma unroll
    for (int j = 0; j < 18; j++) {
        int lin = j * 256 + tid;
        int row = lin / 48, col = lin % 48;
        float2 f = *(const float2*)&Sb[row * 96 + col * 2];
        ((uint32_t*)&As[row][0])[col] = packbf(f.x, f.y);
        ((uint32_t*)&Bs[row][0])[col] = gsrc[row * 48 + col];
    }
    __syncthreads();

    float acc[3][3][4] = {};
    #pragma unroll
    for (int ks = 0; ks < 6; ks++) {
        int k0 = ks * 16;
        uint32_t a[3][4], bf[3][2];
        #pragma unroll
        for (int mf = 0; mf < 3; mf++)
            ldsm4(a[mf][0], a[mf][1], a[mf][2], a[mf][3],
                  smem_u32(&As[mw + mf*16 + (lane&15)][k0 + (lane>>4)*8]));
        ldsm4t(bf[0][0], bf[0][1], bf[1][0], bf[1][1],
               smem_u32(&Bs[k0 + (lane&15)][nw + (lane>>4)*8]));
        ldsm2t(bf[2][0], bf[2][1],
               smem_u32(&Bs[k0 + (lane&15)][nw + 16]));
        #pragma unroll
        for (int mf = 0; mf < 3; mf++)
            #pragma unroll
            for (int nf = 0; nf < 3; nf++)
                mma_bf16(acc[mf][nf], a[mf][0], a[mf][1], a[mf][2], a[mf][3],
                         bf[nf][0], bf[nf][1]);
    }
    float beta = *beta_p;
    size_t base = ((size_t)b * CC + c) * HWSZ;
    #pragma unroll
    for (int mf = 0; mf < 3; mf++) {
        int i1 = mw + mf * 16 + g, i2 = i1 + 8;
        #pragma unroll
        for (int nf = 0; nf < 3; nf++) {
            int col = nw + nf * 8 + tg * 2;
            size_t o1 = base + (size_t)i1 * 96 + col;
            size_t o2 = base + (size_t)i2 * 96 + col;
            float2 xa = *(const float2*)&xin[o1];
            float2 xb2 = *(const float2*)&xin[o2];
            *(float2*)&xout[o1] = make_float2(xa.x + beta*acc[mf][nf][0], xa.y + beta*acc[mf][nf][1]);
            *(float2*)&xout[o2] = make_float2(xb2.x + beta*acc[mf][nf][2], xb2.y + beta*acc[mf][nf][3]);
        }
    }
}

// ---------------------------------------------------------------------------
// channel logits: S[i,j] = theta[i,:].phi[j,:], K=9216. Tile 64x64, BK=64.
// 4 warps (2x2), warp 32x32. A [m][k] non-trans; B [n][k] non-trans.
// ---------------------------------------------------------------------------
__global__ __launch_bounds__(128) void chan_logits_bf16_kernel()
{
    __shared__ __align__(16) __nv_bfloat16 As[64][72];
    __shared__ __align__(16) __nv_bfloat16 Bs[64][72];

    int b = blockIdx.z, i0 = blockIdx.y * 64, j0 = blockIdx.x * 64;
    int tid = threadIdx.x, wid = tid >> 5, lane = tid & 31;
    int mw = (wid >> 1) * 32, nw = (wid & 1) * 32;
    int g = lane >> 2, tg = lane & 3;

    float acc[2][4][4] = {};
    int r = tid >> 1, kh = (tid & 1) * 32;

    for (int kk = 0; kk < HWSZ; kk += 64) {
        {
            const uint4* ts = (const uint4*)(g_thb + ((size_t)b * CC + i0 + r) * HWSZ + kk + kh);
            const uint4* ps = (const uint4*)(g_phb + ((size_t)b * CC + j0 + r) * HWSZ + kk + kh);
            uint4* da = (uint4*)&As[r][kh];
            uint4* db = (uint4*)&Bs[r][kh];
            da[0]=ts[0]; da[1]=ts[1]; da[2]=ts[2]; da[3]=ts[3];
            db[0]=ps[0]; db[1]=ps[1]; db[2]=ps[2]; db[3]=ps[3];
        }
        __syncthreads();
        #pragma unroll
        for (int ks = 0; ks < 4; ks++) {
            int k0 = ks * 16;
            uint32_t a[2][4], bf[4][2];
            #pragma unroll
            for (int mf = 0; mf < 2; mf++)
                ldsm4(a[mf][0], a[mf][1], a[mf][2], a[mf][3],
                      smem_u32(&As[mw + mf*16 + (lane&15)][k0 + (lane>>4)*8]));
            #pragma unroll
            for (int nb = 0; nb < 2; nb++)
                ldsm4(bf[nb*2][0], bf[nb*2][1], bf[nb*2+1][0], bf[nb*2+1][1],
                      smem_u32(&Bs[nw + nb*16 + (lane>>4)*8 + (lane&7)][k0 + ((lane>>3)&1)*8]));
            #pragma unroll
            for (int mf = 0; mf < 2; mf++)
                #pragma unroll
                for (int nf = 0; nf < 4; nf++)
                    mma_bf16(acc[mf][nf], a[mf][0], a[mf][1], a[mf][2], a[mf][3],
                             bf[nf][0], bf[nf][1]);
        }
        __syncthreads();
    }
    float* Sb = g_S + (size_t)b * 65536;
    #pragma unroll
    for (int mf = 0; mf < 2; mf++) {
        int i1 = i0 + mw + mf * 16 + g, i2 = i1 + 8;
        #pragma unroll
        for (int nf = 0; nf < 4; nf++) {
            int jc = j0 + nw + nf * 8 + tg * 2;
            *(float2*)&Sb[(size_t)i1 * 256 + jc] = make_float2(acc[mf][nf][0], acc[mf][nf][1]);
            *(float2*)&Sb[(size_t)i2 * 256 + jc] = make_float2(acc[mf][nf][2], acc[mf][nf][3]);
        }
    }
}

// ---------------------------------------------------------------------------
// apply channel: out = xin + beta * (P[256x256] @ g[256x9216]).
// Tile 128x128, BK=64, 8 warps (2x4), warp 64x32. A = P (cvt), B = g [k][n] trans.
// ---------------------------------------------------------------------------
__global__ __launch_bounds__(256) void apply_channel_bf16_kernel(
    const float* __restrict__ xin, float* __restrict__ xout, const float* __restrict__ beta_p)
{
    __shared__ __align__(16) __nv_bfloat16 As[128][72];
    __shared__ __align__(16) __nv_bfloat16 Bs[64][136];

    int b = blockIdx.z, m0 = blockIdx.y * 128, n0 = blockIdx.x * 128;
    int tid = threadIdx.x, wid = tid >> 5, lane = tid & 31;
    int mw = (wid >> 2) * 64, nw = (wid & 3) * 32;
    int g = lane >> 2, tg = lane & 3;

    const float* Pb = g_S + (size_t)b * 65536;
    float acc[4][4][4] = {};
    int am = tid >> 1, akh = (tid & 1) * 32;
    int bk = tid >> 2, bns = (tid & 3) * 32;

    for (int kk = 0; kk < 256; kk += 64) {
        {
            const float4* src = (const float4*)(Pb + (size_t)(m0 + am) * 256 + kk + akh);
            uint4* dst = (uint4*)&As[am][akh];
            #pragma unroll
            for (int j = 0; j < 4; j++) {
                float4 f0 = src[2*j], f1 = src[2*j+1];
                uint4 v;
                v.x = packbf(f0.x, f0.y); v.y = packbf(f0.z, f0.w);
                v.z = packbf(f1.x, f1.y); v.w = packbf(f1.z, f1.w);
                dst[j] = v;
            }
        }
        {
            const uint4* src = (const uint4*)(g_gb + ((size_t)b * CC + kk + bk) * HWSZ + n0 + bns);
            uint4* dst = (uint4*)&Bs[bk][bns];
            dst[0]=src[0]; dst[1]=src[1]; dst[2]=src[2]; dst[3]=src[3];
        }
        __syncthreads();
        #pragma unroll
        for (int ks = 0; ks < 4; ks++) {
            int k0 = ks * 16;
            uint32_t a[4][4], bf[4][2];
            #pragma unroll
            for (int mf = 0; mf < 4; mf++)
                ldsm4(a[mf][0], a[mf][1], a[mf][2], a[mf][3],
                      smem_u32(&As[mw + mf*16 + (lane&15)][k0 + (lane>>4)*8]));
            #pragma unroll
            for (int nb = 0; nb < 2; nb++)
                ldsm4t(bf[nb*2][0], bf[nb*2][1], bf[nb*2+1][0], bf[nb*2+1][1],
                       smem_u32(&Bs[k0 + (lane&15)][nw + nb*16 + (lane>>4)*8]));
            #pragma unroll
            for (int mf = 0; mf < 4; mf++)
                #pragma unroll
                for (int nf = 0; nf < 4; nf++)
                    mma_bf16(acc[mf][nf], a[mf][0], a[mf][1], a[mf][2], a[mf][3],
                             bf[nf][0], bf[nf][1]);
        }
        __syncthreads();
    }
    float beta = *beta_p;
    #pragma unroll
    for (int mf = 0; mf < 4; mf++) {
        int r1 = m0 + mw + mf * 16 + g, r2 = r1 + 8;
        size_t base1 = ((size_t)b * CC + r1) * HWSZ + n0;
        size_t base2 = ((size_t)b * CC + r2) * HWSZ + n0;
        #pragma unroll
        for (int nf = 0; nf < 4; nf++) {
            int col = nw + nf * 8 + tg * 2;
            float2 xa = *(const float2*)&xin[base1 + col];
            float2 xb2 = *(const float2*)&xin[base2 + col];
            *(float2*)&xout[base1 + col] =
                make_float2(xa.x + beta*acc[mf][nf][0], xa.y + beta*acc[mf][nf][1]);
            *(float2*)&xout[base2 + col] =
                make_float2(xb2.x + beta*acc[mf][nf][2], xb2.y + beta*acc[mf][nf][3]);
        }
    }
}

// ---------------------------------------------------------------------------
extern "C" void kernel_launch(void* const* d_in, const int* in_sizes, int n_in,
                              void* d_out, int out_size)
{
    const float* x      = (const float*)d_in[0];
    const float* wt     = (const float*)d_in[1];
    const float* bt     = (const float*)d_in[2];
    const float* wp     = (const float*)d_in[3];
    const float* bp     = (const float*)d_in[4];
    const float* wg     = (const float*)d_in[5];
    const float* bg     = (const float*)d_in[6];
    const float* beta_w = (const float*)d_in[7];
    const float* beta_h = (const float*)d_in[8];
    const float* beta_c = (const float*)d_in[9];
    float* out = (float*)d_out;

    float *x1, *x2, *S;
    cudaGetSymbolAddress((void**)&x1, g_x1);
    cudaGetSymbolAddress((void**)&x2, g_x2);
    cudaGetSymbolAddress((void**)&S,  g_S);

    wconv_kernel<<<768, 256>>>(wt, wp, wg);

    dim3 convg(72, 6, 16);

    // ---- round 1: width attention ----
    conv3_bf16_kernel<<<convg, 256>>>(x, bt, bp, bg);
    cudaMemsetAsync(S, 0, (size_t)16 * 9216 * sizeof(float), 0);
    slice_logits_bf16_kernel<0><<<dim3(16, 16), 256>>>();
    softmax_kernel<<<16 * 96, 256>>>(96);
    apply_slice_w_kernel<<<dim3(192, 16), 256>>>(x, x1, beta_w);

    // ---- round 2: height attention ----
    conv3_bf16_kernel<<<convg, 256>>>(x1, bt, bp, bg);
    cudaMemsetAsync(S, 0, (size_t)16 * 9216 * sizeof(float), 0);
    slice_logits_bf16_kernel<1><<<dim3(16, 16), 256>>>();
    softmax_kernel<<<16 * 96, 256>>>(96);
    apply_slice_h_kernel<<<dim3(256, 16), 256>>>(x1, x2, beta_h);

    // ---- round 3: channel attention ----
    conv3_bf16_kernel<<<convg, 256>>>(x2, bt, bp, bg);
    chan_logits_bf16_kernel<<<dim3(4, 4, 16), 128>>>();
    softmax_kernel<<<16 * 256, 256>>>(256);
    apply_channel_bf16_kernel<<<dim3(72, 2, 16), 256>>>(x2, out, beta_c);
}

// round 4
// speedup vs baseline: 4.3137x; 1.3785x over previous
#include <cuda_runtime.h>
#include <cuda_bf16.h>
#include <math.h>
#include <stdint.h>

#define BB 16
#define CC 256
#define HH 96
#define WW 96
#define HWSZ (HH*WW)           // 9216
#define NELEM (BB*CC*HWSZ)     // 37,748,736

// Scratch (device globals: allocation-free rule)
__device__ __nv_bfloat16 g_thb[NELEM];
__device__ __nv_bfloat16 g_phb[NELEM];
__device__ __nv_bfloat16 g_gb[NELEM];
__device__ __nv_bfloat16 g_xb[NELEM];        // bf16 mirror of current x
__device__ float g_x1[NELEM];
__device__ float g_x2[NELEM];
__device__ float g_S[BB*CC*CC];              // logits fp32
__device__ __nv_bfloat16 g_Pb[BB*CC*CC];     // probabilities bf16
__device__ __nv_bfloat16 g_Wbf[3*CC*CC];     // [theta; phi; g] weights bf16 (768x256)

// ---------------------------------------------------------------------------
// helpers
// ---------------------------------------------------------------------------
__device__ __forceinline__ uint32_t smem_u32(const void* p) {
    return (uint32_t)__cvta_generic_to_shared(p);
}
__device__ __forceinline__ uint32_t packbf(float lo, float hi) {
    __nv_bfloat162 h = __floats2bfloat162_rn(lo, hi);
    return *(uint32_t*)&h;
}
__device__ __forceinline__ void cpa16(uint32_t dst, const void* src) {
    asm volatile("cp.async.cg.shared.global [%0], [%1], 16;" :: "r"(dst), "l"(src));
}
#define CP_COMMIT() asm volatile("cp.async.commit_group;")
template<int N> __device__ __forceinline__ void cp_wait() {
    asm volatile("cp.async.wait_group %0;" :: "n"(N));
}
__device__ __forceinline__ void ldsm4(uint32_t& r0, uint32_t& r1, uint32_t& r2, uint32_t& r3, uint32_t a) {
    asm volatile("ldmatrix.sync.aligned.m8n8.x4.shared.b16 {%0,%1,%2,%3},[%4];"
                 : "=r"(r0), "=r"(r1), "=r"(r2), "=r"(r3) : "r"(a));
}
__device__ __forceinline__ void ldsm4t(uint32_t& r0, uint32_t& r1, uint32_t& r2, uint32_t& r3, uint32_t a) {
    asm volatile("ldmatrix.sync.aligned.m8n8.x4.trans.shared.b16 {%0,%1,%2,%3},[%4];"
                 : "=r"(r0), "=r"(r1), "=r"(r2), "=r"(r3) : "r"(a));
}
__device__ __forceinline__ void ldsm2(uint32_t& r0, uint32_t& r1, uint32_t a) {
    asm volatile("ldmatrix.sync.aligned.m8n8.x2.shared.b16 {%0,%1},[%2];"
                 : "=r"(r0), "=r"(r1) : "r"(a));
}
__device__ __forceinline__ void ldsm2t(uint32_t& r0, uint32_t& r1, uint32_t a) {
    asm volatile("ldmatrix.sync.aligned.m8n8.x2.trans.shared.b16 {%0,%1},[%2];"
                 : "=r"(r0), "=r"(r1) : "r"(a));
}
__device__ __forceinline__ void mma_bf16(float (&d)[4], uint32_t a0, uint32_t a1, uint32_t a2, uint32_t a3,
                                         uint32_t b0, uint32_t b1) {
    asm volatile(
        "mma.sync.aligned.m16n8k16.row.col.f32.bf16.bf16.f32 "
        "{%0,%1,%2,%3},{%4,%5,%6,%7},{%8,%9},{%0,%1,%2,%3};"
        : "+f"(d[0]), "+f"(d[1]), "+f"(d[2]), "+f"(d[3])
        : "r"(a0), "r"(a1), "r"(a2), "r"(a3), "r"(b0), "r"(b1));
}

// shared 128x128x64 MMA inner step: A [m][k] lda=72 non-trans, B [k][n] ldb=136 trans.
__device__ __forceinline__ void mma_128x128(const __nv_bfloat16* As, const __nv_bfloat16* Bs,
                                            int mw, int nw, int lane, float (&acc)[4][4][4])
{
    #pragma unroll
    for (int ks = 0; ks < 4; ks++) {
        int k0 = ks * 16;
        uint32_t a[4][4], bf[4][2];
        #pragma unroll
        for (int mf = 0; mf < 4; mf++)
            ldsm4(a[mf][0], a[mf][1], a[mf][2], a[mf][3],
                  smem_u32(As + (mw + mf*16 + (lane & 15)) * 72 + k0 + (lane >> 4) * 8));
        #pragma unroll
        for (int nb = 0; nb < 2; nb++)
            ldsm4t(bf[nb*2][0], bf[nb*2][1], bf[nb*2+1][0], bf[nb*2+1][1],
                   smem_u32(Bs + (k0 + (lane & 15)) * 136 + nw + nb*16 + (lane >> 4) * 8));
        #pragma unroll
        for (int mf = 0; mf < 4; mf++)
            #pragma unroll
            for (int nf = 0; nf < 4; nf++)
                mma_bf16(acc[mf][nf], a[mf][0], a[mf][1], a[mf][2], a[mf][3],
                         bf[nf][0], bf[nf][1]);
    }
}

// ---------------------------------------------------------------------------
// one-time converts
// ---------------------------------------------------------------------------
__global__ void wconv_kernel(const float* __restrict__ wt, const float* __restrict__ wp,
                             const float* __restrict__ wg) {
    int i = blockIdx.x * 256 + threadIdx.x;
    const float* src = (i < 65536) ? wt : (i < 131072 ? wp : wg);
    g_Wbf[i] = __float2bfloat16(src[i & 65535]);
}
__global__ void xconv_kernel(const float* __restrict__ x) {
    size_t base = ((size_t)blockIdx.x * 256 + threadIdx.x) * 8;
    float4 f0 = *(const float4*)(x + base);
    float4 f1 = *(const float4*)(x + base + 4);
    uint4 v;
    v.x = packbf(f0.x, f0.y); v.y = packbf(f0.z, f0.w);
    v.z = packbf(f1.x, f1.y); v.w = packbf(f1.z, f1.w);
    *(uint4*)(g_xb + base) = v;
}

// ---------------------------------------------------------------------------
// conv3: [768x256 Wbf] @ [256x9216 xb]; tile 128x128, BK=64, 8 warps (2x4).
// Double-buffered cp.async. Outputs theta/phi/g bf16.
// ---------------------------------------------------------------------------
__global__ __launch_bounds__(256) void conv3_bf16_kernel(
    const float* __restrict__ bt, const float* __restrict__ bp, const float* __restrict__ bg)
{
    extern __shared__ __align__(16) __nv_bfloat16 dynsm[];
    __nv_bfloat16* Abuf[2] = { dynsm, dynsm + 128*72 };
    __nv_bfloat16* Bbuf[2] = { dynsm + 2*128*72, dynsm + 2*128*72 + 64*136 };

    int b = blockIdx.z, m0 = blockIdx.y * 128, n0 = blockIdx.x * 128;
    int tid = threadIdx.x, wid = tid >> 5, lane = tid & 31;
    int mw = (wid >> 2) * 64, nw = (wid & 3) * 32;
    int g = lane >> 2, tg = lane & 3;

    int arow = tid >> 1, acb = (tid & 1) * 32;
    int brow = tid >> 2, bcb = (tid & 3) * 32;
    const __nv_bfloat16* asrc0 = g_Wbf + (size_t)(m0 + arow) * 256 + acb;
    const __nv_bfloat16* bsrc0 = g_xb + ((size_t)b * CC + brow) * HWSZ + n0 + bcb;

    float acc[4][4][4] = {};

    // prologue: stage 0
    {
        uint32_t ad = smem_u32(Abuf[0] + arow*72 + acb);
        uint32_t bd = smem_u32(Bbuf[0] + brow*136 + bcb);
        #pragma unroll
        for (int j = 0; j < 4; j++) { cpa16(ad + j*16, asrc0 + j*8); cpa16(bd + j*16, bsrc0 + j*8); }
        CP_COMMIT();
    }
    #pragma unroll
    for (int s = 0; s < 4; s++) {
        if (s < 3) {
            int kk = (s + 1) * 64;
            uint32_t ad = smem_u32(Abuf[(s+1)&1] + arow*72 + acb);
            uint32_t bd = smem_u32(Bbuf[(s+1)&1] + brow*136 + bcb);
            #pragma unroll
            for (int j = 0; j < 4; j++) {
                cpa16(ad + j*16, asrc0 + kk + j*8);
                cpa16(bd + j*16, bsrc0 + (size_t)kk * HWSZ + j*8);
            }
            CP_COMMIT();
            cp_wait<1>();
        } else cp_wait<0>();
        __syncthreads();
        mma_128x128(Abuf[s&1], Bbuf[s&1], mw, nw, lane, acc);
        __syncthreads();
    }

    int mat = m0 >> 8, ob = m0 & 255;
    __nv_bfloat16* dst = (mat == 0) ? g_thb : (mat == 1) ? g_phb : g_gb;
    const float* bias = (mat == 0) ? bt : (mat == 1) ? bp : bg;
    #pragma unroll
    for (int mf = 0; mf < 4; mf++) {
        int r = mw + mf * 16 + g;
        int o1 = ob + r, o2 = o1 + 8;
        float b1 = bias[o1], b2 = bias[o2];
        size_t base1 = ((size_t)b * CC + o1) * HWSZ + n0;
        size_t base2 = ((size_t)b * CC + o2) * HWSZ + n0;
        #pragma unroll
        for (int nf = 0; nf < 4; nf++) {
            int col = nw + nf * 8 + tg * 2;
            *(uint32_t*)&dst[base1 + col] = packbf(acc[mf][nf][0] + b1, acc[mf][nf][1] + b1);
            *(uint32_t*)&dst[base2 + col] = packbf(acc[mf][nf][2] + b2, acc[mf][nf][3] + b2);
        }
    }
}

// ---------------------------------------------------------------------------
// slice logits: MODE 0 = width, MODE 1 = height. 16 channels per block,
// double-buffered cp.async across channels. 8 warps (2x4), warp 48x24.
// ---------------------------------------------------------------------------
template<int MODE>
__global__ __launch_bounds__(256) void slice_logits_bf16_kernel()
{
    extern __shared__ __align__(16) __nv_bfloat16 dynsm[];
    __nv_bfloat16* Tb[2] = { dynsm,            dynsm + 2*96*104 };
    __nv_bfloat16* Pb[2] = { dynsm + 96*104,   dynsm + 3*96*104 };

    int b = blockIdx.y, cch = blockIdx.x;
    int tid = threadIdx.x, wid = tid >> 5, lane = tid & 31;
    int mw = (wid >> 2) * 48, nw = (wid & 3) * 24;
    int g = lane >> 2, tg = lane & 3;

    const __nv_bfloat16* tbase = g_thb + ((size_t)b * CC + cch * 16) * HWSZ;
    const __nv_bfloat16* pbase = g_phb + ((size_t)b * CC + cch * 16) * HWSZ;

    float acc[3][3][4] = {};

    // stage loader: channel cc into buffer bi
    auto stage = [&](int cc, int bi) {
        const __nv_bfloat16* ts = tbase + (size_t)cc * HWSZ;
        const __nv_bfloat16* ps = pbase + (size_t)cc * HWSZ;
        #pragma unroll
        for (int j = 0; j < 9; j++) {
            int c = j * 256 + tid;           // 0..2303
            int cc2 = (c < 1152) ? c : c - 1152;
            int row = cc2 / 12, col = (cc2 % 12) * 8;
            if (c < 1152) cpa16(smem_u32(Tb[bi] + row*104 + col), ts + row*96 + col);
            else          cpa16(smem_u32(Pb[bi] + row*104 + col), ps + row*96 + col);
        }
        CP_COMMIT();
    };

    stage(0, 0);
    for (int cc = 0; cc < 16; cc++) {
        if (cc < 15) { stage(cc + 1, (cc + 1) & 1); cp_wait<1>(); }
        else cp_wait<0>();
        __syncthreads();
        const __nv_bfloat16* As = Tb[cc & 1];
        const __nv_bfloat16* Bs = Pb[cc & 1];
        #pragma unroll
        for (int ks = 0; ks < 6; ks++) {
            int k0 = ks * 16;
            uint32_t a[3][4], bf[3][2];
            #pragma unroll
            for (int mf = 0; mf < 3; mf++) {
                if (MODE == 0)
                    ldsm4t(a[mf][0], a[mf][1], a[mf][2], a[mf][3],
                        smem_u32(As + (k0 + ((lane>>4)&1)*8 + (lane&7))*104 + mw + mf*16 + ((lane>>3)&1)*8));
                else
                    ldsm4(a[mf][0], a[mf][1], a[mf][2], a[mf][3],
                        smem_u32(As + (mw + mf*16 + (lane&15))*104 + k0 + (lane>>4)*8));
            }
            if (MODE == 0) {
                ldsm4t(bf[0][0], bf[0][1], bf[1][0], bf[1][1],
                       smem_u32(Bs + (k0 + (lane&15))*104 + nw + (lane>>4)*8));
                ldsm2t(bf[2][0], bf[2][1],
                       smem_u32(Bs + (k0 + (lane&15))*104 + nw + 16));
            } else {
                ldsm4(bf[0][0], bf[0][1], bf[1][0], bf[1][1],
                      smem_u32(Bs + (nw + (lane>>4)*8 + (lane&7))*104 + k0 + ((lane>>3)&1)*8));
                ldsm2(bf[2][0], bf[2][1],
                      smem_u32(Bs + (nw + 16 + (lane&7))*104 + k0 + ((lane>>3)&1)*8));
            }
            #pragma unroll
            for (int mf = 0; mf < 3; mf++)
                #pragma unroll
                for (int nf = 0; nf < 3; nf++)
                    mma_bf16(acc[mf][nf], a[mf][0], a[mf][1], a[mf][2], a[mf][3],
                             bf[nf][0], bf[nf][1]);
        }
        __syncthreads();
    }
    float* Sb = g_S + (size_t)b * 9216;
    #pragma unroll
    for (int mf = 0; mf < 3; mf++) {
        int i1 = mw + mf * 16 + g, i2 = i1 + 8;
        #pragma unroll
        for (int nf = 0; nf < 3; nf++) {
            int jc = nw + nf * 8 + tg * 2;
            atomicAdd(&Sb[i1 * 96 + jc],     acc[mf][nf][0]);
            atomicAdd(&Sb[i1 * 96 + jc + 1], acc[mf][nf][1]);
            atomicAdd(&Sb[i2 * 96 + jc],     acc[mf][nf][2]);
            atomicAdd(&Sb[i2 * 96 + jc + 1], acc[mf][nf][3]);
        }
    }
}

// ---------------------------------------------------------------------------
// softmax: read g_S fp32, write bf16 probabilities to g_Pb. One block per row.
// ---------------------------------------------------------------------------
__global__ __launch_bounds__(256) void softmax_kernel(int n)
{
    size_t base = (size_t)blockIdx.x * n;
    int tid = threadIdx.x;
    __shared__ float red[8];

    float m = -INFINITY;
    for (int j = tid; j < n; j += 256) m = fmaxf(m, g_S[base + j]);
    #pragma unroll
    for (int o = 16; o; o >>= 1) m = fmaxf(m, __shfl_xor_sync(0xffffffffu, m, o));
    if ((tid & 31) == 0) red[tid >> 5] = m;
    __syncthreads();
    float mm = red[0];
    #pragma unroll
    for (int w = 1; w < 8; w++) mm = fmaxf(mm, red[w]);

    float s = 0.f;
    float ev[2];
    int cnt = 0;
    for (int j = tid; j < n; j += 256) {
        float e = __expf(g_S[base + j] - mm);
        ev[cnt++] = e;
        s += e;
    }
    #pragma unroll
    for (int o = 16; o; o >>= 1) s += __shfl_xor_sync(0xffffffffu, s, o);
    if ((tid & 31) == 0) red[tid >> 5] = s;
    __syncthreads();
    float st = 0.f;
    #pragma unroll
    for (int w = 0; w < 8; w++) st += red[w];
    float inv = 1.0f / st;
    cnt = 0;
    for (int j = tid; j < n; j += 256)
        g_Pb[base + j] = __float2bfloat16(ev[cnt++] * inv);
}

// ---------------------------------------------------------------------------
// apply width: D[(c,h), i] = sum_j g[(c,h), j] P[i,j];  out = xin + beta*D.
// Also writes bf16 mirror to g_xb. A=g [m][k] non-trans; B=P [n][k] non-trans.
// ---------------------------------------------------------------------------
__global__ __launch_bounds__(256) void apply_slice_w_kernel(
    const float* __restrict__ xin, float* __restrict__ xout, const float* __restrict__ beta_p)
{
    __shared__ __align__(16) __nv_bfloat16 As[128][104];
    __shared__ __align__(16) __nv_bfloat16 Bs[96][104];

    int b = blockIdx.y, m0 = blockIdx.x * 128;
    int tid = threadIdx.x, wid = tid >> 5, lane = tid & 31;
    int mw = (wid >> 1) * 32, nw = (wid & 1) * 48;
    int g = lane >> 2, tg = lane & 3;

    const __nv_bfloat16* gsrc = g_gb + (size_t)b * CC * HWSZ + (size_t)m0 * 96;
    const __nv_bfloat16* psrc = g_Pb + (size_t)b * 9216;
    #pragma unroll
    for (int j = 0; j < 6; j++) {
        int c = j * 256 + tid;            // 0..1535
        int row = c / 12, col = (c % 12) * 8;
        cpa16(smem_u32(&As[row][col]), gsrc + row*96 + col);
    }
    #pragma unroll
    for (int j = 0; j < 5; j++) {
        int c = j * 256 + tid;
        if (c < 1152) {
            int row = c / 12, col = (c % 12) * 8;
            cpa16(smem_u32(&Bs[row][col]), psrc + row*96 + col);
        }
    }
    CP_COMMIT();
    cp_wait<0>();
    __syncthreads();

    float acc[2][6][4] = {};
    #pragma unroll
    for (int ks = 0; ks < 6; ks++) {
        int k0 = ks * 16;
        uint32_t a[2][4], bf[6][2];
        #pragma unroll
        for (int mf = 0; mf < 2; mf++)
            ldsm4(a[mf][0], a[mf][1], a[mf][2], a[mf][3],
                  smem_u32(&As[mw + mf*16 + (lane&15)][k0 + (lane>>4)*8]));
        #pragma unroll
        for (int nb = 0; nb < 3; nb++)
            ldsm4(bf[nb*2][0], bf[nb*2][1], bf[nb*2+1][0], bf[nb*2+1][1],
                  smem_u32(&Bs[nw + nb*16 + (lane>>4)*8 + (lane&7)][k0 + ((lane>>3)&1)*8]));
        #pragma unroll
        for (int mf = 0; mf < 2; mf++)
            #pragma unroll
            for (int nf = 0; nf < 6; nf++)
                mma_bf16(acc[mf][nf], a[mf][0], a[mf][1], a[mf][2], a[mf][3],
                         bf[nf][0], bf[nf][1]);
    }
    float beta = *beta_p;
    size_t gb = (size_t)b * CC * HWSZ;
    #pragma unroll
    for (int mf = 0; mf < 2; mf++) {
        int r1 = m0 + mw + mf * 16 + g, r2 = r1 + 8;
        #pragma unroll
        for (int nf = 0; nf < 6; nf++) {
            int col = nw + nf * 8 + tg * 2;
            size_t o1 = gb + (size_t)r1 * 96 + col;
            size_t o2 = gb + (size_t)r2 * 96 + col;
            float2 xa = *(const float2*)&xin[o1];
            float2 xb2 = *(const float2*)&xin[o2];
            float v0 = xa.x + beta*acc[mf][nf][0], v1 = xa.y + beta*acc[mf][nf][1];
            float v2 = xb2.x + beta*acc[mf][nf][2], v3 = xb2.y + beta*acc[mf][nf][3];
            *(float2*)&xout[o1] = make_float2(v0, v1);
            *(float2*)&xout[o2] = make_float2(v2, v3);
            *(uint32_t*)&g_xb[o1] = packbf(v0, v1);
            *(uint32_t*)&g_xb[o2] = packbf(v2, v3);
        }
    }
}

// ---------------------------------------------------------------------------
// apply height: per (b,c): D[h, w] = sum_j P[h,j] g[c,j,w]; out = xin + beta*D.
// Also writes bf16 mirror. A=P [m][k] non-trans; B=g [k][n] trans.
// ---------------------------------------------------------------------------
__global__ __launch_bounds__(256) void apply_slice_h_kernel(
    const float* __restrict__ xin, float* __restrict__ xout, const float* __restrict__ beta_p)
{
    __shared__ __align__(16) __nv_bfloat16 As[96][104];
    __shared__ __align__(16) __nv_bfloat16 Bs[96][104];

    int b = blockIdx.y, c = blockIdx.x;
    int tid = threadIdx.x, wid = tid >> 5, lane = tid & 31;
    int mw = (wid >> 2) * 48, nw = (wid & 3) * 24;
    int g = lane >> 2, tg = lane & 3;

    const __nv_bfloat16* psrc = g_Pb + (size_t)b * 9216;
    const __nv_bfloat16* gsrc = g_gb + ((size_t)b * CC + c) * HWSZ;
    #pragma unroll
    for (int j = 0; j < 9; j++) {
        int cidx = j * 256 + tid;         // 0..2303
        int c2 = (cidx < 1152) ? cidx : cidx - 1152;
        int row = c2 / 12, col = (c2 % 12) * 8;
        if (cidx < 1152) cpa16(smem_u32(&As[row][col]), psrc + row*96 + col);
        else             cpa16(smem_u32(&Bs[row][col]), gsrc + row*96 + col);
    }
    CP_COMMIT();
    cp_wait<0>();
    __syncthreads();

    float acc[3][3][4] = {};
    #pragma unroll
    for (int ks = 0; ks < 6; ks++) {
        int k0 = ks * 16;
        uint32_t a[3][4], bf[3][2];
        #pragma unroll
        for (int mf = 0; mf < 3; mf++)
            ldsm4(a[mf][0], a[mf][1], a[mf][2], a[mf][3],
                  smem_u32(&As[mw + mf*16 + (lane&15)][k0 + (lane>>4)*8]));
        ldsm4t(bf[0][0], bf[0][1], bf[1][0], bf[1][1],
               smem_u32(&Bs[k0 + (lane&15)][nw + (lane>>4)*8]));
        ldsm2t(bf[2][0], bf[2][1],
               smem_u32(&Bs[k0 + (lane&15)][nw + 16]));
        #pragma unroll
        for (int mf = 0; mf < 3; mf++)
            #pragma unroll
            for (int nf = 0; nf < 3; nf++)
                mma_bf16(acc[mf][nf], a[mf][0], a[mf][1], a[mf][2], a[mf][3],
                         bf[nf][0], bf[nf][1]);
    }
    float beta = *beta_p;
    size_t base = ((size_t)b * CC + c) * HWSZ;
    #pragma unroll
    for (int mf = 0; mf < 3; mf++) {
        int i1 = mw + mf * 16 + g, i2 = i1 + 8;
        #pragma unroll
        for (int nf = 0; nf < 3; nf++) {
            int col = nw + nf * 8 + tg * 2;
            size_t o1 = base + (size_t)i1 * 96 + col;
            size_t o2 = base + (size_t)i2 * 96 + col;
            float2 xa = *(const float2*)&xin[o1];
            float2 xb2 = *(const float2*)&xin[o2];
            float v0 = xa.x + beta*acc[mf][nf][0], v1 = xa.y + beta*acc[mf][nf][1];
            float v2 = xb2.x + beta*acc[mf][nf][2], v3 = xb2.y + beta*acc[mf][nf][3];
            *(float2*)&xout[o1] = make_float2(v0, v1);
            *(float2*)&xout[o2] = make_float2(v2, v3);
            *(uint32_t*)&g_xb[o1] = packbf(v0, v1);
            *(uint32_t*)&g_xb[o2] = packbf(v2, v3);
        }
    }
}

// ---------------------------------------------------------------------------
// channel logits: S[i,j] = theta[i,:].phi[j,:], K=9216. Tile 64x64, BK=64,
// double-buffered cp.async. 4 warps (2x2), warp 32x32.
// ---------------------------------------------------------------------------
__global__ __launch_bounds__(128) void chan_logits_bf16_kernel()
{
    __shared__ __align__(16) __nv_bfloat16 As[2][64][72];
    __shared__ __align__(16) __nv_bfloat16 Bs[2][64][72];

    int b = blockIdx.z, i0 = blockIdx.y * 64, j0 = blockIdx.x * 64;
    int tid = threadIdx.x, wid = tid >> 5, lane = tid & 31;
    int mw = (wid >> 1) * 32, nw = (wid & 1) * 32;
    int g = lane >> 2, tg = lane & 3;

    int r = tid >> 1, cb = (tid & 1) * 32;
    const __nv_bfloat16* ts0 = g_thb + ((size_t)b * CC + i0 + r) * HWSZ + cb;
    const __nv_bfloat16* ps0 = g_phb + ((size_t)b * CC + j0 + r) * HWSZ + cb;

    float acc[2][4][4] = {};

    auto stage = [&](int kk, int bi) {
        uint32_t ad = smem_u32(&As[bi][r][cb]);
        uint32_t bd = smem_u32(&Bs[bi][r][cb]);
        #pragma unroll
        for (int j = 0; j < 4; j++) {
            cpa16(ad + j*16, ts0 + kk + j*8);
            cpa16(bd + j*16, ps0 + kk + j*8);
        }
        CP_COMMIT();
    };

    stage(0, 0);
    for (int s = 0; s < 144; s++) {
        if (s < 143) { stage((s + 1) * 64, (s + 1) & 1); cp_wait<1>(); }
        else cp_wait<0>();
        __syncthreads();
        const __nv_bfloat16* Ab = &As[s&1][0][0];
        const __nv_bfloat16* Bb = &Bs[s&1][0][0];
        #pragma unroll
        for (int ks = 0; ks < 4; ks++) {
            int k0 = ks * 16;
            uint32_t a[2][4], bf[4][2];
            #pragma unroll
            for (int mf = 0; mf < 2; mf++)
                ldsm4(a[mf][0], a[mf][1], a[mf][2], a[mf][3],
                      smem_u32(Ab + (mw + mf*16 + (lane&15))*72 + k0 + (lane>>4)*8));
            #pragma unroll
            for (int nb = 0; nb < 2; nb++)
                ldsm4(bf[nb*2][0], bf[nb*2][1], bf[nb*2+1][0], bf[nb*2+1][1],
                      smem_u32(Bb + (nw + nb*16 + (lane>>4)*8 + (lane&7))*72 + k0 + ((lane>>3)&1)*8));
            #pragma unroll
            for (int mf = 0; mf < 2; mf++)
                #pragma unroll
                for (int nf = 0; nf < 4; nf++)
                    mma_bf16(acc[mf][nf], a[mf][0], a[mf][1], a[mf][2], a[mf][3],
                             bf[nf][0], bf[nf][1]);
        }
        __syncthreads();
    }
    float* Sb = g_S + (size_t)b * 65536;
    #pragma unroll
    for (int mf = 0; mf < 2; mf++) {
        int i1 = i0 + mw + mf * 16 + g, i2 = i1 + 8;
        #pragma unroll
        for (int nf = 0; nf < 4; nf++) {
            int jc = j0 + nw + nf * 8 + tg * 2;
            *(float2*)&Sb[(size_t)i1 * 256 + jc] = make_float2(acc[mf][nf][0], acc[mf][nf][1]);
            *(float2*)&Sb[(size_t)i2 * 256 + jc] = make_float2(acc[mf][nf][2], acc[mf][nf][3]);
        }
    }
}

// ---------------------------------------------------------------------------
// apply channel: out = xin + beta * (P[256x256] @ g[256x9216]).
// Tile 128x128, BK=64, double-buffered cp.async, 8 warps (2x4).
// ---------------------------------------------------------------------------
__global__ __launch_bounds__(256) void apply_channel_bf16_kernel(
    const float* __restrict__ xin, float* __restrict__ xout, const float* __restrict__ beta_p)
{
    extern __shared__ __align__(16) __nv_bfloat16 dynsm[];
    __nv_bfloat16* Abuf[2] = { dynsm, dynsm + 128*72 };
    __nv_bfloat16* Bbuf[2] = { dynsm + 2*128*72, dynsm + 2*128*72 + 64*136 };

    int b = blockIdx.z, m0 = blockIdx.y * 128, n0 = blockIdx.x * 128;
    int tid = threadIdx.x, wid = tid >> 5, lane = tid & 31;
    int mw = (wid >> 2) * 64, nw = (wid & 3) * 32;
    int g = lane >> 2, tg = lane & 3;

    int arow = tid >> 1, acb = (tid & 1) * 32;
    int brow = tid >> 2, bcb = (tid & 3) * 32;
    const __nv_bfloat16* asrc0 = g_Pb + (size_t)b * 65536 + (size_t)(m0 + arow) * 256 + acb;
    const __nv_bfloat16* bsrc0 = g_gb + ((size_t)b * CC + brow) * HWSZ + n0 + bcb;

    float acc[4][4][4] = {};

    {
        uint32_t ad = smem_u32(Abuf[0] + arow*72 + acb);
        uint32_t bd = smem_u32(Bbuf[0] + brow*136 + bcb);
        #pragma unroll
        for (int j = 0; j < 4; j++) { cpa16(ad + j*16, asrc0 + j*8); cpa16(bd + j*16, bsrc0 + j*8); }
        CP_COMMIT();
    }
    #pragma unroll
    for (int s = 0; s < 4; s++) {
        if (s < 3) {
            int kk = (s + 1) * 64;
            uint32_t ad = smem_u32(Abuf[(s+1)&1] + arow*72 + acb);
            uint32_t bd = smem_u32(Bbuf[(s+1)&1] + brow*136 + bcb);
            #pragma unroll
            for (int j = 0; j < 4; j++) {
                cpa16(ad + j*16, asrc0 + kk + j*8);
                cpa16(bd + j*16, bsrc0 + (size_t)kk * HWSZ + j*8);
            }
            CP_COMMIT();
            cp_wait<1>();
        } else cp_wait<0>();
        __syncthreads();
        mma_128x128(Abuf[s&1], Bbuf[s&1], mw, nw, lane, acc);
        __syncthreads();
    }

    float beta = *beta_p;
    #pragma unroll
    for (int mf = 0; mf < 4; mf++) {
        int r1 = m0 + mw + mf * 16 + g, r2 = r1 + 8;
        size_t base1 = ((size_t)b * CC + r1) * HWSZ + n0;
        size_t base2 = ((size_t)b * CC + r2) * HWSZ + n0;
        #pragma unroll
        for (int nf = 0; nf < 4; nf++) {
            int col = nw + nf * 8 + tg * 2;
            float2 xa = *(const float2*)&xin[base1 + col];
            float2 xb2 = *(const float2*)&xin[base2 + col];
            *(float2*)&xout[base1 + col] =
                make_float2(xa.x + beta*acc[mf][nf][0], xa.y + beta*acc[mf][nf][1]);
            *(float2*)&xout[base2 + col] =
                make_float2(xb2.x + beta*acc[mf][nf][2], xb2.y + beta*acc[mf][nf][3]);
        }
    }
}

// ---------------------------------------------------------------------------
extern "C" void kernel_launch(void* const* d_in, const int* in_sizes, int n_in,
                              void* d_out, int out_size)
{
    const float* x      = (const float*)d_in[0];
    const float* wt     = (const float*)d_in[1];
    const float* bt     = (const float*)d_in[2];
    const float* wp     = (const float*)d_in[3];
    const float* bp     = (const float*)d_in[4];
    const float* wg     = (const float*)d_in[5];
    const float* bg     = (const float*)d_in[6];
    const float* beta_w = (const float*)d_in[7];
    const float* beta_h = (const float*)d_in[8];
    const float* beta_c = (const float*)d_in[9];
    float* out = (float*)d_out;

    float *x1, *x2, *S;
    cudaGetSymbolAddress((void**)&x1, g_x1);
    cudaGetSymbolAddress((void**)&x2, g_x2);
    cudaGetSymbolAddress((void**)&S,  g_S);

    int gemm_smem  = (2*128*72 + 2*64*136) * 2;   // 71680 B
    int slice_smem = 4 * 96 * 104 * 2;            // 79872 B
    cudaFuncSetAttribute(conv3_bf16_kernel,
                         cudaFuncAttributeMaxDynamicSharedMemorySize, gemm_smem);
    cudaFuncSetAttribute(apply_channel_bf16_kernel,
                         cudaFuncAttributeMaxDynamicSharedMemorySize, gemm_smem);
    cudaFuncSetAttribute(slice_logits_bf16_kernel<0>,
                         cudaFuncAttributeMaxDynamicSharedMemorySize, slice_smem);
    cudaFuncSetAttribute(slice_logits_bf16_kernel<1>,
                         cudaFuncAttributeMaxDynamicSharedMemorySize, slice_smem);

    xconv_kernel<<<NELEM / (256 * 8), 256>>>(x);
    wconv_kernel<<<768, 256>>>(wt, wp, wg);

    dim3 convg(72, 6, 16);

    // ---- round 1: width attention ----
    conv3_bf16_kernel<<<convg, 256, gemm_smem>>>(bt, bp, bg);
    cudaMemsetAsync(S, 0, (size_t)16 * 9216 * sizeof(float), 0);
    slice_logits_bf16_kernel<0><<<dim3(16, 16), 256, slice_smem>>>();
    softmax_kernel<<<16 * 96, 256>>>(96);
    apply_slice_w_kernel<<<dim3(192, 16), 256>>>(x, x1, beta_w);

    // ---- round 2: height attention ----
    conv3_bf16_kernel<<<convg, 256, gemm_smem>>>(bt, bp, bg);
    cudaMemsetAsync(S, 0, (size_t)16 * 9216 * sizeof(float), 0);
    slice_logits_bf16_kernel<1><<<dim3(16, 16), 256, slice_smem>>>();
    softmax_kernel<<<16 * 96, 256>>>(96);
    apply_slice_h_kernel<<<dim3(256, 16), 256>>>(x1, x2, beta_h);

    // ---- round 3: channel attention ----
    conv3_bf16_kernel<<<convg, 256, gemm_smem>>>(bt, bp, bg);
    chan_logits_bf16_kernel<<<dim3(4, 4, 16), 128>>>();
    softmax_kernel<<<16 * 256, 256>>>(256);
    apply_channel_bf16_kernel<<<dim3(72, 2, 16), 256, gemm_smem>>>(x2, out, beta_c);
}

// round 5
// speedup vs baseline: 4.6822x; 1.0854x over previous
#include <cuda_runtime.h>
#include <cuda_bf16.h>
#include <math.h>
#include <stdint.h>

#define BB 16
#define CC 256
#define HH 96
#define WW 96
#define HWSZ (HH*WW)           // 9216
#define NELEM (BB*CC*HWSZ)     // 37,748,736

// Scratch (device globals: allocation-free rule)
__device__ __nv_bfloat16 g_thb[NELEM];       // y = M x (rounds 1-2)
__device__ __nv_bfloat16 g_gb[NELEM];        // g = Wg x + bg
__device__ __nv_bfloat16 g_xb[NELEM];        // bf16 mirror of current x
__device__ float g_x1[NELEM];
__device__ float g_x2[NELEM];
__device__ float g_S[BB*CC*CC];              // logits fp32
__device__ __nv_bfloat16 g_Pb[BB*CC*CC];     // probabilities bf16
__device__ __nv_bfloat16 g_Wbf[3*CC*CC];     // [Wt; Wp; Wg] bf16
__device__ __nv_bfloat16 g_W2[2*CC*CC];      // [M = Wt^T Wp ; Wg] bf16 (512x256)
__device__ float g_G[BB*CC*CC];              // Gram X X^T fp32
__device__ float g_T1[BB*CC*CC];             // Wt @ G fp32
__device__ float g_xs[BB*CC*96];             // per-axis sums of x
__device__ float g_xs2[BB*CC];               // full-hw sums of x
__device__ float g_u[BB*96];
__device__ float g_v[BB*96];
__device__ float g_w1[CC];
__device__ float g_w2[CC];
__device__ float g_c0[1];
__device__ float g_sA[BB*CC];
__device__ float g_sB2[BB*CC];

// ---------------------------------------------------------------------------
// helpers
// ---------------------------------------------------------------------------
__device__ __forceinline__ uint32_t smem_u32(const void* p) {
    return (uint32_t)__cvta_generic_to_shared(p);
}
__device__ __forceinline__ uint32_t packbf(float lo, float hi) {
    __nv_bfloat162 h = __floats2bfloat162_rn(lo, hi);
    return *(uint32_t*)&h;
}
__device__ __forceinline__ void cpa16(uint32_t dst, const void* src) {
    asm volatile("cp.async.cg.shared.global [%0], [%1], 16;" :: "r"(dst), "l"(src));
}
#define CP_COMMIT() asm volatile("cp.async.commit_group;")
template<int N> __device__ __forceinline__ void cp_wait() {
    asm volatile("cp.async.wait_group %0;" :: "n"(N));
}
__device__ __forceinline__ void ldsm4(uint32_t& r0, uint32_t& r1, uint32_t& r2, uint32_t& r3, uint32_t a) {
    asm volatile("ldmatrix.sync.aligned.m8n8.x4.shared.b16 {%0,%1,%2,%3},[%4];"
                 : "=r"(r0), "=r"(r1), "=r"(r2), "=r"(r3) : "r"(a));
}
__device__ __forceinline__ void ldsm4t(uint32_t& r0, uint32_t& r1, uint32_t& r2, uint32_t& r3, uint32_t a) {
    asm volatile("ldmatrix.sync.aligned.m8n8.x4.trans.shared.b16 {%0,%1,%2,%3},[%4];"
                 : "=r"(r0), "=r"(r1), "=r"(r2), "=r"(r3) : "r"(a));
}
__device__ __forceinline__ void ldsm2(uint32_t& r0, uint32_t& r1, uint32_t a) {
    asm volatile("ldmatrix.sync.aligned.m8n8.x2.shared.b16 {%0,%1},[%2];"
                 : "=r"(r0), "=r"(r1) : "r"(a));
}
__device__ __forceinline__ void ldsm2t(uint32_t& r0, uint32_t& r1, uint32_t a) {
    asm volatile("ldmatrix.sync.aligned.m8n8.x2.trans.shared.b16 {%0,%1},[%2];"
                 : "=r"(r0), "=r"(r1) : "r"(a));
}
__device__ __forceinline__ void mma_bf16(float (&d)[4], uint32_t a0, uint32_t a1, uint32_t a2, uint32_t a3,
                                         uint32_t b0, uint32_t b1) {
    asm volatile(
        "mma.sync.aligned.m16n8k16.row.col.f32.bf16.bf16.f32 "
        "{%0,%1,%2,%3},{%4,%5,%6,%7},{%8,%9},{%0,%1,%2,%3};"
        : "+f"(d[0]), "+f"(d[1]), "+f"(d[2]), "+f"(d[3])
        : "r"(a0), "r"(a1), "r"(a2), "r"(a3), "r"(b0), "r"(b1));
}

// shared 128x128x64 MMA inner step: A [m][k] lda=72 non-trans, B [k][n] ldb=136 trans.
__device__ __forceinline__ void mma_128x128(const __nv_bfloat16* As, const __nv_bfloat16* Bs,
                                            int mw, int nw, int lane, float (&acc)[4][4][4])
{
    #pragma unroll
    for (int ks = 0; ks < 4; ks++) {
        int k0 = ks * 16;
        uint32_t a[4][4], bf[4][2];
        #pragma unroll
        for (int mf = 0; mf < 4; mf++)
            ldsm4(a[mf][0], a[mf][1], a[mf][2], a[mf][3],
                  smem_u32(As + (mw + mf*16 + (lane & 15)) * 72 + k0 + (lane >> 4) * 8));
        #pragma unroll
        for (int nb = 0; nb < 2; nb++)
            ldsm4t(bf[nb*2][0], bf[nb*2][1], bf[nb*2+1][0], bf[nb*2+1][1],
                   smem_u32(Bs + (k0 + (lane & 15)) * 136 + nw + nb*16 + (lane >> 4) * 8));
        #pragma unroll
        for (int mf = 0; mf < 4; mf++)
            #pragma unroll
            for (int nf = 0; nf < 4; nf++)
                mma_bf16(acc[mf][nf], a[mf][0], a[mf][1], a[mf][2], a[mf][3],
                         bf[nf][0], bf[nf][1]);
    }
}

// ---------------------------------------------------------------------------
// one-time converts / precomputes
// ---------------------------------------------------------------------------
__global__ void wconv_kernel(const float* __restrict__ wt, const float* __restrict__ wp,
                             const float* __restrict__ wg) {
    int i = blockIdx.x * 256 + threadIdx.x;
    const float* src = (i < 65536) ? wt : (i < 131072 ? wp : wg);
    __nv_bfloat16 v = __float2bfloat16(src[i & 65535]);
    g_Wbf[i] = v;
    if (i >= 131072) g_W2[65536 + (i - 131072)] = v;   // Wg half of W2
}
__global__ void xconv_kernel(const float* __restrict__ x) {
    size_t base = ((size_t)blockIdx.x * 256 + threadIdx.x) * 8;
    float4 f0 = *(const float4*)(x + base);
    float4 f1 = *(const float4*)(x + base + 4);
    uint4 v;
    v.x = packbf(f0.x, f0.y); v.y = packbf(f0.z, f0.w);
    v.z = packbf(f1.x, f1.y); v.w = packbf(f1.z, f1.w);
    *(uint4*)(g_xb + base) = v;
}

// M = Wt^T Wp (256x256) -> g_W2 rows 0-255. Tile 64x64, K=256, 4 warps (2x2).
__global__ __launch_bounds__(128) void mprep_kernel()
{
    __shared__ __align__(16) __nv_bfloat16 As[64][72];   // [c][m]
    __shared__ __align__(16) __nv_bfloat16 Bs[64][72];   // [c][n]

    int m0 = blockIdx.y * 64, n0 = blockIdx.x * 64;
    int tid = threadIdx.x, wid = tid >> 5, lane = tid & 31;
    int mw = (wid >> 1) * 32, nw = (wid & 1) * 32;
    int g = lane >> 2, tg = lane & 3;

    float acc[2][4][4] = {};
    int cr = tid >> 1, mc = (tid & 1) * 32;

    for (int kk = 0; kk < 256; kk += 64) {
        uint32_t ad = smem_u32(&As[cr][mc]);
        uint32_t bd = smem_u32(&Bs[cr][mc]);
        const __nv_bfloat16* asrc = g_Wbf + (size_t)(kk + cr) * 256 + m0 + mc;
        const __nv_bfloat16* bsrc = g_Wbf + 65536 + (size_t)(kk + cr) * 256 + n0 + mc;
        #pragma unroll
        for (int j = 0; j < 4; j++) { cpa16(ad + j*16, asrc + j*8); cpa16(bd + j*16, bsrc + j*8); }
        CP_COMMIT();
        cp_wait<0>();
        __syncthreads();
        #pragma unroll
        for (int ks = 0; ks < 4; ks++) {
            int k0 = ks * 16;
            uint32_t a[2][4], bf[4][2];
            #pragma unroll
            for (int mf = 0; mf < 2; mf++)
                ldsm4t(a[mf][0], a[mf][1], a[mf][2], a[mf][3],
                    smem_u32(&As[k0 + ((lane>>4)&1)*8 + (lane&7)][mw + mf*16 + ((lane>>3)&1)*8]));
            ldsm4t(bf[0][0], bf[0][1], bf[1][0], bf[1][1],
                   smem_u32(&Bs[k0 + (lane&15)][nw + (lane>>4)*8]));
            ldsm4t(bf[2][0], bf[2][1], bf[3][0], bf[3][1],
                   smem_u32(&Bs[k0 + (lane&15)][nw + 16 + (lane>>4)*8]));
            #pragma unroll
            for (int mf = 0; mf < 2; mf++)
                #pragma unroll
                for (int nf = 0; nf < 4; nf++)
                    mma_bf16(acc[mf][nf], a[mf][0], a[mf][1], a[mf][2], a[mf][3],
                             bf[nf][0], bf[nf][1]);
        }
        __syncthreads();
    }
    #pragma unroll
    for (int mf = 0; mf < 2; mf++) {
        int r1 = m0 + mw + mf*16 + g, r2 = r1 + 8;
        #pragma unroll
        for (int nf = 0; nf < 4; nf++) {
            int col = n0 + nw + nf*8 + tg*2;
            *(uint32_t*)&g_W2[r1*256 + col] = packbf(acc[mf][nf][0], acc[mf][nf][1]);
            *(uint32_t*)&g_W2[r2*256 + col] = packbf(acc[mf][nf][2], acc[mf][nf][3]);
        }
    }
}

// bias fold vectors: w1[k]=sum_o wt[o,k]bp[o]; w2[k]=sum_o wp[o,k]bt[o]; c0=96*(bt.bp)
__global__ void biasvec_kernel(const float* __restrict__ wt, const float* __restrict__ wp,
                               const float* __restrict__ bt, const float* __restrict__ bp)
{
    int k = threadIdx.x;
    float s1 = 0.f, s2 = 0.f;
    for (int o = 0; o < 256; o++) {
        s1 += wt[o*256 + k] * bp[o];
        s2 += wp[o*256 + k] * bt[o];
    }
    g_w1[k] = s1; g_w2[k] = s2;
    if (k == 0) {
        float c = 0.f;
        for (int o = 0; o < 256; o++) c += bt[o] * bp[o];
        g_c0[0] = 96.f * c;
    }
}

// ---------------------------------------------------------------------------
// conv: [Mrows x 256 W] @ [256 x 9216 xb]; tile 128x128, BK=64, 8 warps.
// dst selected by m0>>8; bias may be null.
// ---------------------------------------------------------------------------
__global__ __launch_bounds__(256) void conv_kernel(
    const __nv_bfloat16* __restrict__ W,
    __nv_bfloat16* dst0, const float* bias0,
    __nv_bfloat16* dst1, const float* bias1)
{
    extern __shared__ __align__(16) __nv_bfloat16 dynsm[];
    __nv_bfloat16* Abuf[2] = { dynsm, dynsm + 128*72 };
    __nv_bfloat16* Bbuf[2] = { dynsm + 2*128*72, dynsm + 2*128*72 + 64*136 };

    int b = blockIdx.z, m0 = blockIdx.y * 128, n0 = blockIdx.x * 128;
    int tid = threadIdx.x, wid = tid >> 5, lane = tid & 31;
    int mw = (wid >> 2) * 64, nw = (wid & 3) * 32;
    int g = lane >> 2, tg = lane & 3;

    int arow = tid >> 1, acb = (tid & 1) * 32;
    int brow = tid >> 2, bcb = (tid & 3) * 32;
    const __nv_bfloat16* asrc0 = W + (size_t)(m0 + arow) * 256 + acb;
    const __nv_bfloat16* bsrc0 = g_xb + ((size_t)b * CC + brow) * HWSZ + n0 + bcb;

    float acc[4][4][4] = {};

    {
        uint32_t ad = smem_u32(Abuf[0] + arow*72 + acb);
        uint32_t bd = smem_u32(Bbuf[0] + brow*136 + bcb);
        #pragma unroll
        for (int j = 0; j < 4; j++) { cpa16(ad + j*16, asrc0 + j*8); cpa16(bd + j*16, bsrc0 + j*8); }
        CP_COMMIT();
    }
    #pragma unroll
    for (int s = 0; s < 4; s++) {
        if (s < 3) {
            int kk = (s + 1) * 64;
            uint32_t ad = smem_u32(Abuf[(s+1)&1] + arow*72 + acb);
            uint32_t bd = smem_u32(Bbuf[(s+1)&1] + brow*136 + bcb);
            #pragma unroll
            for (int j = 0; j < 4; j++) {
                cpa16(ad + j*16, asrc0 + kk + j*8);
                cpa16(bd + j*16, bsrc0 + (size_t)kk * HWSZ + j*8);
            }
            CP_COMMIT();
            cp_wait<1>();
        } else cp_wait<0>();
        __syncthreads();
        mma_128x128(Abuf[s&1], Bbuf[s&1], mw, nw, lane, acc);
        __syncthreads();
    }

    int mat = m0 >> 8, ob = m0 & 255;
    __nv_bfloat16* dst = mat ? dst1 : dst0;
    const float* bias = mat ? bias1 : bias0;
    #pragma unroll
    for (int mf = 0; mf < 4; mf++) {
        int r = mw + mf * 16 + g;
        int o1 = ob + r, o2 = o1 + 8;
        float b1 = bias ? bias[o1] : 0.f;
        float b2 = bias ? bias[o2] : 0.f;
        size_t base1 = ((size_t)b * CC + o1) * HWSZ + n0;
        size_t base2 = ((size_t)b * CC + o2) * HWSZ + n0;
        #pragma unroll
        for (int nf = 0; nf < 4; nf++) {
            int col = nw + nf * 8 + tg * 2;
            *(uint32_t*)&dst[base1 + col] = packbf(acc[mf][nf][0] + b1, acc[mf][nf][1] + b1);
            *(uint32_t*)&dst[base2 + col] = packbf(acc[mf][nf][2] + b2, acc[mf][nf][3] + b2);
        }
    }
}

// ---------------------------------------------------------------------------
// per-axis x sums: MODE 0: xs[b,k,w] = sum_h x[b,k,h,w]; MODE 1: xs[b,k,h] = sum_w
// ---------------------------------------------------------------------------
template<int MODE>
__global__ __launch_bounds__(96) void xsum_kernel()
{
    int k = blockIdx.x, b = blockIdx.y, i = threadIdx.x;
    const __nv_bfloat16* src = g_xb + ((size_t)b * CC + k) * HWSZ;
    float s = 0.f;
    if (MODE == 0) { for (int h = 0; h < 96; h++) s += __bfloat162float(src[h*96 + i]); }
    else           { for (int w = 0; w < 96; w++) s += __bfloat162float(src[i*96 + w]); }
    g_xs[((size_t)b * CC + k) * 96 + i] = s;
}

// u[b,j] = sum_k w2[k] xs[b,k,j]; v[b,j] = sum_k w1[k] xs[b,k,j]
__global__ __launch_bounds__(96) void uv_kernel()
{
    int b = blockIdx.x, j = threadIdx.x;
    float su = 0.f, sv = 0.f;
    for (int k = 0; k < 256; k++) {
        float xv = g_xs[((size_t)b * CC + k) * 96 + j];
        su += g_w2[k] * xv;
        sv += g_w1[k] * xv;
    }
    g_u[b*96 + j] = su;
    g_v[b*96 + j] = sv;
}

// ---------------------------------------------------------------------------
// slice logits: S[i,j] = sum_{c,h} A[c,h,i] B[c,h,j] (MODE 0 width, 1 height)
// ---------------------------------------------------------------------------
template<int MODE>
__global__ __launch_bounds__(256) void slice_logits_bf16_kernel(
    const __nv_bfloat16* __restrict__ Abase, const __nv_bfloat16* __restrict__ Bbase)
{
    extern __shared__ __align__(16) __nv_bfloat16 dynsm[];
    __nv_bfloat16* Tb[2] = { dynsm,            dynsm + 2*96*104 };
    __nv_bfloat16* Pb[2] = { dynsm + 96*104,   dynsm + 3*96*104 };

    int b = blockIdx.y, cch = blockIdx.x;
    int tid = threadIdx.x, wid = tid >> 5, lane = tid & 31;
    int mw = (wid >> 2) * 48, nw = (wid & 3) * 24;
    int g = lane >> 2, tg = lane & 3;

    const __nv_bfloat16* tbase = Abase + ((size_t)b * CC + cch * 16) * HWSZ;
    const __nv_bfloat16* pbase = Bbase + ((size_t)b * CC + cch * 16) * HWSZ;

    float acc[3][3][4] = {};

    auto stage = [&](int cc, int bi) {
        const __nv_bfloat16* ts = tbase + (size_t)cc * HWSZ;
        const __nv_bfloat16* ps = pbase + (size_t)cc * HWSZ;
        #pragma unroll
        for (int j = 0; j < 9; j++) {
            int c = j * 256 + tid;
            int cc2 = (c < 1152) ? c : c - 1152;
            int row = cc2 / 12, col = (cc2 % 12) * 8;
            if (c < 1152) cpa16(smem_u32(Tb[bi] + row*104 + col), ts + row*96 + col);
            else          cpa16(smem_u32(Pb[bi] + row*104 + col), ps + row*96 + col);
        }
        CP_COMMIT();
    };

    stage(0, 0);
    for (int cc = 0; cc < 16; cc++) {
        if (cc < 15) { stage(cc + 1, (cc + 1) & 1); cp_wait<1>(); }
        else cp_wait<0>();
        __syncthreads();
        const __nv_bfloat16* As = Tb[cc & 1];
        const __nv_bfloat16* Bs = Pb[cc & 1];
        #pragma unroll
        for (int ks = 0; ks < 6; ks++) {
            int k0 = ks * 16;
            uint32_t a[3][4], bf[3][2];
            #pragma unroll
            for (int mf = 0; mf < 3; mf++) {
                if (MODE == 0)
                    ldsm4t(a[mf][0], a[mf][1], a[mf][2], a[mf][3],
                        smem_u32(As + (k0 + ((lane>>4)&1)*8 + (lane&7))*104 + mw + mf*16 + ((lane>>3)&1)*8));
                else
                    ldsm4(a[mf][0], a[mf][1], a[mf][2], a[mf][3],
                        smem_u32(As + (mw + mf*16 + (lane&15))*104 + k0 + (lane>>4)*8));
            }
            if (MODE == 0) {
                ldsm4t(bf[0][0], bf[0][1], bf[1][0], bf[1][1],
                       smem_u32(Bs + (k0 + (lane&15))*104 + nw + (lane>>4)*8));
                ldsm2t(bf[2][0], bf[2][1],
                       smem_u32(Bs + (k0 + (lane&15))*104 + nw + 16));
            } else {
                ldsm4(bf[0][0], bf[0][1], bf[1][0], bf[1][1],
                      smem_u32(Bs + (nw + (lane>>4)*8 + (lane&7))*104 + k0 + ((lane>>3)&1)*8));
                ldsm2(bf[2][0], bf[2][1],
                      smem_u32(Bs + (nw + 16 + (lane&7))*104 + k0 + ((lane>>3)&1)*8));
            }
            #pragma unroll
            for (int mf = 0; mf < 3; mf++)
                #pragma unroll
                for (int nf = 0; nf < 3; nf++)
                    mma_bf16(acc[mf][nf], a[mf][0], a[mf][1], a[mf][2], a[mf][3],
                             bf[nf][0], bf[nf][1]);
        }
        __syncthreads();
    }
    float* Sb = g_S + (size_t)b * 9216;
    #pragma unroll
    for (int mf = 0; mf < 3; mf++) {
        int i1 = mw + mf * 16 + g, i2 = i1 + 8;
        #pragma unroll
        for (int nf = 0; nf < 3; nf++) {
            int jc = nw + nf * 8 + tg * 2;
            atomicAdd(&Sb[i1 * 96 + jc],     acc[mf][nf][0]);
            atomicAdd(&Sb[i1 * 96 + jc + 1], acc[mf][nf][1]);
            atomicAdd(&Sb[i2 * 96 + jc],     acc[mf][nf][2]);
            atomicAdd(&Sb[i2 * 96 + jc + 1], acc[mf][nf][3]);
        }
    }
}

// ---------------------------------------------------------------------------
// softmax: optional additive bias val += u[b,j] + v[row] + c0. writes bf16 P.
// ---------------------------------------------------------------------------
__global__ __launch_bounds__(256) void softmax_kernel(int n, const float* u,
                                                      const float* v, const float* c0p)
{
    size_t base = (size_t)blockIdx.x * n;
    int tid = threadIdx.x;
    __shared__ float red[8];

    float rowadd = 0.f;
    int ub = 0;
    if (u) {
        rowadd = v[blockIdx.x] + *c0p;
        ub = (blockIdx.x / 96) * 96;
    }

    float m = -INFINITY;
    for (int j = tid; j < n; j += 256) {
        float val = g_S[base + j] + rowadd + (u ? u[ub + j] : 0.f);
        m = fmaxf(m, val);
    }
    #pragma unroll
    for (int o = 16; o; o >>= 1) m = fmaxf(m, __shfl_xor_sync(0xffffffffu, m, o));
    if ((tid & 31) == 0) red[tid >> 5] = m;
    __syncthreads();
    float mm = red[0];
    #pragma unroll
    for (int w = 1; w < 8; w++) mm = fmaxf(mm, red[w]);

    float s = 0.f;
    float ev[2];
    int cnt = 0;
    for (int j = tid; j < n; j += 256) {
        float val = g_S[base + j] + rowadd + (u ? u[ub + j] : 0.f);
        float e = __expf(val - mm);
        ev[cnt++] = e;
        s += e;
    }
    #pragma unroll
    for (int o = 16; o; o >>= 1) s += __shfl_xor_sync(0xffffffffu, s, o);
    if ((tid & 31) == 0) red[tid >> 5] = s;
    __syncthreads();
    float st = 0.f;
    #pragma unroll
    for (int w = 0; w < 8; w++) st += red[w];
    float inv = 1.0f / st;
    cnt = 0;
    for (int j = tid; j < n; j += 256)
        g_Pb[base + j] = __float2bfloat16(ev[cnt++] * inv);
}

// ---------------------------------------------------------------------------
// apply width / height (unchanged from R4)
// ---------------------------------------------------------------------------
__global__ __launch_bounds__(256) void apply_slice_w_kernel(
    const float* __restrict__ xin, float* __restrict__ xout, const float* __restrict__ beta_p)
{
    __shared__ __align__(16) __nv_bfloat16 As[128][104];
    __shared__ __align__(16) __nv_bfloat16 Bs[96][104];

    int b = blockIdx.y, m0 = blockIdx.x * 128;
    int tid = threadIdx.x, wid = tid >> 5, lane = tid & 31;
    int mw = (wid >> 1) * 32, nw = (wid & 1) * 48;
    int g = lane >> 2, tg = lane & 3;

    const __nv_bfloat16* gsrc = g_gb + (size_t)b * CC * HWSZ + (size_t)m0 * 96;
    const __nv_bfloat16* psrc = g_Pb + (size_t)b * 9216;
    #pragma unroll
    for (int j = 0; j < 6; j++) {
        int c = j * 256 + tid;
        int row = c / 12, col = (c % 12) * 8;
        cpa16(smem_u32(&As[row][col]), gsrc + row*96 + col);
    }
    #pragma unroll
    for (int j = 0; j < 5; j++) {
        int c = j * 256 + tid;
        if (c < 1152) {
            int row = c / 12, col = (c % 12) * 8;
            cpa16(smem_u32(&Bs[row][col]), psrc + row*96 + col);
        }
    }
    CP_COMMIT();
    cp_wait<0>();
    __syncthreads();

    float acc[2][6][4] = {};
    #pragma unroll
    for (int ks = 0; ks < 6; ks++) {
        int k0 = ks * 16;
        uint32_t a[2][4], bf[6][2];
        #pragma unroll
        for (int mf = 0; mf < 2; mf++)
            ldsm4(a[mf][0], a[mf][1], a[mf][2], a[mf][3],
                  smem_u32(&As[mw + mf*16 + (lane&15)][k0 + (lane>>4)*8]));
        #pragma unroll
        for (int nb = 0; nb < 3; nb++)
            ldsm4(bf[nb*2][0], bf[nb*2][1], bf[nb*2+1][0], bf[nb*2+1][1],
                  smem_u32(&Bs[nw + nb*16 + (lane>>4)*8 + (lane&7)][k0 + ((lane>>3)&1)*8]));
        #pragma unroll
        for (int mf = 0; mf < 2; mf++)
            #pragma unroll
            for (int nf = 0; nf < 6; nf++)
                mma_bf16(acc[mf][nf], a[mf][0], a[mf][1], a[mf][2], a[mf][3],
                         bf[nf][0], bf[nf][1]);
    }
    float beta = *beta_p;
    size_t gb = (size_t)b * CC * HWSZ;
    #pragma unroll
    for (int mf = 0; mf < 2; mf++) {
        int r1 = m0 + mw + mf * 16 + g, r2 = r1 + 8;
        #pragma unroll
        for (int nf = 0; nf < 6; nf++) {
            int col = nw + nf * 8 + tg * 2;
            size_t o1 = gb + (size_t)r1 * 96 + col;
            size_t o2 = gb + (size_t)r2 * 96 + col;
            float2 xa = *(const float2*)&xin[o1];
            float2 xb2 = *(const float2*)&xin[o2];
            float v0 = xa.x + beta*acc[mf][nf][0], v1 = xa.y + beta*acc[mf][nf][1];
            float v2 = xb2.x + beta*acc[mf][nf][2], v3 = xb2.y + beta*acc[mf][nf][3];
            *(float2*)&xout[o1] = make_float2(v0, v1);
            *(float2*)&xout[o2] = make_float2(v2, v3);
            *(uint32_t*)&g_xb[o1] = packbf(v0, v1);
            *(uint32_t*)&g_xb[o2] = packbf(v2, v3);
        }
    }
}

__global__ __launch_bounds__(256) void apply_slice_h_kernel(
    const float* __restrict__ xin, float* __restrict__ xout, const float* __restrict__ beta_p)
{
    __shared__ __align__(16) __nv_bfloat16 As[96][104];
    __shared__ __align__(16) __nv_bfloat16 Bs[96][104];

    int b = blockIdx.y, c = blockIdx.x;
    int tid = threadIdx.x, wid = tid >> 5, lane = tid & 31;
    int mw = (wid >> 2) * 48, nw = (wid & 3) * 24;
    int g = lane >> 2, tg = lane & 3;

    const __nv_bfloat16* psrc = g_Pb + (size_t)b * 9216;
    const __nv_bfloat16* gsrc = g_gb + ((size_t)b * CC + c) * HWSZ;
    #pragma unroll
    for (int j = 0; j < 9; j++) {
        int cidx = j * 256 + tid;
        int c2 = (cidx < 1152) ? cidx : cidx - 1152;
        int row = c2 / 12, col = (c2 % 12) * 8;
        if (cidx < 1152) cpa16(smem_u32(&As[row][col]), psrc + row*96 + col);
        else             cpa16(smem_u32(&Bs[row][col]), gsrc + row*96 + col);
    }
    CP_COMMIT();
    cp_wait<0>();
    __syncthreads();

    float acc[3][3][4] = {};
    #pragma unroll
    for (int ks = 0; ks < 6; ks++) {
        int k0 = ks * 16;
        uint32_t a[3][4], bf[3][2];
        #pragma unroll
        for (int mf = 0; mf < 3; mf++)
            ldsm4(a[mf][0], a[mf][1], a[mf][2], a[mf][3],
                  smem_u32(&As[mw + mf*16 + (lane&15)][k0 + (lane>>4)*8]));
        ldsm4t(bf[0][0], bf[0][1], bf[1][0], bf[1][1],
               smem_u32(&Bs[k0 + (lane&15)][nw + (lane>>4)*8]));
        ldsm2t(bf[2][0], bf[2][1],
               smem_u32(&Bs[k0 + (lane&15)][nw + 16]));
        #pragma unroll
        for (int mf = 0; mf < 3; mf++)
            #pragma unroll
            for (int nf = 0; nf < 3; nf++)
                mma_bf16(acc[mf][nf], a[mf][0], a[mf][1], a[mf][2], a[mf][3],
                         bf[nf][0], bf[nf][1]);
    }
    float beta = *beta_p;
    size_t base = ((size_t)b * CC + c) * HWSZ;
    #pragma unroll
    for (int mf = 0; mf < 3; mf++) {
        int i1 = mw + mf * 16 + g, i2 = i1 + 8;
        #pragma unroll
        for (int nf = 0; nf < 3; nf++) {
            int col = nw + nf * 8 + tg * 2;
            size_t o1 = base + (size_t)i1 * 96 + col;
            size_t o2 = base + (size_t)i2 * 96 + col;
            float2 xa = *(const float2*)&xin[o1];
            float2 xb2 = *(const float2*)&xin[o2];
            float v0 = xa.x + beta*acc[mf][nf][0], v1 = xa.y + beta*acc[mf][nf][1];
            float v2 = xb2.x + beta*acc[mf][nf][2], v3 = xb2.y + beta*acc[mf][nf][3];
            *(float2*)&xout[o1] = make_float2(v0, v1);
            *(float2*)&xout[o2] = make_float2(v2, v3);
            *(uint32_t*)&g_xb[o1] = packbf(v0, v1);
            *(uint32_t*)&g_xb[o2] = packbf(v2, v3);
        }
    }
}

// ---------------------------------------------------------------------------
// Gram: G[b][i,j] = sum_hw x[b,i,hw] x[b,j,hw] (fp32 out). Tile 64x64, BK=64.
// ---------------------------------------------------------------------------
__global__ __launch_bounds__(128) void gram_kernel()
{
    __shared__ __align__(16) __nv_bfloat16 As[2][64][72];
    __shared__ __align__(16) __nv_bfloat16 Bs[2][64][72];

    int b = blockIdx.z, i0 = blockIdx.y * 64, j0 = blockIdx.x * 64;
    int tid = threadIdx.x, wid = tid >> 5, lane = tid & 31;
    int mw = (wid >> 1) * 32, nw = (wid & 1) * 32;
    int g = lane >> 2, tg = lane & 3;

    int r = tid >> 1, cb = (tid & 1) * 32;
    const __nv_bfloat16* ts0 = g_xb + ((size_t)b * CC + i0 + r) * HWSZ + cb;
    const __nv_bfloat16* ps0 = g_xb + ((size_t)b * CC + j0 + r) * HWSZ + cb;

    float acc[2][4][4] = {};

    auto stage = [&](int kk, int bi) {
        uint32_t ad = smem_u32(&As[bi][r][cb]);
        uint32_t bd = smem_u32(&Bs[bi][r][cb]);
        #pragma unroll
        for (int j = 0; j < 4; j++) {
            cpa16(ad + j*16, ts0 + kk + j*8);
            cpa16(bd + j*16, ps0 + kk + j*8);
        }
        CP_COMMIT();
    };

    stage(0, 0);
    for (int s = 0; s < 144; s++) {
        if (s < 143) { stage((s + 1) * 64, (s + 1) & 1); cp_wait<1>(); }
        else cp_wait<0>();
        __syncthreads();
        const __nv_bfloat16* Ab = &As[s&1][0][0];
        const __nv_bfloat16* Bb = &Bs[s&1][0][0];
        #pragma unroll
        for (int ks = 0; ks < 4; ks++) {
            int k0 = ks * 16;
            uint32_t a[2][4], bf[4][2];
            #pragma unroll
            for (int mf = 0; mf < 2; mf++)
                ldsm4(a[mf][0], a[mf][1], a[mf][2], a[mf][3],
                      smem_u32(Ab + (mw + mf*16 + (lane&15))*72 + k0 + (lane>>4)*8));
            #pragma unroll
            for (int nb = 0; nb < 2; nb++)
                ldsm4(bf[nb*2][0], bf[nb*2][1], bf[nb*2+1][0], bf[nb*2+1][1],
                      smem_u32(Bb + (nw + nb*16 + (lane>>4)*8 + (lane&7))*72 + k0 + ((lane>>3)&1)*8));
            #pragma unroll
            for (int mf = 0; mf < 2; mf++)
                #pragma unroll
                for (int nf = 0; nf < 4; nf++)
                    mma_bf16(acc[mf][nf], a[mf][0], a[mf][1], a[mf][2], a[mf][3],
                             bf[nf][0], bf[nf][1]);
        }
        __syncthreads();
    }
    float* Gb = g_G + (size_t)b * 65536;
    #pragma unroll
    for (int mf = 0; mf < 2; mf++) {
        int i1 = i0 + mw + mf * 16 + g, i2 = i1 + 8;
        #pragma unroll
        for (int nf = 0; nf < 4; nf++) {
            int jc = j0 + nw + nf * 8 + tg * 2;
            *(float2*)&Gb[(size_t)i1 * 256 + jc] = make_float2(acc[mf][nf][0], acc[mf][nf][1]);
            *(float2*)&Gb[(size_t)i2 * 256 + jc] = make_float2(acc[mf][nf][2], acc[mf][nf][3]);
        }
    }
}

// xs2[b,c] = sum_hw x[b,c,:]
__global__ __launch_bounds__(256) void xsum2_kernel()
{
    int k = blockIdx.x, b = blockIdx.y, tid = threadIdx.x;
    const __nv_bfloat16* src = g_xb + ((size_t)b * CC + k) * HWSZ;
    __shared__ float red[8];
    float s = 0.f;
    for (int e = tid; e < HWSZ; e += 256) s += __bfloat162float(src[e]);
    #pragma unroll
    for (int o = 16; o; o >>= 1) s += __shfl_xor_sync(0xffffffffu, s, o);
    if ((tid & 31) == 0) red[tid >> 5] = s;
    __syncthreads();
    if (tid == 0) {
        float t = 0.f;
        #pragma unroll
        for (int w = 0; w < 8; w++) t += red[w];
        g_xs2[b * CC + k] = t;
    }
}

// sA[b,i] = (Wt xs2)[i]; sB2[b,i] = (Wp xs2)[i] + 9216*bp[i]
__global__ __launch_bounds__(256) void sAsB_kernel(const float* __restrict__ wt,
                                                   const float* __restrict__ wp,
                                                   const float* __restrict__ bp)
{
    int b = blockIdx.x, i = threadIdx.x;
    float sa = 0.f, sb = 0.f;
    const float* xs2 = g_xs2 + b * CC;
    for (int c = 0; c < 256; c++) {
        float xv = xs2[c];
        sa += wt[i*256 + c] * xv;
        sb += wp[i*256 + c] * xv;
    }
    g_sA[b*CC + i] = sa;
    g_sB2[b*CC + i] = sb + 9216.f * bp[i];
}

// ---------------------------------------------------------------------------
// fp32 GEMM NN: T1[b] = wt(256x256 fp32) @ G[b](256x256). Tile 64x64, BK=16.
// ---------------------------------------------------------------------------
__global__ __launch_bounds__(256) void f32gemm_nn_kernel(const float* __restrict__ wt)
{
    int b  = blockIdx.z;
    int i0 = blockIdx.y * 64;
    int n0 = blockIdx.x * 64;

    __shared__ __align__(16) float As[16 * 68];   // [k][i]
    __shared__ __align__(16) float Gs[16 * 68];   // [k][n]

    int tid = threadIdx.x;
    int ti4 = (tid >> 4) * 4, tj4 = (tid & 15) * 4;
    float acc[4][4] = {};

    const float* Gb = g_G + (size_t)b * 65536;

    for (int kk = 0; kk < 256; kk += 16) {
        #pragma unroll
        for (int rr = 0; rr < 4; rr++) {
            int r = rr * 16 + (tid >> 4);
            int cload = tid & 15;
            As[cload * 68 + r] = wt[(i0 + r) * 256 + kk + cload];
        }
        #pragma unroll
        for (int rr = 0; rr < 4; rr++) {
            int k = rr * 4 + (tid >> 6);
            int n = tid & 63;
            Gs[k * 68 + n] = Gb[(size_t)(kk + k) * 256 + n0 + n];
        }
        __syncthreads();
        #pragma unroll
        for (int k = 0; k < 16; k++) {
            float4 a = *(float4*)&As[k * 68 + ti4];
            float4 g4 = *(float4*)&Gs[k * 68 + tj4];
            float ar[4] = {a.x, a.y, a.z, a.w};
            float gr[4] = {g4.x, g4.y, g4.z, g4.w};
            #pragma unroll
            for (int i = 0; i < 4; i++)
                #pragma unroll
                for (int j = 0; j < 4; j++)
                    acc[i][j] += ar[i] * gr[j];
        }
        __syncthreads();
    }

    float* T1b = g_T1 + (size_t)b * 65536;
    #pragma unroll
    for (int i = 0; i < 4; i++)
        #pragma unroll
        for (int j = 0; j < 4; j++)
            T1b[(size_t)(i0 + ti4 + i) * 256 + n0 + tj4 + j] = acc[i][j];
}

// ---------------------------------------------------------------------------
// fp32 GEMM NT + channel-bias epilogue:
// S[b][i,j] = sum_k T1[b][i,k] wp[j,k] + bt[i]*sB2[b,j] + bp[j]*sA[b,i]
// ---------------------------------------------------------------------------
__global__ __launch_bounds__(256) void f32gemm_nt_kernel(const float* __restrict__ wp,
                                                         const float* __restrict__ bt,
                                                         const float* __restrict__ bp)
{
    int b  = blockIdx.z;
    int i0 = blockIdx.y * 64;
    int j0 = blockIdx.x * 64;

    __shared__ __align__(16) float Ts[32 * 68];
    __shared__ __align__(16) float Ps[32 * 68];

    int tid = threadIdx.x;
    int lc = tid & 31, lr = tid >> 5;
    int ti4 = (tid >> 4) * 4, tj4 = (tid & 15) * 4;

    float acc[4][4] = {};
    const float* T1b = g_T1 + (size_t)b * 65536;

    for (int kb = 0; kb < 8; kb++) {
        int k0 = kb * 32;
        #pragma unroll
        for (int rr = 0; rr < 8; rr++) {
            int r = rr * 8 + lr;
            Ts[lc * 68 + r] = T1b[(size_t)(i0 + r) * 256 + k0 + lc];
            Ps[lc * 68 + r] = wp[(j0 + r) * 256 + k0 + lc];
        }
        __syncthreads();
        #pragma unroll
        for (int k = 0; k < 32; k++) {
            float4 a = *(float4*)&Ts[k * 68 + ti4];
            float4 p = *(float4*)&Ps[k * 68 + tj4];
            float ar[4] = {a.x, a.y, a.z, a.w};
            float pr[4] = {p.x, p.y, p.z, p.w};
            #pragma unroll
            for (int i = 0; i < 4; i++)
                #pragma unroll
                for (int j = 0; j < 4; j++)
                    acc[i][j] += ar[i] * pr[j];
        }
        __syncthreads();
    }

    float* Sb = g_S + (size_t)b * 65536;
    #pragma unroll
    for (int i = 0; i < 4; i++) {
        int irow = i0 + ti4 + i;
        float bti = bt[irow], sai = g_sA[b*CC + irow];
        #pragma unroll
        for (int j = 0; j < 4; j++) {
            int jcol = j0 + tj4 + j;
            Sb[(size_t)irow * 256 + jcol] =
                acc[i][j] + bti * g_sB2[b*CC + jcol] + bp[jcol] * sai;
        }
    }
}

// ---------------------------------------------------------------------------
// apply channel (unchanged from R4)
// ---------------------------------------------------------------------------
__global__ __launch_bounds__(256) void apply_channel_bf16_kernel(
    const float* __restrict__ xin, float* __restrict__ xout, const float* __restrict__ beta_p)
{
    extern __shared__ __align__(16) __nv_bfloat16 dynsm[];
    __nv_bfloat16* Abuf[2] = { dynsm, dynsm + 128*72 };
    __nv_bfloat16* Bbuf[2] = { dynsm + 2*128*72, dynsm + 2*128*72 + 64*136 };

    int b = blockIdx.z, m0 = blockIdx.y * 128, n0 = blockIdx.x * 128;
    int tid = threadIdx.x, wid = tid >> 5, lane = tid & 31;
    int mw = (wid >> 2) * 64, nw = (wid & 3) * 32;
    int g = lane >> 2, tg = lane & 3;

    int arow = tid >> 1, acb = (tid & 1) * 32;
    int brow = tid >> 2, bcb = (tid & 3) * 32;
    const __nv_bfloat16* asrc0 = g_Pb + (size_t)b * 65536 + (size_t)(m0 + arow) * 256 + acb;
    const __nv_bfloat16* bsrc0 = g_gb + ((size_t)b * CC + brow) * HWSZ + n0 + bcb;

    float acc[4][4][4] = {};

    {
        uint32_t ad = smem_u32(Abuf[0] + arow*72 + acb);
        uint32_t bd = smem_u32(Bbuf[0] + brow*136 + bcb);
        #pragma unroll
        for (int j = 0; j < 4; j++) { cpa16(ad + j*16, asrc0 + j*8); cpa16(bd + j*16, bsrc0 + j*8); }
        CP_COMMIT();
    }
    #pragma unroll
    for (int s = 0; s < 4; s++) {
        if (s < 3) {
            int kk = (s + 1) * 64;
            uint32_t ad = smem_u32(Abuf[(s+1)&1] + arow*72 + acb);
            uint32_t bd = smem_u32(Bbuf[(s+1)&1] + brow*136 + bcb);
            #pragma unroll
            for (int j = 0; j < 4; j++) {
                cpa16(ad + j*16, asrc0 + kk + j*8);
                cpa16(bd + j*16, bsrc0 + (size_t)kk * HWSZ + j*8);
            }
            CP_COMMIT();
            cp_wait<1>();
        } else cp_wait<0>();
        __syncthreads();
        mma_128x128(Abuf[s&1], Bbuf[s&1], mw, nw, lane, acc);
        __syncthreads();
    }

    float beta = *beta_p;
    #pragma unroll
    for (int mf = 0; mf < 4; mf++) {
        int r1 = m0 + mw + mf * 16 + g, r2 = r1 + 8;
        size_t base1 = ((size_t)b * CC + r1) * HWSZ + n0;
        size_t base2 = ((size_t)b * CC + r2) * HWSZ + n0;
        #pragma unroll
        for (int nf = 0; nf < 4; nf++) {
            int col = nw + nf * 8 + tg * 2;
            float2 xa = *(const float2*)&xin[base1 + col];
            float2 xb2 = *(const float2*)&xin[base2 + col];
            *(float2*)&xout[base1 + col] =
                make_float2(xa.x + beta*acc[mf][nf][0], xa.y + beta*acc[mf][nf][1]);
            *(float2*)&xout[base2 + col] =
                make_float2(xb2.x + beta*acc[mf][nf][2], xb2.y + beta*acc[mf][nf][3]);
        }
    }
}

// ---------------------------------------------------------------------------
extern "C" void kernel_launch(void* const* d_in, const int* in_sizes, int n_in,
                              void* d_out, int out_size)
{
    const float* x      = (const float*)d_in[0];
    const float* wt     = (const float*)d_in[1];
    const float* bt     = (const float*)d_in[2];
    const float* wp     = (const float*)d_in[3];
    const float* bp     = (const float*)d_in[4];
    const float* wg     = (const float*)d_in[5];
    const float* bg     = (const float*)d_in[6];
    const float* beta_w = (const float*)d_in[7];
    const float* beta_h = (const float*)d_in[8];
    const float* beta_c = (const float*)d_in[9];
    float* out = (float*)d_out;

    float *x1, *x2, *S, *uu, *vv, *c0;
    __nv_bfloat16 *thb, *gbb, *W2, *xbb, *Wbf;
    cudaGetSymbolAddress((void**)&x1, g_x1);
    cudaGetSymbolAddress((void**)&x2, g_x2);
    cudaGetSymbolAddress((void**)&S,  g_S);
    cudaGetSymbolAddress((void**)&uu, g_u);
    cudaGetSymbolAddress((void**)&vv, g_v);
    cudaGetSymbolAddress((void**)&c0, g_c0);
    cudaGetSymbolAddress((void**)&thb, g_thb);
    cudaGetSymbolAddress((void**)&gbb, g_gb);
    cudaGetSymbolAddress((void**)&W2,  g_W2);
    cudaGetSymbolAddress((void**)&xbb, g_xb);
    cudaGetSymbolAddress((void**)&Wbf, g_Wbf);

    int gemm_smem  = (2*128*72 + 2*64*136) * 2;   // 71680 B
    int slice_smem = 4 * 96 * 104 * 2;            // 79872 B
    cudaFuncSetAttribute(conv_kernel,
                         cudaFuncAttributeMaxDynamicSharedMemorySize, gemm_smem);
    cudaFuncSetAttribute(apply_channel_bf16_kernel,
                         cudaFuncAttributeMaxDynamicSharedMemorySize, gemm_smem);
    cudaFuncSetAttribute(slice_logits_bf16_kernel<0>,
                         cudaFuncAttributeMaxDynamicSharedMemorySize, slice_smem);
    cudaFuncSetAttribute(slice_logits_bf16_kernel<1>,
                         cudaFuncAttributeMaxDynamicSharedMemorySize, slice_smem);

    xconv_kernel<<<NELEM / (256 * 8), 256>>>(x);
    wconv_kernel<<<768, 256>>>(wt, wp, wg);
    mprep_kernel<<<dim3(4, 4), 128>>>();
    biasvec_kernel<<<1, 256>>>(wt, wp, bt, bp);

    // ---- round 1: width attention ----
    conv_kernel<<<dim3(72, 4, 16), 256, gemm_smem>>>(W2, thb, nullptr, gbb, bg);
    cudaMemsetAsync(S, 0, (size_t)16 * 9216 * sizeof(float), 0);
    xsum_kernel<0><<<dim3(256, 16), 96>>>();
    uv_kernel<<<16, 96>>>();
    slice_logits_bf16_kernel<0><<<dim3(16, 16), 256, slice_smem>>>(xbb, thb);
    softmax_kernel<<<16 * 96, 256>>>(96, uu, vv, c0);
    apply_slice_w_kernel<<<dim3(192, 16), 256>>>(x, x1, beta_w);

    // ---- round 2: height attention ----
    conv_kernel<<<dim3(72, 4, 16), 256, gemm_smem>>>(W2, thb, nullptr, gbb, bg);
    cudaMemsetAsync(S, 0, (size_t)16 * 9216 * sizeof(float), 0);
    xsum_kernel<1><<<dim3(256, 16), 96>>>();
    uv_kernel<<<16, 96>>>();
    slice_logits_bf16_kernel<1><<<dim3(16, 16), 256, slice_smem>>>(xbb, thb);
    softmax_kernel<<<16 * 96, 256>>>(96, uu, vv, c0);
    apply_slice_h_kernel<<<dim3(256, 16), 256>>>(x1, x2, beta_h);

    // ---- round 3: channel attention ----
    conv_kernel<<<dim3(72, 2, 16), 256, gemm_smem>>>(Wbf + 2*65536, gbb, bg, gbb, bg);
    gram_kernel<<<dim3(4, 4, 16), 128>>>();
    xsum2_kernel<<<dim3(256, 16), 256>>>();
    sAsB_kernel<<<16, 256>>>(wt, wp, bp);
    f32gemm_nn_kernel<<<dim3(4, 4, 16), 256>>>(wt);
    f32gemm_nt_kernel<<<dim3(4, 4, 16), 256>>>(wp, bt, bp);
    softmax_kernel<<<16 * 256, 256>>>(256, nullptr, nullptr, nullptr);
    apply_channel_bf16_kernel<<<dim3(72, 2, 16), 256, gemm_smem>>>(x2, out, beta_c);
}

// round 6
// speedup vs baseline: 4.9947x; 1.0667x over previous
#include <cuda_runtime.h>
#include <cuda_bf16.h>
#include <math.h>
#include <stdint.h>

#define BB 16
#define CC 256
#define HH 96
#define WW 96
#define HWSZ (HH*WW)           // 9216
#define NELEM (BB*CC*HWSZ)     // 37,748,736

// Scratch (device globals: allocation-free rule)
__device__ __nv_bfloat16 g_thb[NELEM];       // y = M x (rounds 1-2)
__device__ __nv_bfloat16 g_gb[NELEM];        // g = Wg x + bg
__device__ __nv_bfloat16 g_xb[NELEM];        // bf16 mirror of current x
__device__ float g_x1[NELEM];
__device__ float g_x2[NELEM];
__device__ float g_S[BB*CC*CC];              // logits fp32
__device__ __nv_bfloat16 g_Pb[BB*CC*CC];     // probabilities bf16
__device__ __nv_bfloat16 g_Wbf[3*CC*CC];     // [Wt; Wp; Wg] bf16
__device__ __nv_bfloat16 g_W2[2*CC*CC];      // [M = Wt^T Wp ; Wg] bf16 (512x256)
__device__ float g_G[BB*CC*CC];              // Gram X X^T fp32
__device__ float g_T1[BB*CC*CC];             // Wt @ G fp32
__device__ float g_xs[BB*CC*96];             // per-axis sums of x
__device__ float g_xs2[BB*CC];               // full-hw sums of x
__device__ float g_u[BB*96];
__device__ float g_v[BB*96];
__device__ float g_w1[CC];
__device__ float g_w2[CC];
__device__ float g_c0[1];
__device__ float g_sA[BB*CC];
__device__ float g_sB2[BB*CC];

// ---------------------------------------------------------------------------
// helpers
// ---------------------------------------------------------------------------
__device__ __forceinline__ uint32_t smem_u32(const void* p) {
    return (uint32_t)__cvta_generic_to_shared(p);
}
__device__ __forceinline__ uint32_t packbf(float lo, float hi) {
    __nv_bfloat162 h = __floats2bfloat162_rn(lo, hi);
    return *(uint32_t*)&h;
}
__device__ __forceinline__ void cpa16(uint32_t dst, const void* src) {
    asm volatile("cp.async.cg.shared.global [%0], [%1], 16;" :: "r"(dst), "l"(src));
}
#define CP_COMMIT() asm volatile("cp.async.commit_group;")
template<int N> __device__ __forceinline__ void cp_wait() {
    asm volatile("cp.async.wait_group %0;" :: "n"(N));
}
__device__ __forceinline__ void ldsm4(uint32_t& r0, uint32_t& r1, uint32_t& r2, uint32_t& r3, uint32_t a) {
    asm volatile("ldmatrix.sync.aligned.m8n8.x4.shared.b16 {%0,%1,%2,%3},[%4];"
                 : "=r"(r0), "=r"(r1), "=r"(r2), "=r"(r3) : "r"(a));
}
__device__ __forceinline__ void ldsm4t(uint32_t& r0, uint32_t& r1, uint32_t& r2, uint32_t& r3, uint32_t a) {
    asm volatile("ldmatrix.sync.aligned.m8n8.x4.trans.shared.b16 {%0,%1,%2,%3},[%4];"
                 : "=r"(r0), "=r"(r1), "=r"(r2), "=r"(r3) : "r"(a));
}
__device__ __forceinline__ void ldsm2(uint32_t& r0, uint32_t& r1, uint32_t a) {
    asm volatile("ldmatrix.sync.aligned.m8n8.x2.shared.b16 {%0,%1},[%2];"
                 : "=r"(r0), "=r"(r1) : "r"(a));
}
__device__ __forceinline__ void ldsm2t(uint32_t& r0, uint32_t& r1, uint32_t a) {
    asm volatile("ldmatrix.sync.aligned.m8n8.x2.trans.shared.b16 {%0,%1},[%2];"
                 : "=r"(r0), "=r"(r1) : "r"(a));
}
__device__ __forceinline__ void mma_bf16(float (&d)[4], uint32_t a0, uint32_t a1, uint32_t a2, uint32_t a3,
                                         uint32_t b0, uint32_t b1) {
    asm volatile(
        "mma.sync.aligned.m16n8k16.row.col.f32.bf16.bf16.f32 "
        "{%0,%1,%2,%3},{%4,%5,%6,%7},{%8,%9},{%0,%1,%2,%3};"
        : "+f"(d[0]), "+f"(d[1]), "+f"(d[2]), "+f"(d[3])
        : "r"(a0), "r"(a1), "r"(a2), "r"(a3), "r"(b0), "r"(b1));
}

// shared 128x128x64 MMA inner step: A [m][k] lda=72 non-trans, B [k][n] ldb=136 trans.
__device__ __forceinline__ void mma_128x128(const __nv_bfloat16* As, const __nv_bfloat16* Bs,
                                            int mw, int nw, int lane, float (&acc)[4][4][4])
{
    #pragma unroll
    for (int ks = 0; ks < 4; ks++) {
        int k0 = ks * 16;
        uint32_t a[4][4], bf[4][2];
        #pragma unroll
        for (int mf = 0; mf < 4; mf++)
            ldsm4(a[mf][0], a[mf][1], a[mf][2], a[mf][3],
                  smem_u32(As + (mw + mf*16 + (lane & 15)) * 72 + k0 + (lane >> 4) * 8));
        #pragma unroll
        for (int nb = 0; nb < 2; nb++)
            ldsm4t(bf[nb*2][0], bf[nb*2][1], bf[nb*2+1][0], bf[nb*2+1][1],
                   smem_u32(Bs + (k0 + (lane & 15)) * 136 + nw + nb*16 + (lane >> 4) * 8));
        #pragma unroll
        for (int mf = 0; mf < 4; mf++)
            #pragma unroll
            for (int nf = 0; nf < 4; nf++)
                mma_bf16(acc[mf][nf], a[mf][0], a[mf][1], a[mf][2], a[mf][3],
                         bf[nf][0], bf[nf][1]);
    }
}

// ---------------------------------------------------------------------------
// one-time converts / precomputes
// ---------------------------------------------------------------------------
__global__ void wconv_kernel(const float* __restrict__ wt, const float* __restrict__ wp,
                             const float* __restrict__ wg) {
    int i = blockIdx.x * 256 + threadIdx.x;
    const float* src = (i < 65536) ? wt : (i < 131072 ? wp : wg);
    __nv_bfloat16 v = __float2bfloat16(src[i & 65535]);
    g_Wbf[i] = v;
    if (i >= 131072) g_W2[65536 + (i - 131072)] = v;   // Wg half of W2
}
__global__ void xconv_kernel(const float* __restrict__ x) {
    size_t base = ((size_t)blockIdx.x * 256 + threadIdx.x) * 8;
    float4 f0 = *(const float4*)(x + base);
    float4 f1 = *(const float4*)(x + base + 4);
    uint4 v;
    v.x = packbf(f0.x, f0.y); v.y = packbf(f0.z, f0.w);
    v.z = packbf(f1.x, f1.y); v.w = packbf(f1.z, f1.w);
    *(uint4*)(g_xb + base) = v;
}

// M = Wt^T Wp (256x256) -> g_W2 rows 0-255. Tile 64x64, K=256, 4 warps (2x2).
__global__ __launch_bounds__(128) void mprep_kernel()
{
    __shared__ __align__(16) __nv_bfloat16 As[64][72];   // [c][m]
    __shared__ __align__(16) __nv_bfloat16 Bs[64][72];   // [c][n]

    int m0 = blockIdx.y * 64, n0 = blockIdx.x * 64;
    int tid = threadIdx.x, wid = tid >> 5, lane = tid & 31;
    int mw = (wid >> 1) * 32, nw = (wid & 1) * 32;
    int g = lane >> 2, tg = lane & 3;

    float acc[2][4][4] = {};
    int cr = tid >> 1, mc = (tid & 1) * 32;

    for (int kk = 0; kk < 256; kk += 64) {
        uint32_t ad = smem_u32(&As[cr][mc]);
        uint32_t bd = smem_u32(&Bs[cr][mc]);
        const __nv_bfloat16* asrc = g_Wbf + (size_t)(kk + cr) * 256 + m0 + mc;
        const __nv_bfloat16* bsrc = g_Wbf + 65536 + (size_t)(kk + cr) * 256 + n0 + mc;
        #pragma unroll
        for (int j = 0; j < 4; j++) { cpa16(ad + j*16, asrc + j*8); cpa16(bd + j*16, bsrc + j*8); }
        CP_COMMIT();
        cp_wait<0>();
        __syncthreads();
        #pragma unroll
        for (int ks = 0; ks < 4; ks++) {
            int k0 = ks * 16;
            uint32_t a[2][4], bf[4][2];
            #pragma unroll
            for (int mf = 0; mf < 2; mf++)
                ldsm4t(a[mf][0], a[mf][1], a[mf][2], a[mf][3],
                    smem_u32(&As[k0 + ((lane>>4)&1)*8 + (lane&7)][mw + mf*16 + ((lane>>3)&1)*8]));
            ldsm4t(bf[0][0], bf[0][1], bf[1][0], bf[1][1],
                   smem_u32(&Bs[k0 + (lane&15)][nw + (lane>>4)*8]));
            ldsm4t(bf[2][0], bf[2][1], bf[3][0], bf[3][1],
                   smem_u32(&Bs[k0 + (lane&15)][nw + 16 + (lane>>4)*8]));
            #pragma unroll
            for (int mf = 0; mf < 2; mf++)
                #pragma unroll
                for (int nf = 0; nf < 4; nf++)
                    mma_bf16(acc[mf][nf], a[mf][0], a[mf][1], a[mf][2], a[mf][3],
                             bf[nf][0], bf[nf][1]);
        }
        __syncthreads();
    }
    #pragma unroll
    for (int mf = 0; mf < 2; mf++) {
        int r1 = m0 + mw + mf*16 + g, r2 = r1 + 8;
        #pragma unroll
        for (int nf = 0; nf < 4; nf++) {
            int col = n0 + nw + nf*8 + tg*2;
            *(uint32_t*)&g_W2[r1*256 + col] = packbf(acc[mf][nf][0], acc[mf][nf][1]);
            *(uint32_t*)&g_W2[r2*256 + col] = packbf(acc[mf][nf][2], acc[mf][nf][3]);
        }
    }
}

// bias fold vectors, parallel: block k computes w1[k], w2[k] via block reduce over o.
__global__ __launch_bounds__(256) void biasvec_kernel(const float* __restrict__ wt,
                                                      const float* __restrict__ wp,
                                                      const float* __restrict__ bt,
                                                      const float* __restrict__ bp)
{
    int k = blockIdx.x, o = threadIdx.x;
    __shared__ float r1[8], r2[8], r3[8];
    float btv = bt[o], bpv = bp[o];
    float s1 = wt[o*256 + k] * bpv;
    float s2 = wp[o*256 + k] * btv;
    float c  = btv * bpv;
    #pragma unroll
    for (int off = 16; off; off >>= 1) {
        s1 += __shfl_xor_sync(0xffffffffu, s1, off);
        s2 += __shfl_xor_sync(0xffffffffu, s2, off);
        c  += __shfl_xor_sync(0xffffffffu, c, off);
    }
    if ((o & 31) == 0) { r1[o>>5] = s1; r2[o>>5] = s2; r3[o>>5] = c; }
    __syncthreads();
    if (o == 0) {
        float a = 0.f, b2 = 0.f, cc = 0.f;
        #pragma unroll
        for (int w = 0; w < 8; w++) { a += r1[w]; b2 += r2[w]; cc += r3[w]; }
        g_w1[k] = a; g_w2[k] = b2;
        if (k == 0) g_c0[0] = 96.f * cc;
    }
}

// ---------------------------------------------------------------------------
// conv: [Mrows x 256 W] @ [256 x 9216 xb]; tile 128x128, BK=64, 8 warps.
// ---------------------------------------------------------------------------
__global__ __launch_bounds__(256) void conv_kernel(
    const __nv_bfloat16* __restrict__ W,
    __nv_bfloat16* dst0, const float* bias0,
    __nv_bfloat16* dst1, const float* bias1)
{
    extern __shared__ __align__(16) __nv_bfloat16 dynsm[];
    __nv_bfloat16* Abuf[2] = { dynsm, dynsm + 128*72 };
    __nv_bfloat16* Bbuf[2] = { dynsm + 2*128*72, dynsm + 2*128*72 + 64*136 };

    int b = blockIdx.z, m0 = blockIdx.y * 128, n0 = blockIdx.x * 128;
    int tid = threadIdx.x, wid = tid >> 5, lane = tid & 31;
    int mw = (wid >> 2) * 64, nw = (wid & 3) * 32;
    int g = lane >> 2, tg = lane & 3;

    int arow = tid >> 1, acb = (tid & 1) * 32;
    int brow = tid >> 2, bcb = (tid & 3) * 32;
    const __nv_bfloat16* asrc0 = W + (size_t)(m0 + arow) * 256 + acb;
    const __nv_bfloat16* bsrc0 = g_xb + ((size_t)b * CC + brow) * HWSZ + n0 + bcb;

    float acc[4][4][4] = {};

    {
        uint32_t ad = smem_u32(Abuf[0] + arow*72 + acb);
        uint32_t bd = smem_u32(Bbuf[0] + brow*136 + bcb);
        #pragma unroll
        for (int j = 0; j < 4; j++) { cpa16(ad + j*16, asrc0 + j*8); cpa16(bd + j*16, bsrc0 + j*8); }
        CP_COMMIT();
    }
    #pragma unroll
    for (int s = 0; s < 4; s++) {
        if (s < 3) {
            int kk = (s + 1) * 64;
            uint32_t ad = smem_u32(Abuf[(s+1)&1] + arow*72 + acb);
            uint32_t bd = smem_u32(Bbuf[(s+1)&1] + brow*136 + bcb);
            #pragma unroll
            for (int j = 0; j < 4; j++) {
                cpa16(ad + j*16, asrc0 + kk + j*8);
                cpa16(bd + j*16, bsrc0 + (size_t)kk * HWSZ + j*8);
            }
            CP_COMMIT();
            cp_wait<1>();
        } else cp_wait<0>();
        __syncthreads();
        mma_128x128(Abuf[s&1], Bbuf[s&1], mw, nw, lane, acc);
        __syncthreads();
    }

    int mat = m0 >> 8, ob = m0 & 255;
    __nv_bfloat16* dst = mat ? dst1 : dst0;
    const float* bias = mat ? bias1 : bias0;
    #pragma unroll
    for (int mf = 0; mf < 4; mf++) {
        int r = mw + mf * 16 + g;
        int o1 = ob + r, o2 = o1 + 8;
        float b1 = bias ? bias[o1] : 0.f;
        float b2 = bias ? bias[o2] : 0.f;
        size_t base1 = ((size_t)b * CC + o1) * HWSZ + n0;
        size_t base2 = ((size_t)b * CC + o2) * HWSZ + n0;
        #pragma unroll
        for (int nf = 0; nf < 4; nf++) {
            int col = nw + nf * 8 + tg * 2;
            *(uint32_t*)&dst[base1 + col] = packbf(acc[mf][nf][0] + b1, acc[mf][nf][1] + b1);
            *(uint32_t*)&dst[base2 + col] = packbf(acc[mf][nf][2] + b2, acc[mf][nf][3] + b2);
        }
    }
}

// ---------------------------------------------------------------------------
// per-axis x sums
// ---------------------------------------------------------------------------
template<int MODE>
__global__ __launch_bounds__(96) void xsum_kernel()
{
    int k = blockIdx.x, b = blockIdx.y, i = threadIdx.x;
    const __nv_bfloat16* src = g_xb + ((size_t)b * CC + k) * HWSZ;
    float s = 0.f;
    if (MODE == 0) {
        #pragma unroll 8
        for (int h = 0; h < 96; h++) s += __bfloat162float(src[h*96 + i]);
    } else {
        #pragma unroll 8
        for (int w = 0; w < 96; w++) s += __bfloat162float(src[i*96 + w]);
    }
    g_xs[((size_t)b * CC + k) * 96 + i] = s;
}

// u[b,j] = sum_k w2[k] xs[b,k,j]; v[b,j] = sum_k w1[k] xs[b,k,j]
__global__ __launch_bounds__(96) void uv_kernel()
{
    int b = blockIdx.x, j = threadIdx.x;
    float su = 0.f, sv = 0.f;
    #pragma unroll 8
    for (int k = 0; k < 256; k++) {
        float xv = g_xs[((size_t)b * CC + k) * 96 + j];
        su += g_w2[k] * xv;
        sv += g_w1[k] * xv;
    }
    g_u[b*96 + j] = su;
    g_v[b*96 + j] = sv;
}

// ---------------------------------------------------------------------------
// slice logits
// ---------------------------------------------------------------------------
template<int MODE>
__global__ __launch_bounds__(256) void slice_logits_bf16_kernel(
    const __nv_bfloat16* __restrict__ Abase, const __nv_bfloat16* __restrict__ Bbase)
{
    extern __shared__ __align__(16) __nv_bfloat16 dynsm[];
    __nv_bfloat16* Tb[2] = { dynsm,            dynsm + 2*96*104 };
    __nv_bfloat16* Pb[2] = { dynsm + 96*104,   dynsm + 3*96*104 };

    int b = blockIdx.y, cch = blockIdx.x;
    int tid = threadIdx.x, wid = tid >> 5, lane = tid & 31;
    int mw = (wid >> 2) * 48, nw = (wid & 3) * 24;
    int g = lane >> 2, tg = lane & 3;

    const __nv_bfloat16* tbase = Abase + ((size_t)b * CC + cch * 16) * HWSZ;
    const __nv_bfloat16* pbase = Bbase + ((size_t)b * CC + cch * 16) * HWSZ;

    float acc[3][3][4] = {};

    auto stage = [&](int cc, int bi) {
        const __nv_bfloat16* ts = tbase + (size_t)cc * HWSZ;
        const __nv_bfloat16* ps = pbase + (size_t)cc * HWSZ;
        #pragma unroll
        for (int j = 0; j < 9; j++) {
            int c = j * 256 + tid;
            int cc2 = (c < 1152) ? c : c - 1152;
            int row = cc2 / 12, col = (cc2 % 12) * 8;
            if (c < 1152) cpa16(smem_u32(Tb[bi] + row*104 + col), ts + row*96 + col);
            else          cpa16(smem_u32(Pb[bi] + row*104 + col), ps + row*96 + col);
        }
        CP_COMMIT();
    };

    stage(0, 0);
    for (int cc = 0; cc < 16; cc++) {
        if (cc < 15) { stage(cc + 1, (cc + 1) & 1); cp_wait<1>(); }
        else cp_wait<0>();
        __syncthreads();
        const __nv_bfloat16* As = Tb[cc & 1];
        const __nv_bfloat16* Bs = Pb[cc & 1];
        #pragma unroll
        for (int ks = 0; ks < 6; ks++) {
            int k0 = ks * 16;
            uint32_t a[3][4], bf[3][2];
            #pragma unroll
            for (int mf = 0; mf < 3; mf++) {
                if (MODE == 0)
                    ldsm4t(a[mf][0], a[mf][1], a[mf][2], a[mf][3],
                        smem_u32(As + (k0 + ((lane>>4)&1)*8 + (lane&7))*104 + mw + mf*16 + ((lane>>3)&1)*8));
                else
                    ldsm4(a[mf][0], a[mf][1], a[mf][2], a[mf][3],
                        smem_u32(As + (mw + mf*16 + (lane&15))*104 + k0 + (lane>>4)*8));
            }
            if (MODE == 0) {
                ldsm4t(bf[0][0], bf[0][1], bf[1][0], bf[1][1],
                       smem_u32(Bs + (k0 + (lane&15))*104 + nw + (lane>>4)*8));
                ldsm2t(bf[2][0], bf[2][1],
                       smem_u32(Bs + (k0 + (lane&15))*104 + nw + 16));
            } else {
                ldsm4(bf[0][0], bf[0][1], bf[1][0], bf[1][1],
                      smem_u32(Bs + (nw + (lane>>4)*8 + (lane&7))*104 + k0 + ((lane>>3)&1)*8));
                ldsm2(bf[2][0], bf[2][1],
                      smem_u32(Bs + (nw + 16 + (lane&7))*104 + k0 + ((lane>>3)&1)*8));
            }
            #pragma unroll
            for (int mf = 0; mf < 3; mf++)
                #pragma unroll
                for (int nf = 0; nf < 3; nf++)
                    mma_bf16(acc[mf][nf], a[mf][0], a[mf][1], a[mf][2], a[mf][3],
                             bf[nf][0], bf[nf][1]);
        }
        __syncthreads();
    }
    float* Sb = g_S + (size_t)b * 9216;
    #pragma unroll
    for (int mf = 0; mf < 3; mf++) {
        int i1 = mw + mf * 16 + g, i2 = i1 + 8;
        #pragma unroll
        for (int nf = 0; nf < 3; nf++) {
            int jc = nw + nf * 8 + tg * 2;
            atomicAdd(&Sb[i1 * 96 + jc],     acc[mf][nf][0]);
            atomicAdd(&Sb[i1 * 96 + jc + 1], acc[mf][nf][1]);
            atomicAdd(&Sb[i2 * 96 + jc],     acc[mf][nf][2]);
            atomicAdd(&Sb[i2 * 96 + jc + 1], acc[mf][nf][3]);
        }
    }
}

// ---------------------------------------------------------------------------
// softmax: optional additive bias val += u[b,j] + v[row] + c0. writes bf16 P.
// ---------------------------------------------------------------------------
__global__ __launch_bounds__(256) void softmax_kernel(int n, const float* u,
                                                      const float* v, const float* c0p)
{
    size_t base = (size_t)blockIdx.x * n;
    int tid = threadIdx.x;
    __shared__ float red[8];

    float rowadd = 0.f;
    int ub = 0;
    if (u) {
        rowadd = v[blockIdx.x] + *c0p;
        ub = (blockIdx.x / 96) * 96;
    }

    float m = -INFINITY;
    for (int j = tid; j < n; j += 256) {
        float val = g_S[base + j] + rowadd + (u ? u[ub + j] : 0.f);
        m = fmaxf(m, val);
    }
    #pragma unroll
    for (int o = 16; o; o >>= 1) m = fmaxf(m, __shfl_xor_sync(0xffffffffu, m, o));
    if ((tid & 31) == 0) red[tid >> 5] = m;
    __syncthreads();
    float mm = red[0];
    #pragma unroll
    for (int w = 1; w < 8; w++) mm = fmaxf(mm, red[w]);

    float s = 0.f;
    float ev[2];
    int cnt = 0;
    for (int j = tid; j < n; j += 256) {
        float val = g_S[base + j] + rowadd + (u ? u[ub + j] : 0.f);
        float e = __expf(val - mm);
        ev[cnt++] = e;
        s += e;
    }
    #pragma unroll
    for (int o = 16; o; o >>= 1) s += __shfl_xor_sync(0xffffffffu, s, o);
    if ((tid & 31) == 0) red[tid >> 5] = s;
    __syncthreads();
    float st = 0.f;
    #pragma unroll
    for (int w = 0; w < 8; w++) st += red[w];
    float inv = 1.0f / st;
    cnt = 0;
    for (int j = tid; j < n; j += 256)
        g_Pb[base + j] = __float2bfloat16(ev[cnt++] * inv);
}

// ---------------------------------------------------------------------------
// apply width / height
// ---------------------------------------------------------------------------
__global__ __launch_bounds__(256) void apply_slice_w_kernel(
    const float* __restrict__ xin, float* __restrict__ xout, const float* __restrict__ beta_p)
{
    __shared__ __align__(16) __nv_bfloat16 As[128][104];
    __shared__ __align__(16) __nv_bfloat16 Bs[96][104];

    int b = blockIdx.y, m0 = blockIdx.x * 128;
    int tid = threadIdx.x, wid = tid >> 5, lane = tid & 31;
    int mw = (wid >> 1) * 32, nw = (wid & 1) * 48;
    int g = lane >> 2, tg = lane & 3;

    const __nv_bfloat16* gsrc = g_gb + (size_t)b * CC * HWSZ + (size_t)m0 * 96;
    const __nv_bfloat16* psrc = g_Pb + (size_t)b * 9216;
    #pragma unroll
    for (int j = 0; j < 6; j++) {
        int c = j * 256 + tid;
        int row = c / 12, col = (c % 12) * 8;
        cpa16(smem_u32(&As[row][col]), gsrc + row*96 + col);
    }
    #pragma unroll
    for (int j = 0; j < 5; j++) {
        int c = j * 256 + tid;
        if (c < 1152) {
            int row = c / 12, col = (c % 12) * 8;
            cpa16(smem_u32(&Bs[row][col]), psrc + row*96 + col);
        }
    }
    CP_COMMIT();
    cp_wait<0>();
    __syncthreads();

    float acc[2][6][4] = {};
    #pragma unroll
    for (int ks = 0; ks < 6; ks++) {
        int k0 = ks * 16;
        uint32_t a[2][4], bf[6][2];
        #pragma unroll
        for (int mf = 0; mf < 2; mf++)
            ldsm4(a[mf][0], a[mf][1], a[mf][2], a[mf][3],
                  smem_u32(&As[mw + mf*16 + (lane&15)][k0 + (lane>>4)*8]));
        #pragma unroll
        for (int nb = 0; nb < 3; nb++)
            ldsm4(bf[nb*2][0], bf[nb*2][1], bf[nb*2+1][0], bf[nb*2+1][1],
                  smem_u32(&Bs[nw + nb*16 + (lane>>4)*8 + (lane&7)][k0 + ((lane>>3)&1)*8]));
        #pragma unroll
        for (int mf = 0; mf < 2; mf++)
            #pragma unroll
            for (int nf = 0; nf < 6; nf++)
                mma_bf16(acc[mf][nf], a[mf][0], a[mf][1], a[mf][2], a[mf][3],
                         bf[nf][0], bf[nf][1]);
    }
    float beta = *beta_p;
    size_t gb = (size_t)b * CC * HWSZ;
    #pragma unroll
    for (int mf = 0; mf < 2; mf++) {
        int r1 = m0 + mw + mf * 16 + g, r2 = r1 + 8;
        #pragma unroll
        for (int nf = 0; nf < 6; nf++) {
            int col = nw + nf * 8 + tg * 2;
            size_t o1 = gb + (size_t)r1 * 96 + col;
            size_t o2 = gb + (size_t)r2 * 96 + col;
            float2 xa = *(const float2*)&xin[o1];
            float2 xb2 = *(const float2*)&xin[o2];
            float v0 = xa.x + beta*acc[mf][nf][0], v1 = xa.y + beta*acc[mf][nf][1];
            float v2 = xb2.x + beta*acc[mf][nf][2], v3 = xb2.y + beta*acc[mf][nf][3];
            *(float2*)&xout[o1] = make_float2(v0, v1);
            *(float2*)&xout[o2] = make_float2(v2, v3);
            *(uint32_t*)&g_xb[o1] = packbf(v0, v1);
            *(uint32_t*)&g_xb[o2] = packbf(v2, v3);
        }
    }
}

__global__ __launch_bounds__(256) void apply_slice_h_kernel(
    const float* __restrict__ xin, float* __restrict__ xout, const float* __restrict__ beta_p)
{
    __shared__ __align__(16) __nv_bfloat16 As[96][104];
    __shared__ __align__(16) __nv_bfloat16 Bs[96][104];

    int b = blockIdx.y, c = blockIdx.x;
    int tid = threadIdx.x, wid = tid >> 5, lane = tid & 31;
    int mw = (wid >> 2) * 48, nw = (wid & 3) * 24;
    int g = lane >> 2, tg = lane & 3;

    const __nv_bfloat16* psrc = g_Pb + (size_t)b * 9216;
    const __nv_bfloat16* gsrc = g_gb + ((size_t)b * CC + c) * HWSZ;
    #pragma unroll
    for (int j = 0; j < 9; j++) {
        int cidx = j * 256 + tid;
        int c2 = (cidx < 1152) ? cidx : cidx - 1152;
        int row = c2 / 12, col = (c2 % 12) * 8;
        if (cidx < 1152) cpa16(smem_u32(&As[row][col]), psrc + row*96 + col);
        else             cpa16(smem_u32(&Bs[row][col]), gsrc + row*96 + col);
    }
    CP_COMMIT();
    cp_wait<0>();
    __syncthreads();

    float acc[3][3][4] = {};
    #pragma unroll
    for (int ks = 0; ks < 6; ks++) {
        int k0 = ks * 16;
        uint32_t a[3][4], bf[3][2];
        #pragma unroll
        for (int mf = 0; mf < 3; mf++)
            ldsm4(a[mf][0], a[mf][1], a[mf][2], a[mf][3],
                  smem_u32(&As[mw + mf*16 + (lane&15)][k0 + (lane>>4)*8]));
        ldsm4t(bf[0][0], bf[0][1], bf[1][0], bf[1][1],
               smem_u32(&Bs[k0 + (lane&15)][nw + (lane>>4)*8]));
        ldsm2t(bf[2][0], bf[2][1],
               smem_u32(&Bs[k0 + (lane&15)][nw + 16]));
        #pragma unroll
        for (int mf = 0; mf < 3; mf++)
            #pragma unroll
            for (int nf = 0; nf < 3; nf++)
                mma_bf16(acc[mf][nf], a[mf][0], a[mf][1], a[mf][2], a[mf][3],
                         bf[nf][0], bf[nf][1]);
    }
    float beta = *beta_p;
    size_t base = ((size_t)b * CC + c) * HWSZ;
    #pragma unroll
    for (int mf = 0; mf < 3; mf++) {
        int i1 = mw + mf * 16 + g, i2 = i1 + 8;
        #pragma unroll
        for (int nf = 0; nf < 3; nf++) {
            int col = nw + nf * 8 + tg * 2;
            size_t o1 = base + (size_t)i1 * 96 + col;
            size_t o2 = base + (size_t)i2 * 96 + col;
            float2 xa = *(const float2*)&xin[o1];
            float2 xb2 = *(const float2*)&xin[o2];
            float v0 = xa.x + beta*acc[mf][nf][0], v1 = xa.y + beta*acc[mf][nf][1];
            float v2 = xb2.x + beta*acc[mf][nf][2], v3 = xb2.y + beta*acc[mf][nf][3];
            *(float2*)&xout[o1] = make_float2(v0, v1);
            *(float2*)&xout[o2] = make_float2(v2, v3);
            *(uint32_t*)&g_xb[o1] = packbf(v0, v1);
            *(uint32_t*)&g_xb[o2] = packbf(v2, v3);
        }
    }
}

// ---------------------------------------------------------------------------
// Gram: G[b][i,j] = sum_hw x[b,i,hw] x[b,j,hw]. Tile 64x64, BK=64.
// ---------------------------------------------------------------------------
__global__ __launch_bounds__(128) void gram_kernel()
{
    __shared__ __align__(16) __nv_bfloat16 As[2][64][72];
    __shared__ __align__(16) __nv_bfloat16 Bs[2][64][72];

    int b = blockIdx.z, i0 = blockIdx.y * 64, j0 = blockIdx.x * 64;
    int tid = threadIdx.x, wid = tid >> 5, lane = tid & 31;
    int mw = (wid >> 1) * 32, nw = (wid & 1) * 32;
    int g = lane >> 2, tg = lane & 3;

    int r = tid >> 1, cb = (tid & 1) * 32;
    const __nv_bfloat16* ts0 = g_xb + ((size_t)b * CC + i0 + r) * HWSZ + cb;
    const __nv_bfloat16* ps0 = g_xb + ((size_t)b * CC + j0 + r) * HWSZ + cb;

    float acc[2][4][4] = {};

    auto stage = [&](int kk, int bi) {
        uint32_t ad = smem_u32(&As[bi][r][cb]);
        uint32_t bd = smem_u32(&Bs[bi][r][cb]);
        #pragma unroll
        for (int j = 0; j < 4; j++) {
            cpa16(ad + j*16, ts0 + kk + j*8);
            cpa16(bd + j*16, ps0 + kk + j*8);
        }
        CP_COMMIT();
    };

    stage(0, 0);
    for (int s = 0; s < 144; s++) {
        if (s < 143) { stage((s + 1) * 64, (s + 1) & 1); cp_wait<1>(); }
        else cp_wait<0>();
        __syncthreads();
        const __nv_bfloat16* Ab = &As[s&1][0][0];
        const __nv_bfloat16* Bb = &Bs[s&1][0][0];
        #pragma unroll
        for (int ks = 0; ks < 4; ks++) {
            int k0 = ks * 16;
            uint32_t a[2][4], bf[4][2];
            #pragma unroll
            for (int mf = 0; mf < 2; mf++)
                ldsm4(a[mf][0], a[mf][1], a[mf][2], a[mf][3],
                      smem_u32(Ab + (mw + mf*16 + (lane&15))*72 + k0 + (lane>>4)*8));
            #pragma unroll
            for (int nb = 0; nb < 2; nb++)
                ldsm4(bf[nb*2][0], bf[nb*2][1], bf[nb*2+1][0], bf[nb*2+1][1],
                      smem_u32(Bb + (nw + nb*16 + (lane>>4)*8 + (lane&7))*72 + k0 + ((lane>>3)&1)*8));
            #pragma unroll
            for (int mf = 0; mf < 2; mf++)
                #pragma unroll
                for (int nf = 0; nf < 4; nf++)
                    mma_bf16(acc[mf][nf], a[mf][0], a[mf][1], a[mf][2], a[mf][3],
                             bf[nf][0], bf[nf][1]);
        }
        __syncthreads();
    }
    float* Gb = g_G + (size_t)b * 65536;
    #pragma unroll
    for (int mf = 0; mf < 2; mf++) {
        int i1 = i0 + mw + mf * 16 + g, i2 = i1 + 8;
        #pragma unroll
        for (int nf = 0; nf < 4; nf++) {
            int jc = j0 + nw + nf * 8 + tg * 2;
            *(float2*)&Gb[(size_t)i1 * 256 + jc] = make_float2(acc[mf][nf][0], acc[mf][nf][1]);
            *(float2*)&Gb[(size_t)i2 * 256 + jc] = make_float2(acc[mf][nf][2], acc[mf][nf][3]);
        }
    }
}

// xs2[b,c] = sum_hw x[b,c,:]
__global__ __launch_bounds__(256) void xsum2_kernel()
{
    int k = blockIdx.x, b = blockIdx.y, tid = threadIdx.x;
    const __nv_bfloat16* src = g_xb + ((size_t)b * CC + k) * HWSZ;
    __shared__ float red[8];
    float s = 0.f;
    for (int e = tid; e < HWSZ; e += 256) s += __bfloat162float(src[e]);
    #pragma unroll
    for (int o = 16; o; o >>= 1) s += __shfl_xor_sync(0xffffffffu, s, o);
    if ((tid & 31) == 0) red[tid >> 5] = s;
    __syncthreads();
    if (tid == 0) {
        float t = 0.f;
        #pragma unroll
        for (int w = 0; w < 8; w++) t += red[w];
        g_xs2[b * CC + k] = t;
    }
}

// sA[b,i] = (Wt xs2)[i]; sB2[b,i] = (Wp xs2)[i] + 9216*bp[i]  (parallel, coalesced)
__global__ __launch_bounds__(256) void sAsB_kernel(const float* __restrict__ wt,
                                                   const float* __restrict__ wp,
                                                   const float* __restrict__ bp)
{
    int i = blockIdx.x, b = blockIdx.y, c = threadIdx.x;
    __shared__ float r1[8], r2[8];
    float xv = g_xs2[b*CC + c];
    float sa = wt[i*256 + c] * xv;
    float sb = wp[i*256 + c] * xv;
    #pragma unroll
    for (int off = 16; off; off >>= 1) {
        sa += __shfl_xor_sync(0xffffffffu, sa, off);
        sb += __shfl_xor_sync(0xffffffffu, sb, off);
    }
    if ((c & 31) == 0) { r1[c>>5] = sa; r2[c>>5] = sb; }
    __syncthreads();
    if (c == 0) {
        float a = 0.f, b2 = 0.f;
        #pragma unroll
        for (int w = 0; w < 8; w++) { a += r1[w]; b2 += r2[w]; }
        g_sA[b*CC + i] = a;
        g_sB2[b*CC + i] = b2 + 9216.f * bp[i];
    }
}

// ---------------------------------------------------------------------------
// fp32 GEMM NN: T1[b] = wt @ G[b]. Tile 64x64, BK=16.
// ---------------------------------------------------------------------------
__global__ __launch_bounds__(256) void f32gemm_nn_kernel(const float* __restrict__ wt)
{
    int b  = blockIdx.z;
    int i0 = blockIdx.y * 64;
    int n0 = blockIdx.x * 64;

    __shared__ __align__(16) float As[16 * 68];
    __shared__ __align__(16) float Gs[16 * 68];

    int tid = threadIdx.x;
    int ti4 = (tid >> 4) * 4, tj4 = (tid & 15) * 4;
    float acc[4][4] = {};

    const float* Gb = g_G + (size_t)b * 65536;

    for (int kk = 0; kk < 256; kk += 16) {
        #pragma unroll
        for (int rr = 0; rr < 4; rr++) {
            int r = rr * 16 + (tid >> 4);
            int cload = tid & 15;
            As[cload * 68 + r] = wt[(i0 + r) * 256 + kk + cload];
        }
        #pragma unroll
        for (int rr = 0; rr < 4; rr++) {
            int k = rr * 4 + (tid >> 6);
            int n = tid & 63;
            Gs[k * 68 + n] = Gb[(size_t)(kk + k) * 256 + n0 + n];
        }
        __syncthreads();
        #pragma unroll
        for (int k = 0; k < 16; k++) {
            float4 a = *(float4*)&As[k * 68 + ti4];
            float4 g4 = *(float4*)&Gs[k * 68 + tj4];
            float ar[4] = {a.x, a.y, a.z, a.w};
            float gr[4] = {g4.x, g4.y, g4.z, g4.w};
            #pragma unroll
            for (int i = 0; i < 4; i++)
                #pragma unroll
                for (int j = 0; j < 4; j++)
                    acc[i][j] += ar[i] * gr[j];
        }
        __syncthreads();
    }

    float* T1b = g_T1 + (size_t)b * 65536;
    #pragma unroll
    for (int i = 0; i < 4; i++)
        #pragma unroll
        for (int j = 0; j < 4; j++)
            T1b[(size_t)(i0 + ti4 + i) * 256 + n0 + tj4 + j] = acc[i][j];
}

// ---------------------------------------------------------------------------
// fp32 GEMM NT + channel-bias epilogue.
// ---------------------------------------------------------------------------
__global__ __launch_bounds__(256) void f32gemm_nt_kernel(const float* __restrict__ wp,
                                                         const float* __restrict__ bt,
                                                         const float* __restrict__ bp)
{
    int b  = blockIdx.z;
    int i0 = blockIdx.y * 64;
    int j0 = blockIdx.x * 64;

    __shared__ __align__(16) float Ts[32 * 68];
    __shared__ __align__(16) float Ps[32 * 68];

    int tid = threadIdx.x;
    int lc = tid & 31, lr = tid >> 5;
    int ti4 = (tid >> 4) * 4, tj4 = (tid & 15) * 4;

    float acc[4][4] = {};
    const float* T1b = g_T1 + (size_t)b * 65536;

    for (int kb = 0; kb < 8; kb++) {
        int k0 = kb * 32;
        #pragma unroll
        for (int rr = 0; rr < 8; rr++) {
            int r = rr * 8 + lr;
            Ts[lc * 68 + r] = T1b[(size_t)(i0 + r) * 256 + k0 + lc];
            Ps[lc * 68 + r] = wp[(j0 + r) * 256 + k0 + lc];
        }
        __syncthreads();
        #pragma unroll
        for (int k = 0; k < 32; k++) {
            float4 a = *(float4*)&Ts[k * 68 + ti4];
            float4 p = *(float4*)&Ps[k * 68 + tj4];
            float ar[4] = {a.x, a.y, a.z, a.w};
            float pr[4] = {p.x, p.y, p.z, p.w};
            #pragma unroll
            for (int i = 0; i < 4; i++)
                #pragma unroll
                for (int j = 0; j < 4; j++)
                    acc[i][j] += ar[i] * pr[j];
        }
        __syncthreads();
    }

    float* Sb = g_S + (size_t)b * 65536;
    #pragma unroll
    for (int i = 0; i < 4; i++) {
        int irow = i0 + ti4 + i;
        float bti = bt[irow], sai = g_sA[b*CC + irow];
        #pragma unroll
        for (int j = 0; j < 4; j++) {
            int jcol = j0 + tj4 + j;
            Sb[(size_t)irow * 256 + jcol] =
                acc[i][j] + bti * g_sB2[b*CC + jcol] + bp[jcol] * sai;
        }
    }
}

// ---------------------------------------------------------------------------
// apply channel
// ---------------------------------------------------------------------------
__global__ __launch_bounds__(256) void apply_channel_bf16_kernel(
    const float* __restrict__ xin, float* __restrict__ xout, const float* __restrict__ beta_p)
{
    extern __shared__ __align__(16) __nv_bfloat16 dynsm[];
    __nv_bfloat16* Abuf[2] = { dynsm, dynsm + 128*72 };
    __nv_bfloat16* Bbuf[2] = { dynsm + 2*128*72, dynsm + 2*128*72 + 64*136 };

    int b = blockIdx.z, m0 = blockIdx.y * 128, n0 = blockIdx.x * 128;
    int tid = threadIdx.x, wid = tid >> 5, lane = tid & 31;
    int mw = (wid >> 2) * 64, nw = (wid & 3) * 32;
    int g = lane >> 2, tg = lane & 3;

    int arow = tid >> 1, acb = (tid & 1) * 32;
    int brow = tid >> 2, bcb = (tid & 3) * 32;
    const __nv_bfloat16* asrc0 = g_Pb + (size_t)b * 65536 + (size_t)(m0 + arow) * 256 + acb;
    const __nv_bfloat16* bsrc0 = g_gb + ((size_t)b * CC + brow) * HWSZ + n0 + bcb;

    float acc[4][4][4] = {};

    {
        uint32_t ad = smem_u32(Abuf[0] + arow*72 + acb);
        uint32_t bd = smem_u32(Bbuf[0] + brow*136 + bcb);
        #pragma unroll
        for (int j = 0; j < 4; j++) { cpa16(ad + j*16, asrc0 + j*8); cpa16(bd + j*16, bsrc0 + j*8); }
        CP_COMMIT();
    }
    #pragma unroll
    for (int s = 0; s < 4; s++) {
        if (s < 3) {
            int kk = (s + 1) * 64;
            uint32_t ad = smem_u32(Abuf[(s+1)&1] + arow*72 + acb);
            uint32_t bd = smem_u32(Bbuf[(s+1)&1] + brow*136 + bcb);
            #pragma unroll
            for (int j = 0; j < 4; j++) {
                cpa16(ad + j*16, asrc0 + kk + j*8);
                cpa16(bd + j*16, bsrc0 + (size_t)kk * HWSZ + j*8);
            }
            CP_COMMIT();
            cp_wait<1>();
        } else cp_wait<0>();
        __syncthreads();
        mma_128x128(Abuf[s&1], Bbuf[s&1], mw, nw, lane, acc);
        __syncthreads();
    }

    float beta = *beta_p;
    #pragma unroll
    for (int mf = 0; mf < 4; mf++) {
        int r1 = m0 + mw + mf * 16 + g, r2 = r1 + 8;
        size_t base1 = ((size_t)b * CC + r1) * HWSZ + n0;
        size_t base2 = ((size_t)b * CC + r2) * HWSZ + n0;
        #pragma unroll
        for (int nf = 0; nf < 4; nf++) {
            int col = nw + nf * 8 + tg * 2;
            float2 xa = *(const float2*)&xin[base1 + col];
            float2 xb2 = *(const float2*)&xin[base2 + col];
            *(float2*)&xout[base1 + col] =
                make_float2(xa.x + beta*acc[mf][nf][0], xa.y + beta*acc[mf][nf][1]);
            *(float2*)&xout[base2 + col] =
                make_float2(xb2.x + beta*acc[mf][nf][2], xb2.y + beta*acc[mf][nf][3]);
        }
    }
}

// ---------------------------------------------------------------------------
extern "C" void kernel_launch(void* const* d_in, const int* in_sizes, int n_in,
                              void* d_out, int out_size)
{
    const float* x      = (const float*)d_in[0];
    const float* wt     = (const float*)d_in[1];
    const float* bt     = (const float*)d_in[2];
    const float* wp     = (const float*)d_in[3];
    const float* bp     = (const float*)d_in[4];
    const float* wg     = (const float*)d_in[5];
    const float* bg     = (const float*)d_in[6];
    const float* beta_w = (const float*)d_in[7];
    const float* beta_h = (const float*)d_in[8];
    const float* beta_c = (const float*)d_in[9];
    float* out = (float*)d_out;

    float *x1, *x2, *S, *uu, *vv, *c0;
    __nv_bfloat16 *thb, *gbb, *W2, *xbb, *Wbf;
    cudaGetSymbolAddress((void**)&x1, g_x1);
    cudaGetSymbolAddress((void**)&x2, g_x2);
    cudaGetSymbolAddress((void**)&S,  g_S);
    cudaGetSymbolAddress((void**)&uu, g_u);
    cudaGetSymbolAddress((void**)&vv, g_v);
    cudaGetSymbolAddress((void**)&c0, g_c0);
    cudaGetSymbolAddress((void**)&thb, g_thb);
    cudaGetSymbolAddress((void**)&gbb, g_gb);
    cudaGetSymbolAddress((void**)&W2,  g_W2);
    cudaGetSymbolAddress((void**)&xbb, g_xb);
    cudaGetSymbolAddress((void**)&Wbf, g_Wbf);

    int gemm_smem  = (2*128*72 + 2*64*136) * 2;   // 71680 B
    int slice_smem = 4 * 96 * 104 * 2;            // 79872 B
    cudaFuncSetAttribute(conv_kernel,
                         cudaFuncAttributeMaxDynamicSharedMemorySize, gemm_smem);
    cudaFuncSetAttribute(apply_channel_bf16_kernel,
                         cudaFuncAttributeMaxDynamicSharedMemorySize, gemm_smem);
    cudaFuncSetAttribute(slice_logits_bf16_kernel<0>,
                         cudaFuncAttributeMaxDynamicSharedMemorySize, slice_smem);
    cudaFuncSetAttribute(slice_logits_bf16_kernel<1>,
                         cudaFuncAttributeMaxDynamicSharedMemorySize, slice_smem);

    // second stream + events (host-side resources; created once, outside capture)
    static cudaStream_t s2 = nullptr;
    static cudaEvent_t ev[8];
    if (!s2) {
        cudaStreamCreateWithFlags(&s2, cudaStreamNonBlocking);
        for (int i = 0; i < 8; i++)
            cudaEventCreateWithFlags(&ev[i], cudaEventDisableTiming);
    }
    cudaStream_t s0 = 0;

    // ---- prologue ----
    xconv_kernel<<<NELEM / (256 * 8), 256, 0, s0>>>(x);
    cudaEventRecord(ev[0], s0);                               // g_xb ready

    cudaStreamWaitEvent(s2, ev[0], 0);                        // fork s2
    wconv_kernel<<<768, 256, 0, s2>>>(wt, wp, wg);
    mprep_kernel<<<dim3(4, 4), 128, 0, s2>>>();
    cudaEventRecord(ev[1], s2);                               // W2 ready
    biasvec_kernel<<<256, 256, 0, s2>>>(wt, wp, bt, bp);
    cudaMemsetAsync(S, 0, (size_t)16 * 9216 * sizeof(float), s2);
    xsum_kernel<0><<<dim3(256, 16), 96, 0, s2>>>();
    uv_kernel<<<16, 96, 0, s2>>>();
    cudaEventRecord(ev[2], s2);                               // S zeroed + u/v ready

    // ---- round 1: width attention ----
    cudaStreamWaitEvent(s0, ev[1], 0);
    conv_kernel<<<dim3(72, 4, 16), 256, gemm_smem, s0>>>(W2, thb, nullptr, gbb, bg);
    cudaStreamWaitEvent(s0, ev[2], 0);
    slice_logits_bf16_kernel<0><<<dim3(16, 16), 256, slice_smem, s0>>>(xbb, thb);
    softmax_kernel<<<16 * 96, 256, 0, s0>>>(96, uu, vv, c0);
    apply_slice_w_kernel<<<dim3(192, 16), 256, 0, s0>>>(x, x1, beta_w);
    cudaEventRecord(ev[3], s0);                               // new x (g_xb) ready

    // ---- round 2: height attention ----
    cudaStreamWaitEvent(s2, ev[3], 0);
    cudaMemsetAsync(S, 0, (size_t)16 * 9216 * sizeof(float), s2);
    xsum_kernel<1><<<dim3(256, 16), 96, 0, s2>>>();
    uv_kernel<<<16, 96, 0, s2>>>();
    cudaEventRecord(ev[4], s2);

    conv_kernel<<<dim3(72, 4, 16), 256, gemm_smem, s0>>>(W2, thb, nullptr, gbb, bg);
    cudaStreamWaitEvent(s0, ev[4], 0);
    slice_logits_bf16_kernel<1><<<dim3(16, 16), 256, slice_smem, s0>>>(xbb, thb);
    softmax_kernel<<<16 * 96, 256, 0, s0>>>(96, uu, vv, c0);
    apply_slice_h_kernel<<<dim3(256, 16), 256, 0, s0>>>(x1, x2, beta_h);
    cudaEventRecord(ev[5], s0);                               // new x (g_xb) ready

    // ---- round 3: channel attention ----
    cudaStreamWaitEvent(s2, ev[5], 0);
    xsum2_kernel<<<dim3(256, 16), 256, 0, s2>>>();
    sAsB_kernel<<<dim3(256, 16), 256, 0, s2>>>(wt, wp, bp);
    gram_kernel<<<dim3(4, 4, 16), 128, 0, s2>>>();
    cudaEventRecord(ev[6], s2);                               // G + sA/sB2 ready

    conv_kernel<<<dim3(72, 2, 16), 256, gemm_smem, s0>>>(Wbf + 2*65536, gbb, bg, gbb, bg);
    cudaStreamWaitEvent(s0, ev[6], 0);
    f32gemm_nn_kernel<<<dim3(4, 4, 16), 256, 0, s0>>>(wt);
    f32gemm_nt_kernel<<<dim3(4, 4, 16), 256, 0, s0>>>(wp, bt, bp);
    softmax_kernel<<<16 * 256, 256, 0, s0>>>(256, nullptr, nullptr, nullptr);
    apply_channel_bf16_kernel<<<dim3(72, 2, 16), 256, gemm_smem, s0>>>(x2, out, beta_c);
}

// round 8
// speedup vs baseline: 5.3390x; 1.0689x over previous
#include <cuda_runtime.h>
#include <cuda_bf16.h>
#include <math.h>
#include <stdint.h>

#define BB 16
#define CC 256
#define HH 96
#define WW 96
#define HWSZ (HH*WW)           // 9216
#define NELEM (BB*CC*HWSZ)     // 37,748,736

// Scratch (device globals: allocation-free rule)
__device__ __nv_bfloat16 g_thb[NELEM];       // y = M x (rounds 1-2)
__device__ __nv_bfloat16 g_gb[NELEM];        // g = Wg x + bg
__device__ __nv_bfloat16 g_xb[NELEM];        // bf16 mirror of current x
__device__ float g_x1[NELEM];
__device__ float g_x2[NELEM];
__device__ float g_S[BB*CC*CC];              // logits fp32
__device__ __nv_bfloat16 g_Pb[BB*CC*CC];     // probabilities bf16
__device__ __nv_bfloat16 g_Wbf[3*CC*CC];     // [Wt; Wp; Wg] bf16
__device__ __nv_bfloat16 g_W2[2*CC*CC];      // [M = Wt^T Wp ; Wg] bf16 (512x256)
__device__ float g_G[BB*CC*CC];              // Gram X X^T fp32
__device__ float g_T1[BB*CC*CC];             // Wt @ G fp32
__device__ float g_xs[BB*CC*96];             // per-axis sums of x
__device__ float g_xs2[BB*CC];               // full-hw sums of x
__device__ float g_u[BB*96];
__device__ float g_v[BB*96];
__device__ float g_w1[CC];
__device__ float g_w2[CC];
__device__ float g_c0[1];
__device__ float g_sA[BB*CC];
__device__ float g_sB2[BB*CC];

// ---------------------------------------------------------------------------
// helpers
// ---------------------------------------------------------------------------
__device__ __forceinline__ uint32_t smem_u32(const void* p) {
    return (uint32_t)__cvta_generic_to_shared(p);
}
__device__ __forceinline__ uint32_t packbf(float lo, float hi) {
    __nv_bfloat162 h = __floats2bfloat162_rn(lo, hi);
    return *(uint32_t*)&h;
}
__device__ __forceinline__ void cpa16(uint32_t dst, const void* src) {
    asm volatile("cp.async.cg.shared.global [%0], [%1], 16;" :: "r"(dst), "l"(src));
}
#define CP_COMMIT() asm volatile("cp.async.commit_group;")
template<int N> __device__ __forceinline__ void cp_wait() {
    asm volatile("cp.async.wait_group %0;" :: "n"(N));
}
__device__ __forceinline__ void ldsm4(uint32_t& r0, uint32_t& r1, uint32_t& r2, uint32_t& r3, uint32_t a) {
    asm volatile("ldmatrix.sync.aligned.m8n8.x4.shared.b16 {%0,%1,%2,%3},[%4];"
                 : "=r"(r0), "=r"(r1), "=r"(r2), "=r"(r3) : "r"(a));
}
__device__ __forceinline__ void ldsm4t(uint32_t& r0, uint32_t& r1, uint32_t& r2, uint32_t& r3, uint32_t a) {
    asm volatile("ldmatrix.sync.aligned.m8n8.x4.trans.shared.b16 {%0,%1,%2,%3},[%4];"
                 : "=r"(r0), "=r"(r1), "=r"(r2), "=r"(r3) : "r"(a));
}
__device__ __forceinline__ void ldsm2(uint32_t& r0, uint32_t& r1, uint32_t a) {
    asm volatile("ldmatrix.sync.aligned.m8n8.x2.shared.b16 {%0,%1},[%2];"
                 : "=r"(r0), "=r"(r1) : "r"(a));
}
__device__ __forceinline__ void ldsm2t(uint32_t& r0, uint32_t& r1, uint32_t a) {
    asm volatile("ldmatrix.sync.aligned.m8n8.x2.trans.shared.b16 {%0,%1},[%2];"
                 : "=r"(r0), "=r"(r1) : "r"(a));
}
__device__ __forceinline__ void mma_bf16(float (&d)[4], uint32_t a0, uint32_t a1, uint32_t a2, uint32_t a3,
                                         uint32_t b0, uint32_t b1) {
    asm volatile(
        "mma.sync.aligned.m16n8k16.row.col.f32.bf16.bf16.f32 "
        "{%0,%1,%2,%3},{%4,%5,%6,%7},{%8,%9},{%0,%1,%2,%3};"
        : "+f"(d[0]), "+f"(d[1]), "+f"(d[2]), "+f"(d[3])
        : "r"(a0), "r"(a1), "r"(a2), "r"(a3), "r"(b0), "r"(b1));
}

// 128(M)x128(N) tile step: A [m][k] non-trans lda=LDA, B [k][n] trans ldb=LDB, KS k-steps.
template<int LDA, int LDB, int KS>
__device__ __forceinline__ void mma_tileT(const __nv_bfloat16* As, const __nv_bfloat16* Bs,
                                          int mw, int nw, int lane, float (&acc)[4][4][4])
{
    #pragma unroll
    for (int ks = 0; ks < KS; ks++) {
        int k0 = ks * 16;
        uint32_t a[4][4], bf[4][2];
        #pragma unroll
        for (int mf = 0; mf < 4; mf++)
            ldsm4(a[mf][0], a[mf][1], a[mf][2], a[mf][3],
                  smem_u32(As + (mw + mf*16 + (lane & 15)) * LDA + k0 + (lane >> 4) * 8));
        #pragma unroll
        for (int nb = 0; nb < 2; nb++)
            ldsm4t(bf[nb*2][0], bf[nb*2][1], bf[nb*2+1][0], bf[nb*2+1][1],
                   smem_u32(Bs + (k0 + (lane & 15)) * LDB + nw + nb*16 + (lane >> 4) * 8));
        #pragma unroll
        for (int mf = 0; mf < 4; mf++)
            #pragma unroll
            for (int nf = 0; nf < 4; nf++)
                mma_bf16(acc[mf][nf], a[mf][0], a[mf][1], a[mf][2], a[mf][3],
                         bf[nf][0], bf[nf][1]);
    }
}

// 128x128 tile step, B [n][k] non-trans (for gram).
template<int LDA, int LDB, int KS>
__device__ __forceinline__ void mma_tileNN(const __nv_bfloat16* As, const __nv_bfloat16* Bs,
                                           int mw, int nw, int lane, float (&acc)[4][4][4])
{
    #pragma unroll
    for (int ks = 0; ks < KS; ks++) {
        int k0 = ks * 16;
        uint32_t a[4][4], bf[4][2];
        #pragma unroll
        for (int mf = 0; mf < 4; mf++)
            ldsm4(a[mf][0], a[mf][1], a[mf][2], a[mf][3],
                  smem_u32(As + (mw + mf*16 + (lane & 15)) * LDA + k0 + (lane >> 4) * 8));
        #pragma unroll
        for (int nb = 0; nb < 2; nb++)
            ldsm4(bf[nb*2][0], bf[nb*2][1], bf[nb*2+1][0], bf[nb*2+1][1],
                  smem_u32(Bs + (nw + nb*16 + (lane>>4)*8 + (lane&7)) * LDB + k0 + ((lane>>3)&1)*8));
        #pragma unroll
        for (int mf = 0; mf < 4; mf++)
            #pragma unroll
            for (int nf = 0; nf < 4; nf++)
                mma_bf16(acc[mf][nf], a[mf][0], a[mf][1], a[mf][2], a[mf][3],
                         bf[nf][0], bf[nf][1]);
    }
}

// ---------------------------------------------------------------------------
// one-time converts / precomputes
// ---------------------------------------------------------------------------
__global__ void wconv_kernel(const float* __restrict__ wt, const float* __restrict__ wp,
                             const float* __restrict__ wg) {
    int i = blockIdx.x * 256 + threadIdx.x;
    const float* src = (i < 65536) ? wt : (i < 131072 ? wp : wg);
    __nv_bfloat16 v = __float2bfloat16(src[i & 65535]);
    g_Wbf[i] = v;
    if (i >= 131072) g_W2[65536 + (i - 131072)] = v;
}
__global__ void xconv_kernel(const float* __restrict__ x) {
    size_t base = ((size_t)blockIdx.x * 256 + threadIdx.x) * 8;
    float4 f0 = *(const float4*)(x + base);
    float4 f1 = *(const float4*)(x + base + 4);
    uint4 v;
    v.x = packbf(f0.x, f0.y); v.y = packbf(f0.z, f0.w);
    v.z = packbf(f1.x, f1.y); v.w = packbf(f1.z, f1.w);
    *(uint4*)(g_xb + base) = v;
}

// M = Wt^T Wp (256x256) -> g_W2 rows 0-255. Tile 64x64, K=256, 4 warps (2x2).
__global__ __launch_bounds__(128) void mprep_kernel()
{
    __shared__ __align__(16) __nv_bfloat16 As[64][72];
    __shared__ __align__(16) __nv_bfloat16 Bs[64][72];

    int m0 = blockIdx.y * 64, n0 = blockIdx.x * 64;
    int tid = threadIdx.x, wid = tid >> 5, lane = tid & 31;
    int mw = (wid >> 1) * 32, nw = (wid & 1) * 32;
    int g = lane >> 2, tg = lane & 3;

    float acc[2][4][4] = {};
    int cr = tid >> 1, mc = (tid & 1) * 32;

    for (int kk = 0; kk < 256; kk += 64) {
        uint32_t ad = smem_u32(&As[cr][mc]);
        uint32_t bd = smem_u32(&Bs[cr][mc]);
        const __nv_bfloat16* asrc = g_Wbf + (size_t)(kk + cr) * 256 + m0 + mc;
        const __nv_bfloat16* bsrc = g_Wbf + 65536 + (size_t)(kk + cr) * 256 + n0 + mc;
        #pragma unroll
        for (int j = 0; j < 4; j++) { cpa16(ad + j*16, asrc + j*8); cpa16(bd + j*16, bsrc + j*8); }
        CP_COMMIT();
        cp_wait<0>();
        __syncthreads();
        #pragma unroll
        for (int ks = 0; ks < 4; ks++) {
            int k0 = ks * 16;
            uint32_t a[2][4], bf[4][2];
            #pragma unroll
            for (int mf = 0; mf < 2; mf++)
                ldsm4t(a[mf][0], a[mf][1], a[mf][2], a[mf][3],
                    smem_u32(&As[k0 + ((lane>>4)&1)*8 + (lane&7)][mw + mf*16 + ((lane>>3)&1)*8]));
            ldsm4t(bf[0][0], bf[0][1], bf[1][0], bf[1][1],
                   smem_u32(&Bs[k0 + (lane&15)][nw + (lane>>4)*8]));
            ldsm4t(bf[2][0], bf[2][1], bf[3][0], bf[3][1],
                   smem_u32(&Bs[k0 + (lane&15)][nw + 16 + (lane>>4)*8]));
            #pragma unroll
            for (int mf = 0; mf < 2; mf++)
                #pragma unroll
                for (int nf = 0; nf < 4; nf++)
                    mma_bf16(acc[mf][nf], a[mf][0], a[mf][1], a[mf][2], a[mf][3],
                             bf[nf][0], bf[nf][1]);
        }
        __syncthreads();
    }
    #pragma unroll
    for (int mf = 0; mf < 2; mf++) {
        int r1 = m0 + mw + mf*16 + g, r2 = r1 + 8;
        #pragma unroll
        for (int nf = 0; nf < 4; nf++) {
            int col = n0 + nw + nf*8 + tg*2;
            *(uint32_t*)&g_W2[r1*256 + col] = packbf(acc[mf][nf][0], acc[mf][nf][1]);
            *(uint32_t*)&g_W2[r2*256 + col] = packbf(acc[mf][nf][2], acc[mf][nf][3]);
        }
    }
}

// bias fold vectors
__global__ __launch_bounds__(256) void biasvec_kernel(const float* __restrict__ wt,
                                                      const float* __restrict__ wp,
                                                      const float* __restrict__ bt,
                                                      const float* __restrict__ bp)
{
    int k = blockIdx.x, o = threadIdx.x;
    __shared__ float r1[8], r2[8], r3[8];
    float btv = bt[o], bpv = bp[o];
    float s1 = wt[o*256 + k] * bpv;
    float s2 = wp[o*256 + k] * btv;
    float c  = btv * bpv;
    #pragma unroll
    for (int off = 16; off; off >>= 1) {
        s1 += __shfl_xor_sync(0xffffffffu, s1, off);
        s2 += __shfl_xor_sync(0xffffffffu, s2, off);
        c  += __shfl_xor_sync(0xffffffffu, c, off);
    }
    if ((o & 31) == 0) { r1[o>>5] = s1; r2[o>>5] = s2; r3[o>>5] = c; }
    __syncthreads();
    if (o == 0) {
        float a = 0.f, b2 = 0.f, cc = 0.f;
        #pragma unroll
        for (int w = 0; w < 8; w++) { a += r1[w]; b2 += r2[w]; cc += r3[w]; }
        g_w1[k] = a; g_w2[k] = b2;
        if (k == 0) g_c0[0] = 96.f * cc;
    }
}

// ---------------------------------------------------------------------------
// conv panel: B panel (256K x 128N of xb) resident in smem; loop mtiles of A.
// smem: Bs 256x136, Ab 2x(128x40). 90,112 B. 8 warps, warp 64x32 per m-tile.
// ---------------------------------------------------------------------------
__global__ __launch_bounds__(256) void conv_panel_kernel(
    const __nv_bfloat16* __restrict__ W, int mtiles,
    __nv_bfloat16* dst0, const float* bias0,
    __nv_bfloat16* dst1, const float* bias1)
{
    extern __shared__ __align__(16) __nv_bfloat16 dynsm[];
    __nv_bfloat16* Bs = dynsm;                               // [256][136]
    __nv_bfloat16* Ab[2] = { dynsm + 256*136, dynsm + 256*136 + 128*40 };

    int b = blockIdx.z, n0 = blockIdx.x * 128;
    int tid = threadIdx.x, wid = tid >> 5, lane = tid & 31;
    int mw = (wid >> 2) * 64, nw = (wid & 3) * 32;
    int g = lane >> 2, tg = lane & 3;

    // stage full B panel (one group)
    const __nv_bfloat16* bbase = g_xb + (size_t)b * CC * HWSZ + n0;
    #pragma unroll
    for (int j = 0; j < 16; j++) {
        int idx = j * 256 + tid;               // 0..4095
        int row = idx >> 4, cb8 = (idx & 15) * 8;
        cpa16(smem_u32(Bs + row*136 + cb8), bbase + (size_t)row * HWSZ + cb8);
    }
    CP_COMMIT();

    int arow = tid >> 1, acb = (tid & 1) * 16;

    for (int mt = 0; mt < mtiles; mt++) {
        int mbase = mt * 128;
        const __nv_bfloat16* asrc = W + (size_t)(mbase + arow) * 256 + acb;
        {
            uint32_t ad = smem_u32(Ab[0] + arow*40 + acb);
            cpa16(ad, asrc); cpa16(ad + 16, asrc + 8);
            CP_COMMIT();
        }
        float acc[4][4][4] = {};
        for (int kc = 0; kc < 8; kc++) {
            if (kc < 7) {
                uint32_t ad = smem_u32(Ab[(kc+1)&1] + arow*40 + acb);
                const __nv_bfloat16* as = asrc + (kc + 1) * 32;
                cpa16(ad, as); cpa16(ad + 16, as + 8);
                CP_COMMIT();
                cp_wait<1>();
            } else cp_wait<0>();
            __syncthreads();
            mma_tileT<40, 136, 2>(Ab[kc&1], Bs + kc*32*136, mw, nw, lane, acc);
            __syncthreads();
        }
        int mat = mbase >> 8, ob = mbase & 255;
        __nv_bfloat16* dst = mat ? dst1 : dst0;
        const float* bias = mat ? bias1 : bias0;
        #pragma unroll
        for (int mf = 0; mf < 4; mf++) {
            int r = mw + mf * 16 + g;
            int o1 = ob + r, o2 = o1 + 8;
            float b1 = bias ? bias[o1] : 0.f;
            float b2 = bias ? bias[o2] : 0.f;
            size_t base1 = ((size_t)b * CC + o1) * HWSZ + n0;
            size_t base2 = ((size_t)b * CC + o2) * HWSZ + n0;
            #pragma unroll
            for (int nf = 0; nf < 4; nf++) {
                int col = nw + nf * 8 + tg * 2;
                *(uint32_t*)&dst[base1 + col] = packbf(acc[mf][nf][0] + b1, acc[mf][nf][1] + b1);
                *(uint32_t*)&dst[base2 + col] = packbf(acc[mf][nf][2] + b2, acc[mf][nf][3] + b2);
            }
        }
    }
}

// ---------------------------------------------------------------------------
// apply channel panel: out = xin + beta * (P @ g), B = g panel resident.
// ---------------------------------------------------------------------------
__global__ __launch_bounds__(256) void apply_channel_panel_kernel(
    const float* __restrict__ xin, float* __restrict__ xout, const float* __restrict__ beta_p)
{
    extern __shared__ __align__(16) __nv_bfloat16 dynsm[];
    __nv_bfloat16* Bs = dynsm;
    __nv_bfloat16* Ab[2] = { dynsm + 256*136, dynsm + 256*136 + 128*40 };

    int b = blockIdx.z, n0 = blockIdx.x * 128;
    int tid = threadIdx.x, wid = tid >> 5, lane = tid & 31;
    int mw = (wid >> 2) * 64, nw = (wid & 3) * 32;
    int g = lane >> 2, tg = lane & 3;

    const __nv_bfloat16* bbase = g_gb + (size_t)b * CC * HWSZ + n0;
    #pragma unroll
    for (int j = 0; j < 16; j++) {
        int idx = j * 256 + tid;
        int row = idx >> 4, cb8 = (idx & 15) * 8;
        cpa16(smem_u32(Bs + row*136 + cb8), bbase + (size_t)row * HWSZ + cb8);
    }
    CP_COMMIT();

    int arow = tid >> 1, acb = (tid & 1) * 16;
    float beta = *beta_p;

    for (int mt = 0; mt < 2; mt++) {
        int mbase = mt * 128;
        const __nv_bfloat16* asrc = g_Pb + (size_t)b * 65536 + (size_t)(mbase + arow) * 256 + acb;
        {
            uint32_t ad = smem_u32(Ab[0] + arow*40 + acb);
            cpa16(ad, asrc); cpa16(ad + 16, asrc + 8);
            CP_COMMIT();
        }
        float acc[4][4][4] = {};
        for (int kc = 0; kc < 8; kc++) {
            if (kc < 7) {
                uint32_t ad = smem_u32(Ab[(kc+1)&1] + arow*40 + acb);
                const __nv_bfloat16* as = asrc + (kc + 1) * 32;
                cpa16(ad, as); cpa16(ad + 16, as + 8);
                CP_COMMIT();
                cp_wait<1>();
            } else cp_wait<0>();
            __syncthreads();
            mma_tileT<40, 136, 2>(Ab[kc&1], Bs + kc*32*136, mw, nw, lane, acc);
            __syncthreads();
        }
        #pragma unroll
        for (int mf = 0; mf < 4; mf++) {
            int r1 = mbase + mw + mf * 16 + g, r2 = r1 + 8;
            size_t base1 = ((size_t)b * CC + r1) * HWSZ + n0;
            size_t base2 = ((size_t)b * CC + r2) * HWSZ + n0;
            #pragma unroll
            for (int nf = 0; nf < 4; nf++) {
                int col = nw + nf * 8 + tg * 2;
                float2 xa = *(const float2*)&xin[base1 + col];
                float2 xb2 = *(const float2*)&xin[base2 + col];
                *(float2*)&xout[base1 + col] =
                    make_float2(xa.x + beta*acc[mf][nf][0], xa.y + beta*acc[mf][nf][1]);
                *(float2*)&xout[base2 + col] =
                    make_float2(xb2.x + beta*acc[mf][nf][2], xb2.y + beta*acc[mf][nf][3]);
            }
        }
    }
}

// ---------------------------------------------------------------------------
// per-axis x sums
// ---------------------------------------------------------------------------
template<int MODE>
__global__ __launch_bounds__(96) void xsum_kernel()
{
    int k = blockIdx.x, b = blockIdx.y, i = threadIdx.x;
    const __nv_bfloat16* src = g_xb + ((size_t)b * CC + k) * HWSZ;
    float s = 0.f;
    if (MODE == 0) {
        #pragma unroll 8
        for (int h = 0; h < 96; h++) s += __bfloat162float(src[h*96 + i]);
    } else {
        #pragma unroll 8
        for (int w = 0; w < 96; w++) s += __bfloat162float(src[i*96 + w]);
    }
    g_xs[((size_t)b * CC + k) * 96 + i] = s;
}

__global__ __launch_bounds__(96) void uv_kernel()
{
    int b = blockIdx.x, j = threadIdx.x;
    float su = 0.f, sv = 0.f;
    #pragma unroll 8
    for (int k = 0; k < 256; k++) {
        float xv = g_xs[((size_t)b * CC + k) * 96 + j];
        su += g_w2[k] * xv;
        sv += g_w1[k] * xv;
    }
    g_u[b*96 + j] = su;
    g_v[b*96 + j] = sv;
}

// ---------------------------------------------------------------------------
// slice logits
// ---------------------------------------------------------------------------
template<int MODE>
__global__ __launch_bounds__(256) void slice_logits_bf16_kernel(
    const __nv_bfloat16* __restrict__ Abase, const __nv_bfloat16* __restrict__ Bbase)
{
    extern __shared__ __align__(16) __nv_bfloat16 dynsm[];
    __nv_bfloat16* Tb[2] = { dynsm,            dynsm + 2*96*104 };
    __nv_bfloat16* Pb[2] = { dynsm + 96*104,   dynsm + 3*96*104 };

    int b = blockIdx.y, cch = blockIdx.x;
    int tid = threadIdx.x, wid = tid >> 5, lane = tid & 31;
    int mw = (wid >> 2) * 48, nw = (wid & 3) * 24;
    int g = lane >> 2, tg = lane & 3;

    const __nv_bfloat16* tbase = Abase + ((size_t)b * CC + cch * 16) * HWSZ;
    const __nv_bfloat16* pbase = Bbase + ((size_t)b * CC + cch * 16) * HWSZ;

    float acc[3][3][4] = {};

    auto stage = [&](int cc, int bi) {
        const __nv_bfloat16* ts = tbase + (size_t)cc * HWSZ;
        const __nv_bfloat16* ps = pbase + (size_t)cc * HWSZ;
        #pragma unroll
        for (int j = 0; j < 9; j++) {
            int c = j * 256 + tid;
            int cc2 = (c < 1152) ? c : c - 1152;
            int row = cc2 / 12, col = (cc2 % 12) * 8;
            if (c < 1152) cpa16(smem_u32(Tb[bi] + row*104 + col), ts + row*96 + col);
            else          cpa16(smem_u32(Pb[bi] + row*104 + col), ps + row*96 + col);
        }
        CP_COMMIT();
    };

    stage(0, 0);
    for (int cc = 0; cc < 16; cc++) {
        if (cc < 15) { stage(cc + 1, (cc + 1) & 1); cp_wait<1>(); }
        else cp_wait<0>();
        __syncthreads();
        const __nv_bfloat16* As = Tb[cc & 1];
        const __nv_bfloat16* Bs = Pb[cc & 1];
        #pragma unroll
        for (int ks = 0; ks < 6; ks++) {
            int k0 = ks * 16;
            uint32_t a[3][4], bf[3][2];
            #pragma unroll
            for (int mf = 0; mf < 3; mf++) {
                if (MODE == 0)
                    ldsm4t(a[mf][0], a[mf][1], a[mf][2], a[mf][3],
                        smem_u32(As + (k0 + ((lane>>4)&1)*8 + (lane&7))*104 + mw + mf*16 + ((lane>>3)&1)*8));
                else
                    ldsm4(a[mf][0], a[mf][1], a[mf][2], a[mf][3],
                        smem_u32(As + (mw + mf*16 + (lane&15))*104 + k0 + (lane>>4)*8));
            }
            if (MODE == 0) {
                ldsm4t(bf[0][0], bf[0][1], bf[1][0], bf[1][1],
                       smem_u32(Bs + (k0 + (lane&15))*104 + nw + (lane>>4)*8));
                ldsm2t(bf[2][0], bf[2][1],
                       smem_u32(Bs + (k0 + (lane&15))*104 + nw + 16));
            } else {
                ldsm4(bf[0][0], bf[0][1], bf[1][0], bf[1][1],
                      smem_u32(Bs + (nw + (lane>>4)*8 + (lane&7))*104 + k0 + ((lane>>3)&1)*8));
                ldsm2(bf[2][0], bf[2][1],
                      smem_u32(Bs + (nw + 16 + (lane&7))*104 + k0 + ((lane>>3)&1)*8));
            }
            #pragma unroll
            for (int mf = 0; mf < 3; mf++)
                #pragma unroll
                for (int nf = 0; nf < 3; nf++)
                    mma_bf16(acc[mf][nf], a[mf][0], a[mf][1], a[mf][2], a[mf][3],
                             bf[nf][0], bf[nf][1]);
        }
        __syncthreads();
    }
    float* Sb = g_S + (size_t)b * 9216;
    #pragma unroll
    for (int mf = 0; mf < 3; mf++) {
        int i1 = mw + mf * 16 + g, i2 = i1 + 8;
        #pragma unroll
        for (int nf = 0; nf < 3; nf++) {
            int jc = nw + nf * 8 + tg * 2;
            atomicAdd(&Sb[i1 * 96 + jc],     acc[mf][nf][0]);
            atomicAdd(&Sb[i1 * 96 + jc + 1], acc[mf][nf][1]);
            atomicAdd(&Sb[i2 * 96 + jc],     acc[mf][nf][2]);
            atomicAdd(&Sb[i2 * 96 + jc + 1], acc[mf][nf][3]);
        }
    }
}

// ---------------------------------------------------------------------------
// softmax: optional additive bias. writes bf16 P.
// ---------------------------------------------------------------------------
__global__ __launch_bounds__(256) void softmax_kernel(int n, const float* u,
                                                      const float* v, const float* c0p)
{
    size_t base = (size_t)blockIdx.x * n;
    int tid = threadIdx.x;
    __shared__ float red[8];

    float rowadd = 0.f;
    int ub = 0;
    if (u) {
        rowadd = v[blockIdx.x] + *c0p;
        ub = (blockIdx.x / 96) * 96;
    }

    float m = -INFINITY;
    for (int j = tid; j < n; j += 256) {
        float val = g_S[base + j] + rowadd + (u ? u[ub + j] : 0.f);
        m = fmaxf(m, val);
    }
    #pragma unroll
    for (int o = 16; o; o >>= 1) m = fmaxf(m, __shfl_xor_sync(0xffffffffu, m, o));
    if ((tid & 31) == 0) red[tid >> 5] = m;
    __syncthreads();
    float mm = red[0];
    #pragma unroll
    for (int w = 1; w < 8; w++) mm = fmaxf(mm, red[w]);

    float s = 0.f;
    float ev[2];
    int cnt = 0;
    for (int j = tid; j < n; j += 256) {
        float val = g_S[base + j] + rowadd + (u ? u[ub + j] : 0.f);
        float e = __expf(val - mm);
        ev[cnt++] = e;
        s += e;
    }
    #pragma unroll
    for (int o = 16; o; o >>= 1) s += __shfl_xor_sync(0xffffffffu, s, o);
    if ((tid & 31) == 0) red[tid >> 5] = s;
    __syncthreads();
    float st = 0.f;
    #pragma unroll
    for (int w = 0; w < 8; w++) st += red[w];
    float inv = 1.0f / st;
    cnt = 0;
    for (int j = tid; j < n; j += 256)
        g_Pb[base + j] = __float2bfloat16(ev[cnt++] * inv);
}

// ---------------------------------------------------------------------------
// apply width / height
// ---------------------------------------------------------------------------
__global__ __launch_bounds__(256) void apply_slice_w_kernel(
    const float* __restrict__ xin, float* __restrict__ xout, const float* __restrict__ beta_p)
{
    __shared__ __align__(16) __nv_bfloat16 As[128][104];
    __shared__ __align__(16) __nv_bfloat16 Bs[96][104];

    int b = blockIdx.y, m0 = blockIdx.x * 128;
    int tid = threadIdx.x, wid = tid >> 5, lane = tid & 31;
    int mw = (wid >> 1) * 32, nw = (wid & 1) * 48;
    int g = lane >> 2, tg = lane & 3;

    const __nv_bfloat16* gsrc = g_gb + (size_t)b * CC * HWSZ + (size_t)m0 * 96;
    const __nv_bfloat16* psrc = g_Pb + (size_t)b * 9216;
    #pragma unroll
    for (int j = 0; j < 6; j++) {
        int c = j * 256 + tid;
        int row = c / 12, col = (c % 12) * 8;
        cpa16(smem_u32(&As[row][col]), gsrc + row*96 + col);
    }
    #pragma unroll
    for (int j = 0; j < 5; j++) {
        int c = j * 256 + tid;
        if (c < 1152) {
            int row = c / 12, col = (c % 12) * 8;
            cpa16(smem_u32(&Bs[row][col]), psrc + row*96 + col);
        }
    }
    CP_COMMIT();
    cp_wait<0>();
    __syncthreads();

    float acc[2][6][4] = {};
    #pragma unroll
    for (int ks = 0; ks < 6; ks++) {
        int k0 = ks * 16;
        uint32_t a[2][4], bf[6][2];
        #pragma unroll
        for (int mf = 0; mf < 2; mf++)
            ldsm4(a[mf][0], a[mf][1], a[mf][2], a[mf][3],
                  smem_u32(&As[mw + mf*16 + (lane&15)][k0 + (lane>>4)*8]));
        #pragma unroll
        for (int nb = 0; nb < 3; nb++)
            ldsm4(bf[nb*2][0], bf[nb*2][1], bf[nb*2+1][0], bf[nb*2+1][1],
                  smem_u32(&Bs[nw + nb*16 + (lane>>4)*8 + (lane&7)][k0 + ((lane>>3)&1)*8]));
        #pragma unroll
        for (int mf = 0; mf < 2; mf++)
            #pragma unroll
            for (int nf = 0; nf < 6; nf++)
                mma_bf16(acc[mf][nf], a[mf][0], a[mf][1], a[mf][2], a[mf][3],
                         bf[nf][0], bf[nf][1]);
    }
    float beta = *beta_p;
    size_t gb = (size_t)b * CC * HWSZ;
    #pragma unroll
    for (int mf = 0; mf < 2; mf++) {
        int r1 = m0 + mw + mf * 16 + g, r2 = r1 + 8;
        #pragma unroll
        for (int nf = 0; nf < 6; nf++) {
            int col = nw + nf * 8 + tg * 2;
            size_t o1 = gb + (size_t)r1 * 96 + col;
            size_t o2 = gb + (size_t)r2 * 96 + col;
            float2 xa = *(const float2*)&xin[o1];
            float2 xb2 = *(const float2*)&xin[o2];
            float v0 = xa.x + beta*acc[mf][nf][0], v1 = xa.y + beta*acc[mf][nf][1];
            float v2 = xb2.x + beta*acc[mf][nf][2], v3 = xb2.y + beta*acc[mf][nf][3];
            *(float2*)&xout[o1] = make_float2(v0, v1);
            *(float2*)&xout[o2] = make_float2(v2, v3);
            *(uint32_t*)&g_xb[o1] = packbf(v0, v1);
            *(uint32_t*)&g_xb[o2] = packbf(v2, v3);
        }
    }
}

__global__ __launch_bounds__(256) void apply_slice_h_kernel(
    const float* __restrict__ xin, float* __restrict__ xout, const float* __restrict__ beta_p)
{
    __shared__ __align__(16) __nv_bfloat16 As[96][104];
    __shared__ __align__(16) __nv_bfloat16 Bs[96][104];

    int b = blockIdx.y, c = blockIdx.x;
    int tid = threadIdx.x, wid = tid >> 5, lane = tid & 31;
    int mw = (wid >> 2) * 48, nw = (wid & 3) * 24;
    int g = lane >> 2, tg = lane & 3;

    const __nv_bfloat16* psrc = g_Pb + (size_t)b * 9216;
    const __nv_bfloat16* gsrc = g_gb + ((size_t)b * CC + c) * HWSZ;
    #pragma unroll
    for (int j = 0; j < 9; j++) {
        int cidx = j * 256 + tid;
        int c2 = (cidx < 1152) ? cidx : cidx - 1152;
        int row = c2 / 12, col = (c2 % 12) * 8;
        if (cidx < 1152) cpa16(smem_u32(&As[row][col]), psrc + row*96 + col);
        else             cpa16(smem_u32(&Bs[row][col]), gsrc + row*96 + col);
    }
    CP_COMMIT();
    cp_wait<0>();
    __syncthreads();

    float acc[3][3][4] = {};
    #pragma unroll
    for (int ks = 0; ks < 6; ks++) {
        int k0 = ks * 16;
        uint32_t a[3][4], bf[3][2];
        #pragma unroll
        for (int mf = 0; mf < 3; mf++)
            ldsm4(a[mf][0], a[mf][1], a[mf][2], a[mf][3],
                  smem_u32(&As[mw + mf*16 + (lane&15)][k0 + (lane>>4)*8]));
        ldsm4t(bf[0][0], bf[0][1], bf[1][0], bf[1][1],
               smem_u32(&Bs[k0 + (lane&15)][nw + (lane>>4)*8]));
        ldsm2t(bf[2][0], bf[2][1],
               smem_u32(&Bs[k0 + (lane&15)][nw + 16]));
        #pragma unroll
        for (int mf = 0; mf < 3; mf++)
            #pragma unroll
            for (int nf = 0; nf < 3; nf++)
                mma_bf16(acc[mf][nf], a[mf][0], a[mf][1], a[mf][2], a[mf][3],
                         bf[nf][0], bf[nf][1]);
    }
    float beta = *beta_p;
    size_t base = ((size_t)b * CC + c) * HWSZ;
    #pragma unroll
    for (int mf = 0; mf < 3; mf++) {
        int i1 = mw + mf * 16 + g, i2 = i1 + 8;
        #pragma unroll
        for (int nf = 0; nf < 3; nf++) {
            int col = nw + nf * 8 + tg * 2;
            size_t o1 = base + (size_t)i1 * 96 + col;
            size_t o2 = base + (size_t)i2 * 96 + col;
            float2 xa = *(const float2*)&xin[o1];
            float2 xb2 = *(const float2*)&xin[o2];
            float v0 = xa.x + beta*acc[mf][nf][0], v1 = xa.y + beta*acc[mf][nf][1];
            float v2 = xb2.x + beta*acc[mf][nf][2], v3 = xb2.y + beta*acc[mf][nf][3];
            *(float2*)&xout[o1] = make_float2(v0, v1);
            *(float2*)&xout[o2] = make_float2(v2, v3);
            *(uint32_t*)&g_xb[o1] = packbf(v0, v1);
            *(uint32_t*)&g_xb[o2] = packbf(v2, v3);
        }
    }
}

// ---------------------------------------------------------------------------
// Gram: 128x128 tiles, symmetric (3 tile-blocks per b), BK=32 double-buffered.
// grid (3, 16): idx 0 -> (0,0), 1 -> (0,128) (+mirror), 2 -> (128,128).
// ---------------------------------------------------------------------------
__global__ __launch_bounds__(256) void gram_kernel()
{
    __shared__ __align__(16) __nv_bfloat16 Asm[2][128][40];
    __shared__ __align__(16) __nv_bfloat16 Bsm[2][128][40];

    int ti = blockIdx.x, b = blockIdx.y;
    int i0 = (ti == 2) ? 128 : 0;
    int j0 = (ti == 0) ? 0 : 128;
    int tid = threadIdx.x, wid = tid >> 5, lane = tid & 31;
    int mw = (wid >> 2) * 64, nw = (wid & 3) * 32;
    int g = lane >> 2, tg = lane & 3;

    int row = tid >> 1, cb = (tid & 1) * 16;
    const __nv_bfloat16* as0 = g_xb + ((size_t)b * CC + i0 + row) * HWSZ + cb;
    const __nv_bfloat16* bs0 = g_xb + ((size_t)b * CC + j0 + row) * HWSZ + cb;

    float acc[4][4][4] = {};

    auto stage = [&](int kk, int bi) {
        uint32_t ad = smem_u32(&Asm[bi][row][cb]);
        uint32_t bd = smem_u32(&Bsm[bi][row][cb]);
        cpa16(ad, as0 + kk); cpa16(ad + 16, as0 + kk + 8);
        cpa16(bd, bs0 + kk); cpa16(bd + 16, bs0 + kk + 8);
        CP_COMMIT();
    };

    stage(0, 0);
    for (int s = 0; s < 288; s++) {
        if (s < 287) { stage((s + 1) * 32, (s + 1) & 1); cp_wait<1>(); }
        else cp_wait<0>();
        __syncthreads();
        mma_tileNN<40, 40, 2>(&Asm[s&1][0][0], &Bsm[s&1][0][0], mw, nw, lane, acc);
        __syncthreads();
    }
    float* Gb = g_G + (size_t)b * 65536;
    #pragma unroll
    for (int mf = 0; mf < 4; mf++) {
        int i1 = i0 + mw + mf * 16 + g, i2 = i1 + 8;
        #pragma unroll
        for (int nf = 0; nf < 4; nf++) {
            int jc = j0 + nw + nf * 8 + tg * 2;
            *(float2*)&Gb[(size_t)i1 * 256 + jc] = make_float2(acc[mf][nf][0], acc[mf][nf][1]);
            *(float2*)&Gb[(size_t)i2 * 256 + jc] = make_float2(acc[mf][nf][2], acc[mf][nf][3]);
            if (ti == 1) {
                Gb[(size_t)jc * 256 + i1]       = acc[mf][nf][0];
                Gb[(size_t)(jc + 1) * 256 + i1] = acc[mf][nf][1];
                Gb[(size_t)jc * 256 + i2]       = acc[mf][nf][2];
                Gb[(size_t)(jc + 1) * 256 + i2] = acc[mf][nf][3];
            }
        }
    }
}

// xs2[b,c] = sum_hw x[b,c,:]
__global__ __launch_bounds__(256) void xsum2_kernel()
{
    int k = blockIdx.x, b = blockIdx.y, tid = threadIdx.x;
    const __nv_bfloat16* src = g_xb + ((size_t)b * CC + k) * HWSZ;
    __shared__ float red[8];
    float s = 0.f;
    for (int e = tid; e < HWSZ; e += 256) s += __bfloat162float(src[e]);
    #pragma unroll
    for (int o = 16; o; o >>= 1) s += __shfl_xor_sync(0xffffffffu, s, o);
    if ((tid & 31) == 0) red[tid >> 5] = s;
    __syncthreads();
    if (tid == 0) {
        float t = 0.f;
        #pragma unroll
        for (int w = 0; w < 8; w++) t += red[w];
        g_xs2[b * CC + k] = t;
    }
}

__global__ __launch_bounds__(256) void sAsB_kernel(const float* __restrict__ wt,
                                                   const float* __restrict__ wp,
                                                   const float* __restrict__ bp)
{
    int i = blockIdx.x, b = blockIdx.y, c = threadIdx.x;
    __shared__ float r1[8], r2[8];
    float xv = g_xs2[b*CC + c];
    float sa = wt[i*256 + c] * xv;
    float sb = wp[i*256 + c] * xv;
    #pragma unroll
    for (int off = 16; off; off >>= 1) {
        sa += __shfl_xor_sync(0xffffffffu, sa, off);
        sb += __shfl_xor_sync(0xffffffffu, sb, off);
    }
    if ((c & 31) == 0) { r1[c>>5] = sa; r2[c>>5] = sb; }
    __syncthreads();
    if (c == 0) {
        float a = 0.f, b2 = 0.f;
        #pragma unroll
        for (int w = 0; w < 8; w++) { a += r1[w]; b2 += r2[w]; }
        g_sA[b*CC + i] = a;
        g_sB2[b*CC + i] = b2 + 9216.f * bp[i];
    }
}

// ---------------------------------------------------------------------------
// fp32 GEMM NN: T1[b] = wt @ G[b]. Tile 64x64, BK=16.
// ---------------------------------------------------------------------------
__global__ __launch_bounds__(256) void f32gemm_nn_kernel(const float* __restrict__ wt)
{
    int b  = blockIdx.z;
    int i0 = blockIdx.y * 64;
    int n0 = blockIdx.x * 64;

    __shared__ __align__(16) float As[16 * 68];
    __shared__ __align__(16) float Gs[16 * 68];

    int tid = threadIdx.x;
    int ti4 = (tid >> 4) * 4, tj4 = (tid & 15) * 4;
    float acc[4][4] = {};

    const float* Gb = g_G + (size_t)b * 65536;

    for (int kk = 0; kk < 256; kk += 16) {
        #pragma unroll
        for (int rr = 0; rr < 4; rr++) {
            int r = rr * 16 + (tid >> 4);
            int cload = tid & 15;
            As[cload * 68 + r] = wt[(i0 + r) * 256 + kk + cload];
        }
        #pragma unroll
        for (int rr = 0; rr < 4; rr++) {
            int k = rr * 4 + (tid >> 6);
            int n = tid & 63;
            Gs[k * 68 + n] = Gb[(size_t)(kk + k) * 256 + n0 + n];
        }
        __syncthreads();
        #pragma unroll
        for (int k = 0; k < 16; k++) {
            float4 a = *(float4*)&As[k * 68 + ti4];
            float4 g4 = *(float4*)&Gs[k * 68 + tj4];
            float ar[4] = {a.x, a.y, a.z, a.w};
            float gr[4] = {g4.x, g4.y, g4.z, g4.w};
            #pragma unroll
            for (int i = 0; i < 4; i++)
                #pragma unroll
                for (int j = 0; j < 4; j++)
                    acc[i][j] += ar[i] * gr[j];
        }
        __syncthreads();
    }

    float* T1b = g_T1 + (size_t)b * 65536;
    #pragma unroll
    for (int i = 0; i < 4; i++)
        #pragma unroll
        for (int j = 0; j < 4; j++)
            T1b[(size_t)(i0 + ti4 + i) * 256 + n0 + tj4 + j] = acc[i][j];
}

// ---------------------------------------------------------------------------
// fp32 GEMM NT + channel-bias epilogue.
// ---------------------------------------------------------------------------
__global__ __launch_bounds__(256) void f32gemm_nt_kernel(const float* __restrict__ wp,
                                                         const float* __restrict__ bt,
                                                         const float* __restrict__ bp)
{
    int b  = blockIdx.z;
    int i0 = blockIdx.y * 64;
    int j0 = blockIdx.x * 64;

    __shared__ __align__(16) float Ts[32 * 68];
    __shared__ __align__(16) float Ps[32 * 68];

    int tid = threadIdx.x;
    int lc = tid & 31, lr = tid >> 5;
    int ti4 = (tid >> 4) * 4, tj4 = (tid & 15) * 4;

    float acc[4][4] = {};
    const float* T1b = g_T1 + (size_t)b * 65536;

    for (int kb = 0; kb < 8; kb++) {
        int k0 = kb * 32;
        #pragma unroll
        for (int rr = 0; rr < 8; rr++) {
            int r = rr * 8 + lr;
            Ts[lc * 68 + r] = T1b[(size_t)(i0 + r) * 256 + k0 + lc];
            Ps[lc * 68 + r] = wp[(j0 + r) * 256 + k0 + lc];
        }
        __syncthreads();
        #pragma unroll
        for (int k = 0; k < 32; k++) {
            float4 a = *(float4*)&Ts[k * 68 + ti4];
            float4 p = *(float4*)&Ps[k * 68 + tj4];
            float ar[4] = {a.x, a.y, a.z, a.w};
            float pr[4] = {p.x, p.y, p.z, p.w};
            #pragma unroll
            for (int i = 0; i < 4; i++)
                #pragma unroll
                for (int j = 0; j < 4; j++)
                    acc[i][j] += ar[i] * pr[j];
        }
        __syncthreads();
    }

    float* Sb = g_S + (size_t)b * 65536;
    #pragma unroll
    for (int i = 0; i < 4; i++) {
        int irow = i0 + ti4 + i;
        float bti = bt[irow], sai = g_sA[b*CC + irow];
        #pragma unroll
        for (int j = 0; j < 4; j++) {
            int jcol = j0 + tj4 + j;
            Sb[(size_t)irow * 256 + jcol] =
                acc[i][j] + bti * g_sB2[b*CC + jcol] + bp[jcol] * sai;
        }
    }
}

// ---------------------------------------------------------------------------
extern "C" void kernel_launch(void* const* d_in, const int* in_sizes, int n_in,
                              void* d_out, int out_size)
{
    const float* x      = (const float*)d_in[0];
    const float* wt     = (const float*)d_in[1];
    const float* bt     = (const float*)d_in[2];
    const float* wp     = (const float*)d_in[3];
    const float* bp     = (const float*)d_in[4];
    const float* wg     = (const float*)d_in[5];
    const float* bg     = (const float*)d_in[6];
    const float* beta_w = (const float*)d_in[7];
    const float* beta_h = (const float*)d_in[8];
    const float* beta_c = (const float*)d_in[9];
    float* out = (float*)d_out;

    float *x1, *x2, *S, *uu, *vv, *c0;
    __nv_bfloat16 *thb, *gbb, *W2, *xbb, *Wbf;
    cudaGetSymbolAddress((void**)&x1, g_x1);
    cudaGetSymbolAddress((void**)&x2, g_x2);
    cudaGetSymbolAddress((void**)&S,  g_S);
    cudaGetSymbolAddress((void**)&uu, g_u);
    cudaGetSymbolAddress((void**)&vv, g_v);
    cudaGetSymbolAddress((void**)&c0, g_c0);
    cudaGetSymbolAddress((void**)&thb, g_thb);
    cudaGetSymbolAddress((void**)&gbb, g_gb);
    cudaGetSymbolAddress((void**)&W2,  g_W2);
    cudaGetSymbolAddress((void**)&xbb, g_xb);
    cudaGetSymbolAddress((void**)&Wbf, g_Wbf);

    int panel_smem = 256*136*2 + 2*128*40*2;      // 90112 B
    int slice_smem = 4 * 96 * 104 * 2;            // 79872 B
    cudaFuncSetAttribute(conv_panel_kernel,
                         cudaFuncAttributeMaxDynamicSharedMemorySize, panel_smem);
    cudaFuncSetAttribute(apply_channel_panel_kernel,
                         cudaFuncAttributeMaxDynamicSharedMemorySize, panel_smem);
    cudaFuncSetAttribute(slice_logits_bf16_kernel<0>,
                         cudaFuncAttributeMaxDynamicSharedMemorySize, slice_smem);
    cudaFuncSetAttribute(slice_logits_bf16_kernel<1>,
                         cudaFuncAttributeMaxDynamicSharedMemorySize, slice_smem);

    static cudaStream_t s2 = nullptr;
    static cudaEvent_t ev[8];
    if (!s2) {
        cudaStreamCreateWithFlags(&s2, cudaStreamNonBlocking);
        for (int i = 0; i < 8; i++)
            cudaEventCreateWithFlags(&ev[i], cudaEventDisableTiming);
    }
    cudaStream_t s0 = 0;

    // ---- prologue ----
    xconv_kernel<<<NELEM / (256 * 8), 256, 0, s0>>>(x);
    cudaEventRecord(ev[0], s0);                               // g_xb ready

    cudaStreamWaitEvent(s2, ev[0], 0);                        // fork s2
    wconv_kernel<<<768, 256, 0, s2>>>(wt, wp, wg);
    mprep_kernel<<<dim3(4, 4), 128, 0, s2>>>();
    cudaEventRecord(ev[1], s2);                               // W2 ready
    biasvec_kernel<<<256, 256, 0, s2>>>(wt, wp, bt, bp);
    cudaMemsetAsync(S, 0, (size_t)16 * 9216 * sizeof(float), s2);
    xsum_kernel<0><<<dim3(256, 16), 96, 0, s2>>>();
    uv_kernel<<<16, 96, 0, s2>>>();
    cudaEventRecord(ev[2], s2);                               // S zeroed + u/v ready

    // ---- round 1: width attention ----
    cudaStreamWaitEvent(s0, ev[1], 0);
    conv_panel_kernel<<<dim3(72, 1, 16), 256, panel_smem, s0>>>(W2, 4, thb, nullptr, gbb, bg);
    cudaStreamWaitEvent(s0, ev[2], 0);
    slice_logits_bf16_kernel<0><<<dim3(16, 16), 256, slice_smem, s0>>>(xbb, thb);
    softmax_kernel<<<16 * 96, 256, 0, s0>>>(96, uu, vv, c0);
    apply_slice_w_kernel<<<dim3(192, 16), 256, 0, s0>>>(x, x1, beta_w);
    cudaEventRecord(ev[3], s0);                               // new x (g_xb) ready

    // ---- round 2: height attention ----
    cudaStreamWaitEvent(s2, ev[3], 0);
    cudaMemsetAsync(S, 0, (size_t)16 * 9216 * sizeof(float), s2);
    xsum_kernel<1><<<dim3(256, 16), 96, 0, s2>>>();
    uv_kernel<<<16, 96, 0, s2>>>();
    cudaEventRecord(ev[4], s2);

    conv_panel_kernel<<<dim3(72, 1, 16), 256, panel_smem, s0>>>(W2, 4, thb, nullptr, gbb, bg);
    cudaStreamWaitEvent(s0, ev[4], 0);
    slice_logits_bf16_kernel<1><<<dim3(16, 16), 256, slice_smem, s0>>>(xbb, thb);
    softmax_kernel<<<16 * 96, 256, 0, s0>>>(96, uu, vv, c0);
    apply_slice_h_kernel<<<dim3(256, 16), 256, 0, s0>>>(x1, x2, beta_h);
    cudaEventRecord(ev[5], s0);                               // new x (g_xb) ready

    // ---- round 3: channel attention ----
    cudaStreamWaitEvent(s2, ev[5], 0);
    xsum2_kernel<<<dim3(256, 16), 256, 0, s2>>>();
    sAsB_kernel<<<dim3(256, 16), 256, 0, s2>>>(wt, wp, bp);
    gram_kernel<<<dim3(3, 16), 256, 0, s2>>>();
    cudaEventRecord(ev[6], s2);                               // G + sA/sB2 ready

    conv_panel_kernel<<<dim3(72, 1, 16), 256, panel_smem, s0>>>(Wbf + 2*65536, 2, gbb, bg, gbb, bg);
    cudaStreamWaitEvent(s0, ev[6], 0);
    f32gemm_nn_kernel<<<dim3(4, 4, 16), 256, 0, s0>>>(wt);
    f32gemm_nt_kernel<<<dim3(4, 4, 16), 256, 0, s0>>>(wp, bt, bp);
    softmax_kernel<<<16 * 256, 256, 0, s0>>>(256, nullptr, nullptr, nullptr);
    apply_channel_panel_kernel<<<dim3(72, 1, 16), 256, panel_smem, s0>>>(x2, out, beta_c);
}